// round 2
// baseline (speedup 1.0000x reference)
#include <cuda_runtime.h>

#define NB    2
#define SXX   1024
#define SYY   1024
#define DIM   1024
#define NH    16
#define HDIM  64
#define FULLN 1536

// ---------------- scratch (device globals; no allocation allowed) ----------------
__device__ float g_qkv[NB * SXX * 3 * DIM];   // 25.2 MB: [b, i, 3*D]  (Q|K|V)
__device__ float g_q2 [NB * SXX * DIM];       //  8.4 MB: [b, i, D]
__device__ float g_kv2[NB * SYY * 2 * DIM];   // 16.8 MB: [b, j, 2*D]  (K2|V2)
__device__ float g_cat[NB * SXX * 2 * DIM];   // 16.8 MB: [b, i, 2*D]  (a | a2m)
__device__ int   g_lens[4];                   // len_x[0..1], len_y[0..1]

// ---------------- per-batch lengths from take_b index arrays ----------------
__global__ void lens_kernel(const int* __restrict__ xb, int nx,
                            const int* __restrict__ yb, int ny)
{
    __shared__ int cnt[4];
    int t = threadIdx.x;
    if (t < 4) cnt[t] = 0;
    __syncthreads();
    for (int i = t; i < nx; i += blockDim.x) atomicAdd(&cnt[xb[i]], 1);
    for (int i = t; i < ny; i += blockDim.x) atomicAdd(&cnt[2 + yb[i]], 1);
    __syncthreads();
    if (t < 4) g_lens[t] = cnt[t];
}

// ---------------- SGEMM: C[M,N] = A[M,K] @ B[K,N] + bias[N] ----------------
// 128x128 block tile, K-step 8, 256 threads, 8x8 per-thread register tile.
__global__ __launch_bounds__(256, 2)
void sgemm128(const float* __restrict__ A, const float* __restrict__ Bm,
              const float* __restrict__ bias, float* __restrict__ C,
              int M, int N, int K)
{
    __shared__ float As[8][132];   // [k][m], padded (132%32=4) to kill store conflicts
    __shared__ float Bs[8][128];   // [k][n]

    const int tid  = threadIdx.x;
    const int bm   = blockIdx.y << 7;
    const int bn   = blockIdx.x << 7;
    const int arow = tid >> 1, acol = (tid & 1) << 2;    // A: 128 rows x 8 k
    const int brow = tid >> 5, bcol = (tid & 31) << 2;   // B: 8 k x 128 n
    const int m0   = (tid >> 4) << 3;
    const int n0   = (tid & 15) << 3;

    const float* Ap = A  + (size_t)(bm + arow) * K + acol;
    const float* Bp = Bm + (size_t)brow * N + bn + bcol;

    float acc[8][8];
#pragma unroll
    for (int i = 0; i < 8; i++)
#pragma unroll
        for (int j = 0; j < 8; j++) acc[i][j] = 0.f;

    const int nt = K >> 3;
    for (int t = 0; t < nt; t++) {
        float4 av = *(const float4*)Ap;  Ap += 8;
        float4 bv = *(const float4*)Bp;  Bp += (size_t)8 * N;
        __syncthreads();
        As[acol + 0][arow] = av.x;
        As[acol + 1][arow] = av.y;
        As[acol + 2][arow] = av.z;
        As[acol + 3][arow] = av.w;
        *(float4*)&Bs[brow][bcol] = bv;
        __syncthreads();
#pragma unroll
        for (int kk = 0; kk < 8; kk++) {
            float4 a0 = *(const float4*)&As[kk][m0];
            float4 a1 = *(const float4*)&As[kk][m0 + 4];
            float4 b0 = *(const float4*)&Bs[kk][n0];
            float4 b1 = *(const float4*)&Bs[kk][n0 + 4];
            float af[8] = {a0.x, a0.y, a0.z, a0.w, a1.x, a1.y, a1.z, a1.w};
            float bf[8] = {b0.x, b0.y, b0.z, b0.w, b1.x, b1.y, b1.z, b1.w};
#pragma unroll
            for (int i = 0; i < 8; i++)
#pragma unroll
                for (int j = 0; j < 8; j++)
                    acc[i][j] = fmaf(af[i], bf[j], acc[i][j]);
        }
    }

    float bb[8];
#pragma unroll
    for (int j = 0; j < 8; j++) bb[j] = bias[bn + n0 + j];
#pragma unroll
    for (int i = 0; i < 8; i++) {
        float* Cp = C + (size_t)(bm + m0 + i) * N + bn + n0;
        float4 o0 = {acc[i][0] + bb[0], acc[i][1] + bb[1], acc[i][2] + bb[2], acc[i][3] + bb[3]};
        float4 o1 = {acc[i][4] + bb[4], acc[i][5] + bb[5], acc[i][6] + bb[6], acc[i][7] + bb[7]};
        *(float4*)Cp       = o0;
        *(float4*)(Cp + 4) = o1;
    }
}

// ---------------- self attention (causal + additive key mask) ----------------
// grid (SX/64, H, B); 256 threads = 16x16; per-thread 4 queries x 4 keys/dims.
__global__ __launch_bounds__(256, 2)
void attn_self(const float* __restrict__ qkv, const float* __restrict__ mask,
               float* __restrict__ cat)
{
    extern __shared__ float sm[];
    float* Qs = sm;              // [64][64]   Q (pre-scaled)
    float* Ks = Qs + 64 * 64;    // [64][65]   K tile (padded)
    float* Vs = Ks + 64 * 65;    // [64][64]   V tile
    float* Ps = Vs + 64 * 64;    // [64][64]   P[q][j]
    float* Ms = Ps + 64 * 64;    // [64]       additive key mask tile

    const int qt = blockIdx.x, h = blockIdx.y, b = blockIdx.z;
    const int tid = threadIdx.x;
    const int ty = tid >> 4, tx = tid & 15;
    const int q0 = ty << 2, n0 = tx << 2, d0 = tx << 2;

    const size_t base = (size_t)b * SXX * 3072;
    const float* Qg = qkv + base + (size_t)(qt * 64) * 3072 + h * 64;
    for (int idx = tid; idx < 4096; idx += 256) {
        int r = idx >> 6, c = idx & 63;
        Qs[(r << 6) + c] = Qg[(size_t)r * 3072 + c] * 0.125f;
    }

    float m_i[4] = {-1e30f, -1e30f, -1e30f, -1e30f};
    float l_i[4] = {0.f, 0.f, 0.f, 0.f};
    float o[4][4];
#pragma unroll
    for (int i = 0; i < 4; i++)
#pragma unroll
        for (int j = 0; j < 4; j++) o[i][j] = 0.f;

    const float* maskb = mask + b * SXX;
    const int lenx = g_lens[b];
    int jlim = (qt + 1) * 64;
    int lr = ((lenx + 63) >> 6) << 6;    // keys beyond this are exp-underflowed anyway
    if (lr < jlim) jlim = lr;
    const int ntile = jlim >> 6;

    for (int t = 0; t < ntile; t++) {
        const float* Kg = qkv + base + (size_t)(t * 64) * 3072 + 1024 + h * 64;
        const float* Vg = Kg + 1024;
        __syncthreads();
        for (int idx = tid; idx < 4096; idx += 256) {
            int r = idx >> 6, c = idx & 63;
            Ks[r * 65 + c]     = Kg[(size_t)r * 3072 + c];
            Vs[(r << 6) + c]   = Vg[(size_t)r * 3072 + c];
        }
        if (tid < 64) Ms[tid] = maskb[t * 64 + tid];
        __syncthreads();

        float s[4][4];
#pragma unroll
        for (int i = 0; i < 4; i++)
#pragma unroll
            for (int j = 0; j < 4; j++) s[i][j] = 0.f;

#pragma unroll 4
        for (int k = 0; k < 64; k++) {
            float a0 = Qs[(q0 + 0) * 64 + k];
            float a1 = Qs[(q0 + 1) * 64 + k];
            float a2 = Qs[(q0 + 2) * 64 + k];
            float a3 = Qs[(q0 + 3) * 64 + k];
            float k0 = Ks[(n0 + 0) * 65 + k];
            float k1 = Ks[(n0 + 1) * 65 + k];
            float k2 = Ks[(n0 + 2) * 65 + k];
            float k3 = Ks[(n0 + 3) * 65 + k];
            s[0][0] = fmaf(a0, k0, s[0][0]); s[0][1] = fmaf(a0, k1, s[0][1]);
            s[0][2] = fmaf(a0, k2, s[0][2]); s[0][3] = fmaf(a0, k3, s[0][3]);
            s[1][0] = fmaf(a1, k0, s[1][0]); s[1][1] = fmaf(a1, k1, s[1][1]);
            s[1][2] = fmaf(a1, k2, s[1][2]); s[1][3] = fmaf(a1, k3, s[1][3]);
            s[2][0] = fmaf(a2, k0, s[2][0]); s[2][1] = fmaf(a2, k1, s[2][1]);
            s[2][2] = fmaf(a2, k2, s[2][2]); s[2][3] = fmaf(a2, k3, s[2][3]);
            s[3][0] = fmaf(a3, k0, s[3][0]); s[3][1] = fmaf(a3, k1, s[3][1]);
            s[3][2] = fmaf(a3, k2, s[3][2]); s[3][3] = fmaf(a3, k3, s[3][3]);
        }

        const int jbase = t * 64 + n0;
        const int ibase = qt * 64 + q0;
#pragma unroll
        for (int iq = 0; iq < 4; iq++) {
            const int ig = ibase + iq;
#pragma unroll
            for (int jn = 0; jn < 4; jn++) {
                const int jg = jbase + jn;
                float v = (jg <= ig) ? s[iq][jn] : -10000.f;   // ref: w*b1 - 10000*(1-b1)
                s[iq][jn] = v + Ms[n0 + jn];                   // + attention_mask_x
            }
        }
#pragma unroll
        for (int iq = 0; iq < 4; iq++) {
            float mloc = fmaxf(fmaxf(s[iq][0], s[iq][1]), fmaxf(s[iq][2], s[iq][3]));
#pragma unroll
            for (int off = 8; off > 0; off >>= 1)
                mloc = fmaxf(mloc, __shfl_xor_sync(0xffffffffu, mloc, off));
            float mnew  = fmaxf(m_i[iq], mloc);
            float alpha = __expf(m_i[iq] - mnew);
            float rs = 0.f;
#pragma unroll
            for (int jn = 0; jn < 4; jn++) {
                float p = __expf(s[iq][jn] - mnew);
                s[iq][jn] = p;
                rs += p;
            }
#pragma unroll
            for (int off = 8; off > 0; off >>= 1)
                rs += __shfl_xor_sync(0xffffffffu, rs, off);
            l_i[iq] = l_i[iq] * alpha + rs;
            m_i[iq] = mnew;
#pragma unroll
            for (int dj = 0; dj < 4; dj++) o[iq][dj] *= alpha;
#pragma unroll
            for (int jn = 0; jn < 4; jn++) Ps[(q0 + iq) * 64 + n0 + jn] = s[iq][jn];
        }
        __syncthreads();
#pragma unroll 4
        for (int j = 0; j < 64; j++) {
            float p0 = Ps[(q0 + 0) * 64 + j];
            float p1 = Ps[(q0 + 1) * 64 + j];
            float p2 = Ps[(q0 + 2) * 64 + j];
            float p3 = Ps[(q0 + 3) * 64 + j];
            float v0 = Vs[(j << 6) + d0 + 0];
            float v1 = Vs[(j << 6) + d0 + 1];
            float v2 = Vs[(j << 6) + d0 + 2];
            float v3 = Vs[(j << 6) + d0 + 3];
            o[0][0] = fmaf(p0, v0, o[0][0]); o[0][1] = fmaf(p0, v1, o[0][1]);
            o[0][2] = fmaf(p0, v2, o[0][2]); o[0][3] = fmaf(p0, v3, o[0][3]);
            o[1][0] = fmaf(p1, v0, o[1][0]); o[1][1] = fmaf(p1, v1, o[1][1]);
            o[1][2] = fmaf(p1, v2, o[1][2]); o[1][3] = fmaf(p1, v3, o[1][3]);
            o[2][0] = fmaf(p2, v0, o[2][0]); o[2][1] = fmaf(p2, v1, o[2][1]);
            o[2][2] = fmaf(p2, v2, o[2][2]); o[2][3] = fmaf(p2, v3, o[2][3]);
            o[3][0] = fmaf(p3, v0, o[3][0]); o[3][1] = fmaf(p3, v1, o[3][1]);
            o[3][2] = fmaf(p3, v2, o[3][2]); o[3][3] = fmaf(p3, v3, o[3][3]);
        }
    }

    float* Og = cat + (size_t)b * SXX * 2048 + (size_t)(qt * 64) * 2048 + h * 64;
#pragma unroll
    for (int iq = 0; iq < 4; iq++) {
        float inv = 1.0f / l_i[iq];
#pragma unroll
        for (int dj = 0; dj < 4; dj++)
            Og[(size_t)(q0 + iq) * 2048 + d0 + dj] = o[iq][dj] * inv;
    }
}

// ---------------- cross attention (right-aligned queries, bounded keys) ----------------
__global__ __launch_bounds__(256, 2)
void attn_cross(const float* __restrict__ q2, const float* __restrict__ kv2,
                float* __restrict__ cat)
{
    extern __shared__ float sm[];
    float* Qs = sm;
    float* Ks = Qs + 64 * 64;    // [64][65]
    float* Vs = Ks + 64 * 65;
    float* Ps = Vs + 64 * 64;

    const int qt = blockIdx.x, h = blockIdx.y, b = blockIdx.z;
    const int tid = threadIdx.x;
    const int ty = tid >> 4, tx = tid & 15;
    const int q0 = ty << 2, n0 = tx << 2, d0 = tx << 2;

    const int lenx = g_lens[b], leny = g_lens[2 + b];
    const int off  = FULLN - lenx;   // query i sits at global row off+i

    float* Og = cat + (size_t)b * SXX * 2048 + (size_t)(qt * 64) * 2048 + 1024 + h * 64;

    if (qt * 64 >= lenx) {           // whole block past valid queries -> zeros
        for (int idx = tid; idx < 4096; idx += 256) {
            int r = idx >> 6, c = idx & 63;
            Og[(size_t)r * 2048 + c] = 0.f;
        }
        return;
    }

    const float* Qg = q2 + (size_t)b * SXX * 1024 + (size_t)(qt * 64) * 1024 + h * 64;
    for (int idx = tid; idx < 4096; idx += 256) {
        int r = idx >> 6, c = idx & 63;
        Qs[(r << 6) + c] = Qg[(size_t)r * 1024 + c] * 0.125f;
    }

    float m_i[4] = {-1e30f, -1e30f, -1e30f, -1e30f};
    float l_i[4] = {0.f, 0.f, 0.f, 0.f};
    float o[4][4];
#pragma unroll
    for (int i = 0; i < 4; i++)
#pragma unroll
        for (int j = 0; j < 4; j++) o[i][j] = 0.f;

    int qlast = qt * 64 + 63;
    if (qlast >= lenx) qlast = lenx - 1;
    int jmax = off + qlast + 1;
    if (jmax > leny) jmax = leny;
    const int ntile = (jmax + 63) >> 6;

    for (int t = 0; t < ntile; t++) {
        const float* Kg = kv2 + (size_t)b * SYY * 2048 + (size_t)(t * 64) * 2048 + h * 64;
        const float* Vg = Kg + 1024;
        __syncthreads();
        for (int idx = tid; idx < 4096; idx += 256) {
            int r = idx >> 6, c = idx & 63;
            Ks[r * 65 + c]   = Kg[(size_t)r * 2048 + c];
            Vs[(r << 6) + c] = Vg[(size_t)r * 2048 + c];
        }
        __syncthreads();

        float s[4][4];
#pragma unroll
        for (int i = 0; i < 4; i++)
#pragma unroll
            for (int j = 0; j < 4; j++) s[i][j] = 0.f;

#pragma unroll 4
        for (int k = 0; k < 64; k++) {
            float a0 = Qs[(q0 + 0) * 64 + k];
            float a1 = Qs[(q0 + 1) * 64 + k];
            float a2 = Qs[(q0 + 2) * 64 + k];
            float a3 = Qs[(q0 + 3) * 64 + k];
            float k0 = Ks[(n0 + 0) * 65 + k];
            float k1 = Ks[(n0 + 1) * 65 + k];
            float k2 = Ks[(n0 + 2) * 65 + k];
            float k3 = Ks[(n0 + 3) * 65 + k];
            s[0][0] = fmaf(a0, k0, s[0][0]); s[0][1] = fmaf(a0, k1, s[0][1]);
            s[0][2] = fmaf(a0, k2, s[0][2]); s[0][3] = fmaf(a0, k3, s[0][3]);
            s[1][0] = fmaf(a1, k0, s[1][0]); s[1][1] = fmaf(a1, k1, s[1][1]);
            s[1][2] = fmaf(a1, k2, s[1][2]); s[1][3] = fmaf(a1, k3, s[1][3]);
            s[2][0] = fmaf(a2, k0, s[2][0]); s[2][1] = fmaf(a2, k1, s[2][1]);
            s[2][2] = fmaf(a2, k2, s[2][2]); s[2][3] = fmaf(a2, k3, s[2][3]);
            s[3][0] = fmaf(a3, k0, s[3][0]); s[3][1] = fmaf(a3, k1, s[3][1]);
            s[3][2] = fmaf(a3, k2, s[3][2]); s[3][3] = fmaf(a3, k3, s[3][3]);
        }

        const int jbase = t * 64 + n0;
        const int ibase = off + qt * 64 + q0;
#pragma unroll
        for (int iq = 0; iq < 4; iq++) {
            const int ig = ibase + iq;
#pragma unroll
            for (int jn = 0; jn < 4; jn++) {
                const int jg = jbase + jn;
                bool ok = (jg <= ig) && (jg < leny);   // masked entries exp-underflow to 0 exactly
                if (!ok) s[iq][jn] = -1e30f;
            }
        }
#pragma unroll
        for (int iq = 0; iq < 4; iq++) {
            float mloc = fmaxf(fmaxf(s[iq][0], s[iq][1]), fmaxf(s[iq][2], s[iq][3]));
#pragma unroll
            for (int off2 = 8; off2 > 0; off2 >>= 1)
                mloc = fmaxf(mloc, __shfl_xor_sync(0xffffffffu, mloc, off2));
            float mnew  = fmaxf(m_i[iq], mloc);
            float alpha = __expf(m_i[iq] - mnew);
            float rs = 0.f;
#pragma unroll
            for (int jn = 0; jn < 4; jn++) {
                float p = __expf(s[iq][jn] - mnew);
                s[iq][jn] = p;
                rs += p;
            }
#pragma unroll
            for (int off2 = 8; off2 > 0; off2 >>= 1)
                rs += __shfl_xor_sync(0xffffffffu, rs, off2);
            l_i[iq] = l_i[iq] * alpha + rs;
            m_i[iq] = mnew;
#pragma unroll
            for (int dj = 0; dj < 4; dj++) o[iq][dj] *= alpha;
#pragma unroll
            for (int jn = 0; jn < 4; jn++) Ps[(q0 + iq) * 64 + n0 + jn] = s[iq][jn];
        }
        __syncthreads();
#pragma unroll 4
        for (int j = 0; j < 64; j++) {
            float p0 = Ps[(q0 + 0) * 64 + j];
            float p1 = Ps[(q0 + 1) * 64 + j];
            float p2 = Ps[(q0 + 2) * 64 + j];
            float p3 = Ps[(q0 + 3) * 64 + j];
            float v0 = Vs[(j << 6) + d0 + 0];
            float v1 = Vs[(j << 6) + d0 + 1];
            float v2 = Vs[(j << 6) + d0 + 2];
            float v3 = Vs[(j << 6) + d0 + 3];
            o[0][0] = fmaf(p0, v0, o[0][0]); o[0][1] = fmaf(p0, v1, o[0][1]);
            o[0][2] = fmaf(p0, v2, o[0][2]); o[0][3] = fmaf(p0, v3, o[0][3]);
            o[1][0] = fmaf(p1, v0, o[1][0]); o[1][1] = fmaf(p1, v1, o[1][1]);
            o[1][2] = fmaf(p1, v2, o[1][2]); o[1][3] = fmaf(p1, v3, o[1][3]);
            o[2][0] = fmaf(p2, v0, o[2][0]); o[2][1] = fmaf(p2, v1, o[2][1]);
            o[2][2] = fmaf(p2, v2, o[2][2]); o[2][3] = fmaf(p2, v3, o[2][3]);
            o[3][0] = fmaf(p3, v0, o[3][0]); o[3][1] = fmaf(p3, v1, o[3][1]);
            o[3][2] = fmaf(p3, v2, o[3][2]); o[3][3] = fmaf(p3, v3, o[3][3]);
        }
    }

#pragma unroll
    for (int iq = 0; iq < 4; iq++) {
        int irow = qt * 64 + q0 + iq;
        if (irow < lenx) {
            float inv = 1.0f / l_i[iq];
#pragma unroll
            for (int dj = 0; dj < 4; dj++)
                Og[(size_t)(q0 + iq) * 2048 + d0 + dj] = o[iq][dj] * inv;
        } else {
#pragma unroll
            for (int dj = 0; dj < 4; dj++)
                Og[(size_t)(q0 + iq) * 2048 + d0 + dj] = 0.f;
        }
    }
}

// ---------------- launch ----------------
extern "C" void kernel_launch(void* const* d_in, const int* in_sizes, int n_in,
                              void* d_out, int out_size)
{
    const float* x      = (const float*)d_in[0];
    const float* y      = (const float*)d_in[1];
    const float* maskx  = (const float*)d_in[2];
    const float* W_attn = (const float*)d_in[3];
    const float* b_attn = (const float*)d_in[4];
    const float* W_2a   = (const float*)d_in[5];
    const float* b_2a   = (const float*)d_in[6];
    const float* W_2b   = (const float*)d_in[7];
    const float* b_2b   = (const float*)d_in[8];
    const float* W_proj = (const float*)d_in[9];
    const float* b_proj = (const float*)d_in[10];
    const int*   xtb    = (const int*)d_in[11];
    const int*   ytb    = (const int*)d_in[15];

    float *qkv, *q2, *kv2, *cat;
    cudaGetSymbolAddress((void**)&qkv, g_qkv);
    cudaGetSymbolAddress((void**)&q2,  g_q2);
    cudaGetSymbolAddress((void**)&kv2, g_kv2);
    cudaGetSymbolAddress((void**)&cat, g_cat);

    const int SMEM_ATTN = (64 * 64 + 64 * 65 + 64 * 64 + 64 * 64 + 64) * 4;  // 66304 B
    cudaFuncSetAttribute((const void*)attn_self,  cudaFuncAttributeMaxDynamicSharedMemorySize, SMEM_ATTN);
    cudaFuncSetAttribute((const void*)attn_cross, cudaFuncAttributeMaxDynamicSharedMemorySize, SMEM_ATTN);

    lens_kernel<<<1, 256>>>(xtb, in_sizes[11], ytb, in_sizes[15]);

    // qkv = x @ W_attn + b_attn            [2048, 3072]
    sgemm128<<<dim3(24, 16), 256>>>(x, W_attn, b_attn, qkv, 2048, 3072, 1024);
    // q2 = x @ W_2a + b_2a                 [2048, 1024]
    sgemm128<<<dim3(8, 16), 256>>>(x, W_2a, b_2a, q2, 2048, 1024, 1024);
    // kv2 = y @ W_2b + b_2b                [2048, 2048]
    sgemm128<<<dim3(16, 16), 256>>>(y, W_2b, b_2b, kv2, 2048, 2048, 1024);

    attn_self <<<dim3(16, 16, 2), 256, SMEM_ATTN>>>(qkv, maskx, cat);
    attn_cross<<<dim3(16, 16, 2), 256, SMEM_ATTN>>>(q2, kv2, cat);

    // out = cat @ W_proj + b_proj          [2048, 1024]
    sgemm128<<<dim3(8, 16), 256>>>(cat, W_proj, b_proj, (float*)d_out, 2048, 1024, 2048);
}

// round 4
// speedup vs baseline: 1.7482x; 1.7482x over previous
#include <cuda_runtime.h>
#include <cuda_bf16.h>
#include <cstdint>

#define NB    2
#define SXX   1024
#define SYY   1024
#define DIM   1024
#define NH    16
#define HDIM  64
#define FULLN 1536

// ---------------- scratch (device globals; no allocation allowed) ----------------
__device__ float g_qkv[NB * SXX * 3 * DIM];   // [b, i, 3*D]  (Q|K|V)
__device__ float g_q2 [NB * SXX * DIM];       // [b, i, D]
__device__ float g_kv2[NB * SYY * 2 * DIM];   // [b, j, 2*D]  (K2|V2)
__device__ float g_cat[NB * SXX * 2 * DIM];   // [b, i, 2*D]  (a | a2m)
__device__ int   g_lens[4];

// bf16 hi/lo splits (raw u16)
__device__ unsigned short g_xh[2048 * 1024],  g_xl[2048 * 1024];
__device__ unsigned short g_yh[2048 * 1024],  g_yl[2048 * 1024];
__device__ unsigned short g_ch[2048 * 2048],  g_cl[2048 * 2048];
// weights transposed to [N, K] K-major, split hi/lo
__device__ unsigned short g_wqkv_h[3072 * 1024], g_wqkv_l[3072 * 1024];
__device__ unsigned short g_w2a_h [1024 * 1024], g_w2a_l [1024 * 1024];
__device__ unsigned short g_w2b_h [2048 * 1024], g_w2b_l [2048 * 1024];
__device__ unsigned short g_wpj_h [1024 * 2048], g_wpj_l [1024 * 2048];

// ---------------- helpers ----------------
__device__ __forceinline__ uint32_t smem_u32(const void* p) {
    uint32_t a;
    asm("{ .reg .u64 t; cvta.to.shared.u64 t, %1; cvt.u32.u64 %0, t; }" : "=r"(a) : "l"(p));
    return a;
}
#define CP_ASYNC16(dst, src) \
    asm volatile("cp.async.ca.shared.global [%0], [%1], 16;" :: "r"(dst), "l"(src) : "memory")
#define CP_COMMIT() asm volatile("cp.async.commit_group;" ::: "memory")
#define CP_WAIT1()  asm volatile("cp.async.wait_group 1;" ::: "memory")
#define CP_WAIT0()  asm volatile("cp.async.wait_group 0;" ::: "memory")

#define MMA_BF16(c, a0, a1, a2, a3, b0, b1) \
    asm volatile("mma.sync.aligned.m16n8k16.row.col.f32.bf16.bf16.f32 " \
        "{%0,%1,%2,%3}, {%4,%5,%6,%7}, {%8,%9}, {%0,%1,%2,%3};" \
        : "+f"((c)[0]), "+f"((c)[1]), "+f"((c)[2]), "+f"((c)[3]) \
        : "r"(a0), "r"(a1), "r"(a2), "r"(a3), "r"(b0), "r"(b1))

// ---------------- per-batch lengths ----------------
__global__ void lens_kernel(const int* __restrict__ xb, int nx,
                            const int* __restrict__ yb, int ny)
{
    __shared__ int cnt[4];
    int t = threadIdx.x;
    if (t < 4) cnt[t] = 0;
    __syncthreads();
    for (int i = t; i < nx; i += blockDim.x) atomicAdd(&cnt[xb[i]], 1);
    for (int i = t; i < ny; i += blockDim.x) atomicAdd(&cnt[2 + yb[i]], 1);
    __syncthreads();
    if (t < 4) g_lens[t] = cnt[t];
}

// ---------------- fp32 -> bf16 hi/lo split ----------------
__global__ __launch_bounds__(256)
void split_fp32(const float* __restrict__ in, unsigned short* __restrict__ oh,
                unsigned short* __restrict__ ol, int n4)
{
    int i = blockIdx.x * 256 + threadIdx.x;
    if (i >= n4) return;
    float4 v = ((const float4*)in)[i];
    __nv_bfloat16 h0 = __float2bfloat16_rn(v.x);
    __nv_bfloat16 h1 = __float2bfloat16_rn(v.y);
    __nv_bfloat16 h2 = __float2bfloat16_rn(v.z);
    __nv_bfloat16 h3 = __float2bfloat16_rn(v.w);
    __nv_bfloat16 l0 = __float2bfloat16_rn(v.x - __bfloat162float(h0));
    __nv_bfloat16 l1 = __float2bfloat16_rn(v.y - __bfloat162float(h1));
    __nv_bfloat16 l2 = __float2bfloat16_rn(v.z - __bfloat162float(h2));
    __nv_bfloat16 l3 = __float2bfloat16_rn(v.w - __bfloat162float(h3));
    ushort4 hv = { *(unsigned short*)&h0, *(unsigned short*)&h1,
                   *(unsigned short*)&h2, *(unsigned short*)&h3 };
    ushort4 lv = { *(unsigned short*)&l0, *(unsigned short*)&l1,
                   *(unsigned short*)&l2, *(unsigned short*)&l3 };
    ((ushort4*)oh)[i] = hv;
    ((ushort4*)ol)[i] = lv;
}

// ---------------- W[K,N] -> Wt[N,K] bf16 hi/lo ----------------
__global__ __launch_bounds__(256)
void transpose_split(const float* __restrict__ in, unsigned short* __restrict__ oh,
                     unsigned short* __restrict__ ol, int K, int N)
{
    __shared__ float tile[32][33];
    int n0 = blockIdx.x << 5, k0 = blockIdx.y << 5;
    int tx = threadIdx.x & 31, ty = threadIdx.x >> 5;
    for (int i = ty; i < 32; i += 8)
        tile[i][tx] = in[(size_t)(k0 + i) * N + n0 + tx];
    __syncthreads();
    for (int i = ty; i < 32; i += 8) {
        float v = tile[tx][i];
        __nv_bfloat16 h = __float2bfloat16_rn(v);
        __nv_bfloat16 l = __float2bfloat16_rn(v - __bfloat162float(h));
        size_t o = (size_t)(n0 + i) * K + k0 + tx;
        oh[o] = *(unsigned short*)&h;
        ol[o] = *(unsigned short*)&l;
    }
}

// ---------------- mma.sync bf16 split GEMM: C[M,N] = A @ B^T + bias ----------------
// A: [M,K] hi/lo, B: [N,K] hi/lo (both K-major). 128x128 tile, K-chunk 32,
// 8 warps (2x4), warp tile 64x32. cp.async double buffer.
// C = Ah*Bh + Ah*Bl + Al*Bh (fp32 accum).
#define TS   (128 * 40)        // one tile in u16 elements (stride 40)
__global__ __launch_bounds__(256)
void gemm_mma(const unsigned short* __restrict__ Ah, const unsigned short* __restrict__ Al,
              const unsigned short* __restrict__ Bh, const unsigned short* __restrict__ Bl,
              const float* __restrict__ bias, float* __restrict__ C,
              int M, int N, int K)
{
    extern __shared__ unsigned short sm16[];
    unsigned short* sAh = sm16;             // [2][128][40]
    unsigned short* sAl = sm16 + 2 * TS;
    unsigned short* sBh = sm16 + 4 * TS;
    unsigned short* sBl = sm16 + 6 * TS;
    const uint32_t uAh = smem_u32(sAh), uAl = smem_u32(sAl);
    const uint32_t uBh = smem_u32(sBh), uBl = smem_u32(sBl);

    const int tid  = threadIdx.x;
    const int lane = tid & 31, wid = tid >> 5;
    const int wm = (wid >> 2) << 6;       // 0 / 64
    const int wn = (wid & 3) << 5;        // 0/32/64/96
    const int bm = blockIdx.y << 7, bn = blockIdx.x << 7;

    float acc[4][4][4];
#pragma unroll
    for (int i = 0; i < 4; i++)
#pragma unroll
        for (int j = 0; j < 4; j++)
#pragma unroll
            for (int k = 0; k < 4; k++) acc[i][j][k] = 0.f;

    const int lr = tid >> 2;        // 0..63  (load row base)
    const int ls = tid & 3;         // seg 0..3 (8 bf16 each)
    const int nchunk = K >> 5;

    // ---- prefetch chunk t into buffer t&1 ----
#define PREFETCH(t) do { \
        int buf_ = (t) & 1; \
        int k0_  = (t) << 5; \
        _Pragma("unroll") \
        for (int p_ = 0; p_ < 2; p_++) { \
            int row_ = lr + (p_ << 6); \
            uint32_t so_ = (uint32_t)(buf_ * TS + row_ * 40 + ls * 8) * 2; \
            size_t ao_ = (size_t)(bm + row_) * K + k0_ + ls * 8; \
            size_t bo_ = (size_t)(bn + row_) * K + k0_ + ls * 8; \
            CP_ASYNC16(uAh + so_, Ah + ao_); \
            CP_ASYNC16(uAl + so_, Al + ao_); \
            CP_ASYNC16(uBh + so_, Bh + bo_); \
            CP_ASYNC16(uBl + so_, Bl + bo_); \
        } \
    } while (0)

    PREFETCH(0);
    CP_COMMIT();

    const int fr = lane >> 2;           // fragment row / n within group
    const int fc = (lane & 3) << 1;     // fragment k pair

    for (int t = 0; t < nchunk; t++) {
        if (t + 1 < nchunk) { PREFETCH(t + 1); CP_COMMIT(); CP_WAIT1(); }
        else                { CP_WAIT0(); }
        __syncthreads();
        const int buf = (t & 1) * TS;
#pragma unroll
        for (int kk = 0; kk < 32; kk += 16) {
            uint32_t bhf[4][2], blf[4][2];
#pragma unroll
            for (int ni = 0; ni < 4; ni++) {
                int nrow = buf + (wn + (ni << 3) + fr) * 40 + kk + fc;
                bhf[ni][0] = *(const uint32_t*)&sBh[nrow];
                bhf[ni][1] = *(const uint32_t*)&sBh[nrow + 8];
                blf[ni][0] = *(const uint32_t*)&sBl[nrow];
                blf[ni][1] = *(const uint32_t*)&sBl[nrow + 8];
            }
#pragma unroll
            for (int mi = 0; mi < 4; mi++) {
                int ar0 = buf + (wm + (mi << 4) + fr) * 40 + kk + fc;
                int ar1 = ar0 + 8 * 40;
                uint32_t ah0 = *(const uint32_t*)&sAh[ar0];
                uint32_t ah1 = *(const uint32_t*)&sAh[ar1];
                uint32_t ah2 = *(const uint32_t*)&sAh[ar0 + 8];
                uint32_t ah3 = *(const uint32_t*)&sAh[ar1 + 8];
                uint32_t al0 = *(const uint32_t*)&sAl[ar0];
                uint32_t al1 = *(const uint32_t*)&sAl[ar1];
                uint32_t al2 = *(const uint32_t*)&sAl[ar0 + 8];
                uint32_t al3 = *(const uint32_t*)&sAl[ar1 + 8];
#pragma unroll
                for (int ni = 0; ni < 4; ni++) {
                    MMA_BF16(acc[mi][ni], ah0, ah1, ah2, ah3, bhf[ni][0], bhf[ni][1]);
                    MMA_BF16(acc[mi][ni], ah0, ah1, ah2, ah3, blf[ni][0], blf[ni][1]);
                    MMA_BF16(acc[mi][ni], al0, al1, al2, al3, bhf[ni][0], bhf[ni][1]);
                }
            }
        }
        __syncthreads();
    }

    // ---- epilogue: add bias, store fp32 ----
#pragma unroll
    for (int mi = 0; mi < 4; mi++) {
        int row = bm + wm + (mi << 4) + fr;
#pragma unroll
        for (int ni = 0; ni < 4; ni++) {
            int col = bn + wn + (ni << 3) + fc;
            float bx = bias[col], by = bias[col + 1];
            float2 v0 = { acc[mi][ni][0] + bx, acc[mi][ni][1] + by };
            float2 v1 = { acc[mi][ni][2] + bx, acc[mi][ni][3] + by };
            *(float2*)(C + (size_t)row * N + col)       = v0;
            *(float2*)(C + (size_t)(row + 8) * N + col) = v1;
        }
    }
}

// ---------------- self attention ----------------
__global__ __launch_bounds__(256, 2)
void attn_self(const float* __restrict__ qkv, const float* __restrict__ mask,
               float* __restrict__ cat)
{
    extern __shared__ float smf[];
    float* Qs = smf;
    float* Ks = Qs + 64 * 64;
    float* Vs = Ks + 64 * 65;
    float* Ps = Vs + 64 * 64;
    float* Ms = Ps + 64 * 64;

    const int qt = blockIdx.x, h = blockIdx.y, b = blockIdx.z;
    const int tid = threadIdx.x;
    const int ty = tid >> 4, tx = tid & 15;
    const int q0 = ty << 2, n0 = tx << 2, d0 = tx << 2;

    const size_t base = (size_t)b * SXX * 3072;
    const float* Qg = qkv + base + (size_t)(qt * 64) * 3072 + h * 64;
    for (int idx = tid; idx < 4096; idx += 256) {
        int r = idx >> 6, c = idx & 63;
        Qs[(r << 6) + c] = Qg[(size_t)r * 3072 + c] * 0.125f;
    }

    float m_i[4] = {-1e30f, -1e30f, -1e30f, -1e30f};
    float l_i[4] = {0.f, 0.f, 0.f, 0.f};
    float o[4][4];
#pragma unroll
    for (int i = 0; i < 4; i++)
#pragma unroll
        for (int j = 0; j < 4; j++) o[i][j] = 0.f;

    const float* maskb = mask + b * SXX;
    const int lenx = g_lens[b];
    int jlim = (qt + 1) * 64;
    int lrr = ((lenx + 63) >> 6) << 6;
    if (lrr < jlim) jlim = lrr;
    const int ntile = jlim >> 6;

    for (int t = 0; t < ntile; t++) {
        const float* Kg = qkv + base + (size_t)(t * 64) * 3072 + 1024 + h * 64;
        const float* Vg = Kg + 1024;
        __syncthreads();
        for (int idx = tid; idx < 4096; idx += 256) {
            int r = idx >> 6, c = idx & 63;
            Ks[r * 65 + c]   = Kg[(size_t)r * 3072 + c];
            Vs[(r << 6) + c] = Vg[(size_t)r * 3072 + c];
        }
        if (tid < 64) Ms[tid] = maskb[t * 64 + tid];
        __syncthreads();

        float s[4][4];
#pragma unroll
        for (int i = 0; i < 4; i++)
#pragma unroll
            for (int j = 0; j < 4; j++) s[i][j] = 0.f;

#pragma unroll 4
        for (int k = 0; k < 64; k++) {
            float a0 = Qs[(q0 + 0) * 64 + k];
            float a1 = Qs[(q0 + 1) * 64 + k];
            float a2 = Qs[(q0 + 2) * 64 + k];
            float a3 = Qs[(q0 + 3) * 64 + k];
            float k0 = Ks[(n0 + 0) * 65 + k];
            float k1 = Ks[(n0 + 1) * 65 + k];
            float k2 = Ks[(n0 + 2) * 65 + k];
            float k3 = Ks[(n0 + 3) * 65 + k];
            s[0][0] = fmaf(a0, k0, s[0][0]); s[0][1] = fmaf(a0, k1, s[0][1]);
            s[0][2] = fmaf(a0, k2, s[0][2]); s[0][3] = fmaf(a0, k3, s[0][3]);
            s[1][0] = fmaf(a1, k0, s[1][0]); s[1][1] = fmaf(a1, k1, s[1][1]);
            s[1][2] = fmaf(a1, k2, s[1][2]); s[1][3] = fmaf(a1, k3, s[1][3]);
            s[2][0] = fmaf(a2, k0, s[2][0]); s[2][1] = fmaf(a2, k1, s[2][1]);
            s[2][2] = fmaf(a2, k2, s[2][2]); s[2][3] = fmaf(a2, k3, s[2][3]);
            s[3][0] = fmaf(a3, k0, s[3][0]); s[3][1] = fmaf(a3, k1, s[3][1]);
            s[3][2] = fmaf(a3, k2, s[3][2]); s[3][3] = fmaf(a3, k3, s[3][3]);
        }

        const int jbase = t * 64 + n0;
        const int ibase = qt * 64 + q0;
#pragma unroll
        for (int iq = 0; iq < 4; iq++) {
            const int ig = ibase + iq;
#pragma unroll
            for (int jn = 0; jn < 4; jn++) {
                const int jg = jbase + jn;
                float v = (jg <= ig) ? s[iq][jn] : -10000.f;
                s[iq][jn] = v + Ms[n0 + jn];
            }
        }
#pragma unroll
        for (int iq = 0; iq < 4; iq++) {
            float mloc = fmaxf(fmaxf(s[iq][0], s[iq][1]), fmaxf(s[iq][2], s[iq][3]));
#pragma unroll
            for (int off = 8; off > 0; off >>= 1)
                mloc = fmaxf(mloc, __shfl_xor_sync(0xffffffffu, mloc, off));
            float mnew  = fmaxf(m_i[iq], mloc);
            float alpha = __expf(m_i[iq] - mnew);
            float rs = 0.f;
#pragma unroll
            for (int jn = 0; jn < 4; jn++) {
                float p = __expf(s[iq][jn] - mnew);
                s[iq][jn] = p;
                rs += p;
            }
#pragma unroll
            for (int off = 8; off > 0; off >>= 1)
                rs += __shfl_xor_sync(0xffffffffu, rs, off);
            l_i[iq] = l_i[iq] * alpha + rs;
            m_i[iq] = mnew;
#pragma unroll
            for (int dj = 0; dj < 4; dj++) o[iq][dj] *= alpha;
#pragma unroll
            for (int jn = 0; jn < 4; jn++) Ps[(q0 + iq) * 64 + n0 + jn] = s[iq][jn];
        }
        __syncthreads();
#pragma unroll 4
        for (int j = 0; j < 64; j++) {
            float p0 = Ps[(q0 + 0) * 64 + j];
            float p1 = Ps[(q0 + 1) * 64 + j];
            float p2 = Ps[(q0 + 2) * 64 + j];
            float p3 = Ps[(q0 + 3) * 64 + j];
            float v0 = Vs[(j << 6) + d0 + 0];
            float v1 = Vs[(j << 6) + d0 + 1];
            float v2 = Vs[(j << 6) + d0 + 2];
            float v3 = Vs[(j << 6) + d0 + 3];
            o[0][0] = fmaf(p0, v0, o[0][0]); o[0][1] = fmaf(p0, v1, o[0][1]);
            o[0][2] = fmaf(p0, v2, o[0][2]); o[0][3] = fmaf(p0, v3, o[0][3]);
            o[1][0] = fmaf(p1, v0, o[1][0]); o[1][1] = fmaf(p1, v1, o[1][1]);
            o[1][2] = fmaf(p1, v2, o[1][2]); o[1][3] = fmaf(p1, v3, o[1][3]);
            o[2][0] = fmaf(p2, v0, o[2][0]); o[2][1] = fmaf(p2, v1, o[2][1]);
            o[2][2] = fmaf(p2, v2, o[2][2]); o[2][3] = fmaf(p2, v3, o[2][3]);
            o[3][0] = fmaf(p3, v0, o[3][0]); o[3][1] = fmaf(p3, v1, o[3][1]);
            o[3][2] = fmaf(p3, v2, o[3][2]); o[3][3] = fmaf(p3, v3, o[3][3]);
        }
    }

    float* Og = cat + (size_t)b * SXX * 2048 + (size_t)(qt * 64) * 2048 + h * 64;
#pragma unroll
    for (int iq = 0; iq < 4; iq++) {
        float inv = 1.0f / l_i[iq];
#pragma unroll
        for (int dj = 0; dj < 4; dj++)
            Og[(size_t)(q0 + iq) * 2048 + d0 + dj] = o[iq][dj] * inv;
    }
}

// ---------------- cross attention ----------------
__global__ __launch_bounds__(256, 2)
void attn_cross(const float* __restrict__ q2, const float* __restrict__ kv2,
                float* __restrict__ cat)
{
    extern __shared__ float smf[];
    float* Qs = smf;
    float* Ks = Qs + 64 * 64;
    float* Vs = Ks + 64 * 65;
    float* Ps = Vs + 64 * 64;

    const int qt = blockIdx.x, h = blockIdx.y, b = blockIdx.z;
    const int tid = threadIdx.x;
    const int ty = tid >> 4, tx = tid & 15;
    const int q0 = ty << 2, n0 = tx << 2, d0 = tx << 2;

    const int lenx = g_lens[b], leny = g_lens[2 + b];
    const int off  = FULLN - lenx;

    float* Og = cat + (size_t)b * SXX * 2048 + (size_t)(qt * 64) * 2048 + 1024 + h * 64;

    if (qt * 64 >= lenx) {
        for (int idx = tid; idx < 4096; idx += 256) {
            int r = idx >> 6, c = idx & 63;
            Og[(size_t)r * 2048 + c] = 0.f;
        }
        return;
    }

    const float* Qg = q2 + (size_t)b * SXX * 1024 + (size_t)(qt * 64) * 1024 + h * 64;
    for (int idx = tid; idx < 4096; idx += 256) {
        int r = idx >> 6, c = idx & 63;
        Qs[(r << 6) + c] = Qg[(size_t)r * 1024 + c] * 0.125f;
    }

    float m_i[4] = {-1e30f, -1e30f, -1e30f, -1e30f};
    float l_i[4] = {0.f, 0.f, 0.f, 0.f};
    float o[4][4];
#pragma unroll
    for (int i = 0; i < 4; i++)
#pragma unroll
        for (int j = 0; j < 4; j++) o[i][j] = 0.f;

    int qlast = qt * 64 + 63;
    if (qlast >= lenx) qlast = lenx - 1;
    int jmax = off + qlast + 1;
    if (jmax > leny) jmax = leny;
    const int ntile = (jmax + 63) >> 6;

    for (int t = 0; t < ntile; t++) {
        const float* Kg = kv2 + (size_t)b * SYY * 2048 + (size_t)(t * 64) * 2048 + h * 64;
        const float* Vg = Kg + 1024;
        __syncthreads();
        for (int idx = tid; idx < 4096; idx += 256) {
            int r = idx >> 6, c = idx & 63;
            Ks[r * 65 + c]   = Kg[(size_t)r * 2048 + c];
            Vs[(r << 6) + c] = Vg[(size_t)r * 2048 + c];
        }
        __syncthreads();

        float s[4][4];
#pragma unroll
        for (int i = 0; i < 4; i++)
#pragma unroll
            for (int j = 0; j < 4; j++) s[i][j] = 0.f;

#pragma unroll 4
        for (int k = 0; k < 64; k++) {
            float a0 = Qs[(q0 + 0) * 64 + k];
            float a1 = Qs[(q0 + 1) * 64 + k];
            float a2 = Qs[(q0 + 2) * 64 + k];
            float a3 = Qs[(q0 + 3) * 64 + k];
            float k0 = Ks[(n0 + 0) * 65 + k];
            float k1 = Ks[(n0 + 1) * 65 + k];
            float k2 = Ks[(n0 + 2) * 65 + k];
            float k3 = Ks[(n0 + 3) * 65 + k];
            s[0][0] = fmaf(a0, k0, s[0][0]); s[0][1] = fmaf(a0, k1, s[0][1]);
            s[0][2] = fmaf(a0, k2, s[0][2]); s[0][3] = fmaf(a0, k3, s[0][3]);
            s[1][0] = fmaf(a1, k0, s[1][0]); s[1][1] = fmaf(a1, k1, s[1][1]);
            s[1][2] = fmaf(a1, k2, s[1][2]); s[1][3] = fmaf(a1, k3, s[1][3]);
            s[2][0] = fmaf(a2, k0, s[2][0]); s[2][1] = fmaf(a2, k1, s[2][1]);
            s[2][2] = fmaf(a2, k2, s[2][2]); s[2][3] = fmaf(a2, k3, s[2][3]);
            s[3][0] = fmaf(a3, k0, s[3][0]); s[3][1] = fmaf(a3, k1, s[3][1]);
            s[3][2] = fmaf(a3, k2, s[3][2]); s[3][3] = fmaf(a3, k3, s[3][3]);
        }

        const int jbase = t * 64 + n0;
        const int ibase = off + qt * 64 + q0;
#pragma unroll
        for (int iq = 0; iq < 4; iq++) {
            const int ig = ibase + iq;
#pragma unroll
            for (int jn = 0; jn < 4; jn++) {
                const int jg = jbase + jn;
                bool ok = (jg <= ig) && (jg < leny);
                if (!ok) s[iq][jn] = -1e30f;
            }
        }
#pragma unroll
        for (int iq = 0; iq < 4; iq++) {
            float mloc = fmaxf(fmaxf(s[iq][0], s[iq][1]), fmaxf(s[iq][2], s[iq][3]));
#pragma unroll
            for (int off2 = 8; off2 > 0; off2 >>= 1)
                mloc = fmaxf(mloc, __shfl_xor_sync(0xffffffffu, mloc, off2));
            float mnew  = fmaxf(m_i[iq], mloc);
            float alpha = __expf(m_i[iq] - mnew);
            float rs = 0.f;
#pragma unroll
            for (int jn = 0; jn < 4; jn++) {
                float p = __expf(s[iq][jn] - mnew);
                s[iq][jn] = p;
                rs += p;
            }
#pragma unroll
            for (int off2 = 8; off2 > 0; off2 >>= 1)
                rs += __shfl_xor_sync(0xffffffffu, rs, off2);
            l_i[iq] = l_i[iq] * alpha + rs;
            m_i[iq] = mnew;
#pragma unroll
            for (int dj = 0; dj < 4; dj++) o[iq][dj] *= alpha;
#pragma unroll
            for (int jn = 0; jn < 4; jn++) Ps[(q0 + iq) * 64 + n0 + jn] = s[iq][jn];
        }
        __syncthreads();
#pragma unroll 4
        for (int j = 0; j < 64; j++) {
            float p0 = Ps[(q0 + 0) * 64 + j];
            float p1 = Ps[(q0 + 1) * 64 + j];
            float p2 = Ps[(q0 + 2) * 64 + j];
            float p3 = Ps[(q0 + 3) * 64 + j];
            float v0 = Vs[(j << 6) + d0 + 0];
            float v1 = Vs[(j << 6) + d0 + 1];
            float v2 = Vs[(j << 6) + d0 + 2];
            float v3 = Vs[(j << 6) + d0 + 3];
            o[0][0] = fmaf(p0, v0, o[0][0]); o[0][1] = fmaf(p0, v1, o[0][1]);
            o[0][2] = fmaf(p0, v2, o[0][2]); o[0][3] = fmaf(p0, v3, o[0][3]);
            o[1][0] = fmaf(p1, v0, o[1][0]); o[1][1] = fmaf(p1, v1, o[1][1]);
            o[1][2] = fmaf(p1, v2, o[1][2]); o[1][3] = fmaf(p1, v3, o[1][3]);
            o[2][0] = fmaf(p2, v0, o[2][0]); o[2][1] = fmaf(p2, v1, o[2][1]);
            o[2][2] = fmaf(p2, v2, o[2][2]); o[2][3] = fmaf(p2, v3, o[2][3]);
            o[3][0] = fmaf(p3, v0, o[3][0]); o[3][1] = fmaf(p3, v1, o[3][1]);
            o[3][2] = fmaf(p3, v2, o[3][2]); o[3][3] = fmaf(p3, v3, o[3][3]);
        }
    }

#pragma unroll
    for (int iq = 0; iq < 4; iq++) {
        int irow = qt * 64 + q0 + iq;
        if (irow < lenx) {
            float inv = 1.0f / l_i[iq];
#pragma unroll
            for (int dj = 0; dj < 4; dj++)
                Og[(size_t)(q0 + iq) * 2048 + d0 + dj] = o[iq][dj] * inv;
        } else {
#pragma unroll
            for (int dj = 0; dj < 4; dj++)
                Og[(size_t)(q0 + iq) * 2048 + d0 + dj] = 0.f;
        }
    }
}

// ---------------- launch ----------------
extern "C" void kernel_launch(void* const* d_in, const int* in_sizes, int n_in,
                              void* d_out, int out_size)
{
    const float* x      = (const float*)d_in[0];
    const float* y      = (const float*)d_in[1];
    const float* maskx  = (const float*)d_in[2];
    const float* W_attn = (const float*)d_in[3];
    const float* b_attn = (const float*)d_in[4];
    const float* W_2a   = (const float*)d_in[5];
    const float* b_2a   = (const float*)d_in[6];
    const float* W_2b   = (const float*)d_in[7];
    const float* b_2b   = (const float*)d_in[8];
    const float* W_proj = (const float*)d_in[9];
    const float* b_proj = (const float*)d_in[10];
    const int*   xtb    = (const int*)d_in[11];
    const int*   ytb    = (const int*)d_in[15];

    float *qkv, *q2, *kv2, *cat;
    cudaGetSymbolAddress((void**)&qkv, g_qkv);
    cudaGetSymbolAddress((void**)&q2,  g_q2);
    cudaGetSymbolAddress((void**)&kv2, g_kv2);
    cudaGetSymbolAddress((void**)&cat, g_cat);
    unsigned short *xh, *xl, *yh, *yl, *ch, *cl;
    unsigned short *wqh, *wql, *wah, *wal, *wbh, *wbl, *wph, *wpl;
    cudaGetSymbolAddress((void**)&xh, g_xh);   cudaGetSymbolAddress((void**)&xl, g_xl);
    cudaGetSymbolAddress((void**)&yh, g_yh);   cudaGetSymbolAddress((void**)&yl, g_yl);
    cudaGetSymbolAddress((void**)&ch, g_ch);   cudaGetSymbolAddress((void**)&cl, g_cl);
    cudaGetSymbolAddress((void**)&wqh, g_wqkv_h); cudaGetSymbolAddress((void**)&wql, g_wqkv_l);
    cudaGetSymbolAddress((void**)&wah, g_w2a_h);  cudaGetSymbolAddress((void**)&wal, g_w2a_l);
    cudaGetSymbolAddress((void**)&wbh, g_w2b_h);  cudaGetSymbolAddress((void**)&wbl, g_w2b_l);
    cudaGetSymbolAddress((void**)&wph, g_wpj_h);  cudaGetSymbolAddress((void**)&wpl, g_wpj_l);

    const int SMEM_ATTN = (64 * 64 + 64 * 65 + 64 * 64 + 64 * 64 + 64) * 4;
    const int SMEM_GEMM = 8 * TS * 2;  // 81920 B
    cudaFuncSetAttribute((const void*)attn_self,  cudaFuncAttributeMaxDynamicSharedMemorySize, SMEM_ATTN);
    cudaFuncSetAttribute((const void*)attn_cross, cudaFuncAttributeMaxDynamicSharedMemorySize, SMEM_ATTN);
    cudaFuncSetAttribute((const void*)gemm_mma,   cudaFuncAttributeMaxDynamicSharedMemorySize, SMEM_GEMM);

    lens_kernel<<<1, 256>>>(xtb, in_sizes[11], ytb, in_sizes[15]);

    // split activations
    split_fp32<<<2048, 256>>>(x, xh, xl, 2048 * 1024 / 4);
    split_fp32<<<2048, 256>>>(y, yh, yl, 2048 * 1024 / 4);
    // transpose + split weights -> [N, K]
    transpose_split<<<dim3(96, 32), 256>>>(W_attn, wqh, wql, 1024, 3072);
    transpose_split<<<dim3(32, 32), 256>>>(W_2a,   wah, wal, 1024, 1024);
    transpose_split<<<dim3(64, 32), 256>>>(W_2b,   wbh, wbl, 1024, 2048);
    transpose_split<<<dim3(32, 64), 256>>>(W_proj, wph, wpl, 2048, 1024);

    // tensor-core GEMMs (mma.sync bf16 3-term split)
    gemm_mma<<<dim3(24, 16), 256, SMEM_GEMM>>>(xh, xl, wqh, wql, b_attn, qkv, 2048, 3072, 1024);
    gemm_mma<<<dim3(8,  16), 256, SMEM_GEMM>>>(xh, xl, wah, wal, b_2a,   q2,  2048, 1024, 1024);
    gemm_mma<<<dim3(16, 16), 256, SMEM_GEMM>>>(yh, yl, wbh, wbl, b_2b,   kv2, 2048, 2048, 1024);

    attn_self <<<dim3(16, 16, 2), 256, SMEM_ATTN>>>(qkv, maskx, cat);
    attn_cross<<<dim3(16, 16, 2), 256, SMEM_ATTN>>>(q2, kv2, cat);

    // out = cat @ W_proj + b_proj
    split_fp32<<<4096, 256>>>(cat, ch, cl, 2048 * 2048 / 4);
    gemm_mma<<<dim3(8, 16), 256, SMEM_GEMM>>>(ch, cl, wph, wpl, b_proj, (float*)d_out, 2048, 1024, 2048);
}

// round 5
// speedup vs baseline: 2.1726x; 1.2428x over previous
#include <cuda_runtime.h>
#include <cuda_bf16.h>
#include <cstdint>

#define NB    2
#define SXX   1024
#define SYY   1024
#define DIM   1024
#define NH    16
#define HDIM  64
#define FULLN 1536

// ---------------- scratch (device globals; no allocation allowed) ----------------
__device__ int g_lens[4];

// bf16 hi/lo activation splits
__device__ unsigned short g_xh [2048 * 1024], g_xl [2048 * 1024];
__device__ unsigned short g_yh [2048 * 1024], g_yl [2048 * 1024];
// GEMM outputs in hi/lo
__device__ unsigned short g_qkvh[2048 * 3072], g_qkvl[2048 * 3072];
__device__ unsigned short g_q2h [2048 * 1024], g_q2l [2048 * 1024];
__device__ unsigned short g_kv2h[2048 * 2048], g_kv2l[2048 * 2048];
__device__ unsigned short g_cath[2048 * 2048], g_catl[2048 * 2048];
// weights transposed to [N, K] K-major, split hi/lo
__device__ unsigned short g_wqkv_h[3072 * 1024], g_wqkv_l[3072 * 1024];
__device__ unsigned short g_w2a_h [1024 * 1024], g_w2a_l [1024 * 1024];
__device__ unsigned short g_w2b_h [2048 * 1024], g_w2b_l [2048 * 1024];
__device__ unsigned short g_wpj_h [1024 * 2048], g_wpj_l [1024 * 2048];

// ---------------- helpers ----------------
__device__ __forceinline__ uint32_t smem_u32(const void* p) {
    uint32_t a;
    asm("{ .reg .u64 t; cvta.to.shared.u64 t, %1; cvt.u32.u64 %0, t; }" : "=r"(a) : "l"(p));
    return a;
}
#define CP_ASYNC16(dst, src) \
    asm volatile("cp.async.ca.shared.global [%0], [%1], 16;" :: "r"(dst), "l"(src) : "memory")
#define CP_COMMIT() asm volatile("cp.async.commit_group;" ::: "memory")
#define CP_WAIT1()  asm volatile("cp.async.wait_group 1;" ::: "memory")
#define CP_WAIT0()  asm volatile("cp.async.wait_group 0;" ::: "memory")

#define MMA_BF16(c, a0, a1, a2, a3, b0, b1) \
    asm volatile("mma.sync.aligned.m16n8k16.row.col.f32.bf16.bf16.f32 " \
        "{%0,%1,%2,%3}, {%4,%5,%6,%7}, {%8,%9}, {%0,%1,%2,%3};" \
        : "+f"((c)[0]), "+f"((c)[1]), "+f"((c)[2]), "+f"((c)[3]) \
        : "r"(a0), "r"(a1), "r"(a2), "r"(a3), "r"(b0), "r"(b1))

__device__ __forceinline__ void split_pack(float a, float b, uint32_t& h, uint32_t& l) {
    __nv_bfloat16 ha = __float2bfloat16_rn(a), hb = __float2bfloat16_rn(b);
    __nv_bfloat16 la = __float2bfloat16_rn(a - __bfloat162float(ha));
    __nv_bfloat16 lb = __float2bfloat16_rn(b - __bfloat162float(hb));
    h = (uint32_t)*(unsigned short*)&ha | ((uint32_t)*(unsigned short*)&hb << 16);
    l = (uint32_t)*(unsigned short*)&la | ((uint32_t)*(unsigned short*)&lb << 16);
}

// ---------------- per-batch lengths ----------------
__global__ void lens_kernel(const int* __restrict__ xb, int nx,
                            const int* __restrict__ yb, int ny)
{
    __shared__ int cnt[4];
    int t = threadIdx.x;
    if (t < 4) cnt[t] = 0;
    __syncthreads();
    for (int i = t; i < nx; i += blockDim.x) atomicAdd(&cnt[xb[i]], 1);
    for (int i = t; i < ny; i += blockDim.x) atomicAdd(&cnt[2 + yb[i]], 1);
    __syncthreads();
    if (t < 4) g_lens[t] = cnt[t];
}

// ---------------- fp32 -> bf16 hi/lo split ----------------
__global__ __launch_bounds__(256)
void split_fp32(const float* __restrict__ in, unsigned short* __restrict__ oh,
                unsigned short* __restrict__ ol, int n4)
{
    int i = blockIdx.x * 256 + threadIdx.x;
    if (i >= n4) return;
    float4 v = ((const float4*)in)[i];
    uint32_t h0, l0, h1, l1;
    split_pack(v.x, v.y, h0, l0);
    split_pack(v.z, v.w, h1, l1);
    ((uint2*)oh)[i] = make_uint2(h0, h1);
    ((uint2*)ol)[i] = make_uint2(l0, l1);
}

// ---------------- W[K,N] -> Wt[N,K] bf16 hi/lo ----------------
__global__ __launch_bounds__(256)
void transpose_split(const float* __restrict__ in, unsigned short* __restrict__ oh,
                     unsigned short* __restrict__ ol, int K, int N)
{
    __shared__ float tile[32][33];
    int n0 = blockIdx.x << 5, k0 = blockIdx.y << 5;
    int tx = threadIdx.x & 31, ty = threadIdx.x >> 5;
    for (int i = ty; i < 32; i += 8)
        tile[i][tx] = in[(size_t)(k0 + i) * N + n0 + tx];
    __syncthreads();
    for (int i = ty; i < 32; i += 8) {
        float v = tile[tx][i];
        __nv_bfloat16 h = __float2bfloat16_rn(v);
        __nv_bfloat16 l = __float2bfloat16_rn(v - __bfloat162float(h));
        size_t o = (size_t)(n0 + i) * K + k0 + tx;
        oh[o] = *(unsigned short*)&h;
        ol[o] = *(unsigned short*)&l;
    }
}

// ---------------- mma.sync bf16 split GEMM ----------------
// C = A @ B^T + bias;  A:[M,K] hi/lo, B:[N,K] hi/lo.  128x128 tile, K-chunk 32,
// 8 warps, cp.async double buffer.  Output: fp32 (Cf) OR bf16 hi/lo (Ch/Cl).
#define TS   (128 * 40)
__global__ __launch_bounds__(256)
void gemm_mma(const unsigned short* __restrict__ Ah, const unsigned short* __restrict__ Al,
              const unsigned short* __restrict__ Bh, const unsigned short* __restrict__ Bl,
              const float* __restrict__ bias, float* __restrict__ Cf,
              unsigned short* __restrict__ Ch, unsigned short* __restrict__ Cl,
              int M, int N, int K)
{
    extern __shared__ unsigned short sm16[];
    unsigned short* sAh = sm16;
    unsigned short* sAl = sm16 + 2 * TS;
    unsigned short* sBh = sm16 + 4 * TS;
    unsigned short* sBl = sm16 + 6 * TS;
    const uint32_t uAh = smem_u32(sAh), uAl = smem_u32(sAl);
    const uint32_t uBh = smem_u32(sBh), uBl = smem_u32(sBl);

    const int tid  = threadIdx.x;
    const int lane = tid & 31, wid = tid >> 5;
    const int wm = (wid >> 2) << 6;
    const int wn = (wid & 3) << 5;
    const int bm = blockIdx.y << 7, bn = blockIdx.x << 7;

    float acc[4][4][4];
#pragma unroll
    for (int i = 0; i < 4; i++)
#pragma unroll
        for (int j = 0; j < 4; j++)
#pragma unroll
            for (int k = 0; k < 4; k++) acc[i][j][k] = 0.f;

    const int lr = tid >> 2;
    const int ls = tid & 3;
    const int nchunk = K >> 5;

#define PREFETCH(t) do { \
        int buf_ = (t) & 1; \
        int k0_  = (t) << 5; \
        _Pragma("unroll") \
        for (int p_ = 0; p_ < 2; p_++) { \
            int row_ = lr + (p_ << 6); \
            uint32_t so_ = (uint32_t)(buf_ * TS + row_ * 40 + ls * 8) * 2; \
            size_t ao_ = (size_t)(bm + row_) * K + k0_ + ls * 8; \
            size_t bo_ = (size_t)(bn + row_) * K + k0_ + ls * 8; \
            CP_ASYNC16(uAh + so_, Ah + ao_); \
            CP_ASYNC16(uAl + so_, Al + ao_); \
            CP_ASYNC16(uBh + so_, Bh + bo_); \
            CP_ASYNC16(uBl + so_, Bl + bo_); \
        } \
    } while (0)

    PREFETCH(0);
    CP_COMMIT();

    const int fr = lane >> 2;
    const int fc = (lane & 3) << 1;

    for (int t = 0; t < nchunk; t++) {
        if (t + 1 < nchunk) { PREFETCH(t + 1); CP_COMMIT(); CP_WAIT1(); }
        else                { CP_WAIT0(); }
        __syncthreads();
        const int buf = (t & 1) * TS;
#pragma unroll
        for (int kk = 0; kk < 32; kk += 16) {
            uint32_t bhf[4][2], blf[4][2];
#pragma unroll
            for (int ni = 0; ni < 4; ni++) {
                int nrow = buf + (wn + (ni << 3) + fr) * 40 + kk + fc;
                bhf[ni][0] = *(const uint32_t*)&sBh[nrow];
                bhf[ni][1] = *(const uint32_t*)&sBh[nrow + 8];
                blf[ni][0] = *(const uint32_t*)&sBl[nrow];
                blf[ni][1] = *(const uint32_t*)&sBl[nrow + 8];
            }
#pragma unroll
            for (int mi = 0; mi < 4; mi++) {
                int ar0 = buf + (wm + (mi << 4) + fr) * 40 + kk + fc;
                int ar1 = ar0 + 8 * 40;
                uint32_t ah0 = *(const uint32_t*)&sAh[ar0];
                uint32_t ah1 = *(const uint32_t*)&sAh[ar1];
                uint32_t ah2 = *(const uint32_t*)&sAh[ar0 + 8];
                uint32_t ah3 = *(const uint32_t*)&sAh[ar1 + 8];
                uint32_t al0 = *(const uint32_t*)&sAl[ar0];
                uint32_t al1 = *(const uint32_t*)&sAl[ar1];
                uint32_t al2 = *(const uint32_t*)&sAl[ar0 + 8];
                uint32_t al3 = *(const uint32_t*)&sAl[ar1 + 8];
#pragma unroll
                for (int ni = 0; ni < 4; ni++) {
                    MMA_BF16(acc[mi][ni], ah0, ah1, ah2, ah3, bhf[ni][0], bhf[ni][1]);
                    MMA_BF16(acc[mi][ni], ah0, ah1, ah2, ah3, blf[ni][0], blf[ni][1]);
                    MMA_BF16(acc[mi][ni], al0, al1, al2, al3, bhf[ni][0], bhf[ni][1]);
                }
            }
        }
        __syncthreads();
    }

    if (Cf) {
#pragma unroll
        for (int mi = 0; mi < 4; mi++) {
            int row = bm + wm + (mi << 4) + fr;
#pragma unroll
            for (int ni = 0; ni < 4; ni++) {
                int col = bn + wn + (ni << 3) + fc;
                float bx = bias[col], by = bias[col + 1];
                float2 v0 = { acc[mi][ni][0] + bx, acc[mi][ni][1] + by };
                float2 v1 = { acc[mi][ni][2] + bx, acc[mi][ni][3] + by };
                *(float2*)(Cf + (size_t)row * N + col)       = v0;
                *(float2*)(Cf + (size_t)(row + 8) * N + col) = v1;
            }
        }
    } else {
#pragma unroll
        for (int mi = 0; mi < 4; mi++) {
            int row = bm + wm + (mi << 4) + fr;
#pragma unroll
            for (int ni = 0; ni < 4; ni++) {
                int col = bn + wn + (ni << 3) + fc;
                float bx = bias[col], by = bias[col + 1];
                uint32_t hh, ll;
                split_pack(acc[mi][ni][0] + bx, acc[mi][ni][1] + by, hh, ll);
                *(uint32_t*)&Ch[(size_t)row * N + col] = hh;
                *(uint32_t*)&Cl[(size_t)row * N + col] = ll;
                split_pack(acc[mi][ni][2] + bx, acc[mi][ni][3] + by, hh, ll);
                *(uint32_t*)&Ch[(size_t)(row + 8) * N + col] = hh;
                *(uint32_t*)&Cl[(size_t)(row + 8) * N + col] = ll;
            }
        }
    }
}

// ================= MMA flash attention =================
// 64 queries x 64 keys per tile; 4 warps x 16 rows; HD=64.
// Scores: Qh*Kh + Qh*Kl + Ql*Kh;  PV: Ph*Vh + Ph*Vl + Pl*Vh.
#define AST 72   // smem row stride (u16); (row*36 + seg) mod 32 bijective per frag load

// ---------------- self attention ----------------
__global__ __launch_bounds__(128)
void attn_self_mma(const unsigned short* __restrict__ qkvh,
                   const unsigned short* __restrict__ qkvl,
                   const float* __restrict__ mask,
                   unsigned short* __restrict__ cath,
                   unsigned short* __restrict__ catl)
{
    extern __shared__ char smraw[];
    unsigned short* sQh = (unsigned short*)smraw;
    unsigned short* sQl = sQh + 64 * AST;
    unsigned short* sKh = sQl + 64 * AST;
    unsigned short* sKl = sKh + 64 * AST;
    unsigned short* sVh = sKl + 64 * AST;    // transposed [dim][key]
    unsigned short* sVl = sVh + 64 * AST;
    float* sMs = (float*)(sVl + 64 * AST);

    const int qt = blockIdx.x, h = blockIdx.y, b = blockIdx.z;
    const int tid = threadIdx.x, lane = tid & 31, wid = tid >> 5;
    const int q0 = wid << 4;
    const int r = lane >> 2, cq = (lane & 3) << 1;

    const size_t gb = (size_t)b * SXX * 3072;
    for (int i = tid; i < 512; i += 128) {
        int rr = i >> 3, seg = i & 7;
        size_t src = gb + (size_t)(qt * 64 + rr) * 3072 + h * 64 + seg * 8;
        *(uint4*)&sQh[rr * AST + seg * 8] = *(const uint4*)&qkvh[src];
        *(uint4*)&sQl[rr * AST + seg * 8] = *(const uint4*)&qkvl[src];
    }

    float o[8][4];
#pragma unroll
    for (int i = 0; i < 8; i++)
#pragma unroll
        for (int j = 0; j < 4; j++) o[i][j] = 0.f;
    float mrow0 = -1e30f, mrow1 = -1e30f, lrow0 = 0.f, lrow1 = 0.f;

    const float* maskb = mask + b * SXX;
    const int lenx = g_lens[b];
    int nt1 = qt + 1, nt2 = (lenx + 63) >> 6;
    const int ntile = nt1 < nt2 ? nt1 : nt2;

    for (int t = 0; t < ntile; t++) {
        __syncthreads();
        for (int i = tid; i < 512; i += 128) {
            int rr = i >> 3, seg = i & 7;
            size_t src = gb + (size_t)(t * 64 + rr) * 3072 + 1024 + h * 64 + seg * 8;
            *(uint4*)&sKh[rr * AST + seg * 8] = *(const uint4*)&qkvh[src];
            *(uint4*)&sKl[rr * AST + seg * 8] = *(const uint4*)&qkvl[src];
        }
        for (int i = tid; i < 4096; i += 128) {
            int rr = i >> 6, c = i & 63;
            size_t src = gb + (size_t)(t * 64 + rr) * 3072 + 2048 + h * 64 + c;
            sVh[c * AST + rr] = qkvh[src];
            sVl[c * AST + rr] = qkvl[src];
        }
        if (tid < 64) sMs[tid] = maskb[t * 64 + tid];
        __syncthreads();

        float sc[8][4];
#pragma unroll
        for (int i = 0; i < 8; i++)
#pragma unroll
            for (int j = 0; j < 4; j++) sc[i][j] = 0.f;

#pragma unroll
        for (int kt = 0; kt < 4; kt++) {
            int ro0 = (q0 + r) * AST + kt * 16 + cq;
            int ro1 = ro0 + 8 * AST;
            uint32_t ah0 = *(uint32_t*)&sQh[ro0], ah1 = *(uint32_t*)&sQh[ro1];
            uint32_t ah2 = *(uint32_t*)&sQh[ro0 + 8], ah3 = *(uint32_t*)&sQh[ro1 + 8];
            uint32_t al0 = *(uint32_t*)&sQl[ro0], al1 = *(uint32_t*)&sQl[ro1];
            uint32_t al2 = *(uint32_t*)&sQl[ro0 + 8], al3 = *(uint32_t*)&sQl[ro1 + 8];
#pragma unroll
            for (int nt = 0; nt < 8; nt++) {
                int bo = (nt * 8 + r) * AST + kt * 16 + cq;
                uint32_t bh0 = *(uint32_t*)&sKh[bo], bh1 = *(uint32_t*)&sKh[bo + 8];
                uint32_t bl0 = *(uint32_t*)&sKl[bo], bl1 = *(uint32_t*)&sKl[bo + 8];
                MMA_BF16(sc[nt], ah0, ah1, ah2, ah3, bh0, bh1);
                MMA_BF16(sc[nt], ah0, ah1, ah2, ah3, bl0, bl1);
                MMA_BF16(sc[nt], al0, al1, al2, al3, bh0, bh1);
            }
        }

        const int grow = qt * 64 + q0 + r;
#pragma unroll
        for (int nt = 0; nt < 8; nt++) {
            int c0 = t * 64 + nt * 8 + cq;
            float m0 = sMs[nt * 8 + cq], m1 = sMs[nt * 8 + cq + 1];
            float v;
            v = sc[nt][0] * 0.125f; sc[nt][0] = ((c0     <= grow    ) ? v : -10000.f) + m0;
            v = sc[nt][1] * 0.125f; sc[nt][1] = ((c0 + 1 <= grow    ) ? v : -10000.f) + m1;
            v = sc[nt][2] * 0.125f; sc[nt][2] = ((c0     <= grow + 8) ? v : -10000.f) + m0;
            v = sc[nt][3] * 0.125f; sc[nt][3] = ((c0 + 1 <= grow + 8) ? v : -10000.f) + m1;
        }

        float mx0 = -1e30f, mx1 = -1e30f;
#pragma unroll
        for (int nt = 0; nt < 8; nt++) {
            mx0 = fmaxf(mx0, fmaxf(sc[nt][0], sc[nt][1]));
            mx1 = fmaxf(mx1, fmaxf(sc[nt][2], sc[nt][3]));
        }
        mx0 = fmaxf(mx0, __shfl_xor_sync(0xffffffffu, mx0, 1));
        mx0 = fmaxf(mx0, __shfl_xor_sync(0xffffffffu, mx0, 2));
        mx1 = fmaxf(mx1, __shfl_xor_sync(0xffffffffu, mx1, 1));
        mx1 = fmaxf(mx1, __shfl_xor_sync(0xffffffffu, mx1, 2));
        float mn0 = fmaxf(mrow0, mx0), mn1 = fmaxf(mrow1, mx1);
        float al0f = __expf(mrow0 - mn0), al1f = __expf(mrow1 - mn1);
        float s0 = 0.f, s1 = 0.f;
#pragma unroll
        for (int nt = 0; nt < 8; nt++) {
            sc[nt][0] = __expf(sc[nt][0] - mn0); s0 += sc[nt][0];
            sc[nt][1] = __expf(sc[nt][1] - mn0); s0 += sc[nt][1];
            sc[nt][2] = __expf(sc[nt][2] - mn1); s1 += sc[nt][2];
            sc[nt][3] = __expf(sc[nt][3] - mn1); s1 += sc[nt][3];
        }
        s0 += __shfl_xor_sync(0xffffffffu, s0, 1);
        s0 += __shfl_xor_sync(0xffffffffu, s0, 2);
        s1 += __shfl_xor_sync(0xffffffffu, s1, 1);
        s1 += __shfl_xor_sync(0xffffffffu, s1, 2);
        lrow0 = lrow0 * al0f + s0; mrow0 = mn0;
        lrow1 = lrow1 * al1f + s1; mrow1 = mn1;
#pragma unroll
        for (int nt = 0; nt < 8; nt++) {
            o[nt][0] *= al0f; o[nt][1] *= al0f;
            o[nt][2] *= al1f; o[nt][3] *= al1f;
        }

#pragma unroll
        for (int kc = 0; kc < 4; kc++) {
            uint32_t ph[4], pl[4];
            split_pack(sc[2*kc][0],   sc[2*kc][1],   ph[0], pl[0]);
            split_pack(sc[2*kc][2],   sc[2*kc][3],   ph[1], pl[1]);
            split_pack(sc[2*kc+1][0], sc[2*kc+1][1], ph[2], pl[2]);
            split_pack(sc[2*kc+1][2], sc[2*kc+1][3], ph[3], pl[3]);
#pragma unroll
            for (int dn = 0; dn < 8; dn++) {
                int vo = (dn * 8 + r) * AST + kc * 16 + cq;
                uint32_t vh0 = *(uint32_t*)&sVh[vo], vh1 = *(uint32_t*)&sVh[vo + 8];
                uint32_t vl0 = *(uint32_t*)&sVl[vo], vl1 = *(uint32_t*)&sVl[vo + 8];
                MMA_BF16(o[dn], ph[0], ph[1], ph[2], ph[3], vh0, vh1);
                MMA_BF16(o[dn], ph[0], ph[1], ph[2], ph[3], vl0, vl1);
                MMA_BF16(o[dn], pl[0], pl[1], pl[2], pl[3], vh0, vh1);
            }
        }
    }

    float i0 = 1.f / lrow0, i1 = 1.f / lrow1;
    size_t ob = (size_t)b * SXX * 2048 + (size_t)(qt * 64 + q0 + r) * 2048 + h * 64;
#pragma unroll
    for (int dn = 0; dn < 8; dn++) {
        uint32_t hh, ll;
        split_pack(o[dn][0] * i0, o[dn][1] * i0, hh, ll);
        *(uint32_t*)&cath[ob + dn * 8 + cq] = hh;
        *(uint32_t*)&catl[ob + dn * 8 + cq] = ll;
        split_pack(o[dn][2] * i1, o[dn][3] * i1, hh, ll);
        *(uint32_t*)&cath[ob + (size_t)8 * 2048 + dn * 8 + cq] = hh;
        *(uint32_t*)&catl[ob + (size_t)8 * 2048 + dn * 8 + cq] = ll;
    }
}

// ---------------- cross attention ----------------
__global__ __launch_bounds__(128)
void attn_cross_mma(const unsigned short* __restrict__ q2h,
                    const unsigned short* __restrict__ q2l,
                    const unsigned short* __restrict__ kvh,
                    const unsigned short* __restrict__ kvl,
                    unsigned short* __restrict__ cath,
                    unsigned short* __restrict__ catl)
{
    extern __shared__ char smraw[];
    unsigned short* sQh = (unsigned short*)smraw;
    unsigned short* sQl = sQh + 64 * AST;
    unsigned short* sKh = sQl + 64 * AST;
    unsigned short* sKl = sKh + 64 * AST;
    unsigned short* sVh = sKl + 64 * AST;
    unsigned short* sVl = sVh + 64 * AST;

    const int qt = blockIdx.x, h = blockIdx.y, b = blockIdx.z;
    const int tid = threadIdx.x, lane = tid & 31, wid = tid >> 5;
    const int q0 = wid << 4;
    const int r = lane >> 2, cq = (lane & 3) << 1;

    const int lenx = g_lens[b], leny = g_lens[2 + b];
    const int off  = FULLN - lenx;

    size_t obase = (size_t)b * SXX * 2048 + (size_t)(qt * 64) * 2048 + 1024 + h * 64;
    if (qt * 64 >= lenx) {    // fully invalid -> zeros
        const uint4 z = {0, 0, 0, 0};
        for (int i = tid; i < 512; i += 128) {
            int rr = i >> 3, seg = i & 7;
            *(uint4*)&cath[obase + (size_t)rr * 2048 + seg * 8] = z;
            *(uint4*)&catl[obase + (size_t)rr * 2048 + seg * 8] = z;
        }
        return;
    }

    const size_t qgb = (size_t)b * SXX * 1024;
    for (int i = tid; i < 512; i += 128) {
        int rr = i >> 3, seg = i & 7;
        size_t src = qgb + (size_t)(qt * 64 + rr) * 1024 + h * 64 + seg * 8;
        *(uint4*)&sQh[rr * AST + seg * 8] = *(const uint4*)&q2h[src];
        *(uint4*)&sQl[rr * AST + seg * 8] = *(const uint4*)&q2l[src];
    }

    float o[8][4];
#pragma unroll
    for (int i = 0; i < 8; i++)
#pragma unroll
        for (int j = 0; j < 4; j++) o[i][j] = 0.f;
    float mrow0 = -1e30f, mrow1 = -1e30f, lrow0 = 0.f, lrow1 = 0.f;

    int qlast = qt * 64 + 63;
    if (qlast >= lenx) qlast = lenx - 1;
    int jmax = off + qlast + 1;
    if (jmax > leny) jmax = leny;
    const int ntile = (jmax + 63) >> 6;

    const size_t kgb = (size_t)b * SYY * 2048;
    for (int t = 0; t < ntile; t++) {
        __syncthreads();
        for (int i = tid; i < 512; i += 128) {
            int rr = i >> 3, seg = i & 7;
            size_t src = kgb + (size_t)(t * 64 + rr) * 2048 + h * 64 + seg * 8;
            *(uint4*)&sKh[rr * AST + seg * 8] = *(const uint4*)&kvh[src];
            *(uint4*)&sKl[rr * AST + seg * 8] = *(const uint4*)&kvl[src];
        }
        for (int i = tid; i < 4096; i += 128) {
            int rr = i >> 6, c = i & 63;
            size_t src = kgb + (size_t)(t * 64 + rr) * 2048 + 1024 + h * 64 + c;
            sVh[c * AST + rr] = kvh[src];
            sVl[c * AST + rr] = kvl[src];
        }
        __syncthreads();

        float sc[8][4];
#pragma unroll
        for (int i = 0; i < 8; i++)
#pragma unroll
            for (int j = 0; j < 4; j++) sc[i][j] = 0.f;

#pragma unroll
        for (int kt = 0; kt < 4; kt++) {
            int ro0 = (q0 + r) * AST + kt * 16 + cq;
            int ro1 = ro0 + 8 * AST;
            uint32_t ah0 = *(uint32_t*)&sQh[ro0], ah1 = *(uint32_t*)&sQh[ro1];
            uint32_t ah2 = *(uint32_t*)&sQh[ro0 + 8], ah3 = *(uint32_t*)&sQh[ro1 + 8];
            uint32_t al0 = *(uint32_t*)&sQl[ro0], al1 = *(uint32_t*)&sQl[ro1];
            uint32_t al2 = *(uint32_t*)&sQl[ro0 + 8], al3 = *(uint32_t*)&sQl[ro1 + 8];
#pragma unroll
            for (int nt = 0; nt < 8; nt++) {
                int bo = (nt * 8 + r) * AST + kt * 16 + cq;
                uint32_t bh0 = *(uint32_t*)&sKh[bo], bh1 = *(uint32_t*)&sKh[bo + 8];
                uint32_t bl0 = *(uint32_t*)&sKl[bo], bl1 = *(uint32_t*)&sKl[bo + 8];
                MMA_BF16(sc[nt], ah0, ah1, ah2, ah3, bh0, bh1);
                MMA_BF16(sc[nt], ah0, ah1, ah2, ah3, bl0, bl1);
                MMA_BF16(sc[nt], al0, al1, al2, al3, bh0, bh1);
            }
        }

        const int grow = off + qt * 64 + q0 + r;   // global causal row
#pragma unroll
        for (int nt = 0; nt < 8; nt++) {
            int c0 = t * 64 + nt * 8 + cq;
            sc[nt][0] = (c0     <= grow     && c0     < leny) ? sc[nt][0] * 0.125f : -1e30f;
            sc[nt][1] = (c0 + 1 <= grow     && c0 + 1 < leny) ? sc[nt][1] * 0.125f : -1e30f;
            sc[nt][2] = (c0     <= grow + 8 && c0     < leny) ? sc[nt][2] * 0.125f : -1e30f;
            sc[nt][3] = (c0 + 1 <= grow + 8 && c0 + 1 < leny) ? sc[nt][3] * 0.125f : -1e30f;
        }

        float mx0 = -1e30f, mx1 = -1e30f;
#pragma unroll
        for (int nt = 0; nt < 8; nt++) {
            mx0 = fmaxf(mx0, fmaxf(sc[nt][0], sc[nt][1]));
            mx1 = fmaxf(mx1, fmaxf(sc[nt][2], sc[nt][3]));
        }
        mx0 = fmaxf(mx0, __shfl_xor_sync(0xffffffffu, mx0, 1));
        mx0 = fmaxf(mx0, __shfl_xor_sync(0xffffffffu, mx0, 2));
        mx1 = fmaxf(mx1, __shfl_xor_sync(0xffffffffu, mx1, 1));
        mx1 = fmaxf(mx1, __shfl_xor_sync(0xffffffffu, mx1, 2));
        float mn0 = fmaxf(mrow0, mx0), mn1 = fmaxf(mrow1, mx1);
        float al0f = __expf(mrow0 - mn0), al1f = __expf(mrow1 - mn1);
        float s0 = 0.f, s1 = 0.f;
#pragma unroll
        for (int nt = 0; nt < 8; nt++) {
            sc[nt][0] = __expf(sc[nt][0] - mn0); s0 += sc[nt][0];
            sc[nt][1] = __expf(sc[nt][1] - mn0); s0 += sc[nt][1];
            sc[nt][2] = __expf(sc[nt][2] - mn1); s1 += sc[nt][2];
            sc[nt][3] = __expf(sc[nt][3] - mn1); s1 += sc[nt][3];
        }
        s0 += __shfl_xor_sync(0xffffffffu, s0, 1);
        s0 += __shfl_xor_sync(0xffffffffu, s0, 2);
        s1 += __shfl_xor_sync(0xffffffffu, s1, 1);
        s1 += __shfl_xor_sync(0xffffffffu, s1, 2);
        lrow0 = lrow0 * al0f + s0; mrow0 = mn0;
        lrow1 = lrow1 * al1f + s1; mrow1 = mn1;
#pragma unroll
        for (int nt = 0; nt < 8; nt++) {
            o[nt][0] *= al0f; o[nt][1] *= al0f;
            o[nt][2] *= al1f; o[nt][3] *= al1f;
        }

#pragma unroll
        for (int kc = 0; kc < 4; kc++) {
            uint32_t ph[4], pl[4];
            split_pack(sc[2*kc][0],   sc[2*kc][1],   ph[0], pl[0]);
            split_pack(sc[2*kc][2],   sc[2*kc][3],   ph[1], pl[1]);
            split_pack(sc[2*kc+1][0], sc[2*kc+1][1], ph[2], pl[2]);
            split_pack(sc[2*kc+1][2], sc[2*kc+1][3], ph[3], pl[3]);
#pragma unroll
            for (int dn = 0; dn < 8; dn++) {
                int vo = (dn * 8 + r) * AST + kc * 16 + cq;
                uint32_t vh0 = *(uint32_t*)&sVh[vo], vh1 = *(uint32_t*)&sVh[vo + 8];
                uint32_t vl0 = *(uint32_t*)&sVl[vo], vl1 = *(uint32_t*)&sVl[vo + 8];
                MMA_BF16(o[dn], ph[0], ph[1], ph[2], ph[3], vh0, vh1);
                MMA_BF16(o[dn], ph[0], ph[1], ph[2], ph[3], vl0, vl1);
                MMA_BF16(o[dn], pl[0], pl[1], pl[2], pl[3], vh0, vh1);
            }
        }
    }

    float i0 = 1.f / lrow0, i1 = 1.f / lrow1;
    int row0 = qt * 64 + q0 + r, row1 = row0 + 8;
    bool v0 = row0 < lenx, v1 = row1 < lenx;
    size_t ob = (size_t)b * SXX * 2048 + (size_t)row0 * 2048 + 1024 + h * 64;
#pragma unroll
    for (int dn = 0; dn < 8; dn++) {
        uint32_t hh = 0, ll = 0;
        if (v0) split_pack(o[dn][0] * i0, o[dn][1] * i0, hh, ll);
        *(uint32_t*)&cath[ob + dn * 8 + cq] = hh;
        *(uint32_t*)&catl[ob + dn * 8 + cq] = ll;
        hh = 0; ll = 0;
        if (v1) split_pack(o[dn][2] * i1, o[dn][3] * i1, hh, ll);
        *(uint32_t*)&cath[ob + (size_t)8 * 2048 + dn * 8 + cq] = hh;
        *(uint32_t*)&catl[ob + (size_t)8 * 2048 + dn * 8 + cq] = ll;
    }
}

// ---------------- launch ----------------
extern "C" void kernel_launch(void* const* d_in, const int* in_sizes, int n_in,
                              void* d_out, int out_size)
{
    const float* x      = (const float*)d_in[0];
    const float* y      = (const float*)d_in[1];
    const float* maskx  = (const float*)d_in[2];
    const float* W_attn = (const float*)d_in[3];
    const float* b_attn = (const float*)d_in[4];
    const float* W_2a   = (const float*)d_in[5];
    const float* b_2a   = (const float*)d_in[6];
    const float* W_2b   = (const float*)d_in[7];
    const float* b_2b   = (const float*)d_in[8];
    const float* W_proj = (const float*)d_in[9];
    const float* b_proj = (const float*)d_in[10];
    const int*   xtb    = (const int*)d_in[11];
    const int*   ytb    = (const int*)d_in[15];

    unsigned short *xh, *xl, *yh, *yl;
    unsigned short *qkvh, *qkvl, *q2h, *q2l, *kv2h, *kv2l, *cath, *catl;
    unsigned short *wqh, *wql, *wah, *wal, *wbh, *wbl, *wph, *wpl;
    cudaGetSymbolAddress((void**)&xh, g_xh);     cudaGetSymbolAddress((void**)&xl, g_xl);
    cudaGetSymbolAddress((void**)&yh, g_yh);     cudaGetSymbolAddress((void**)&yl, g_yl);
    cudaGetSymbolAddress((void**)&qkvh, g_qkvh); cudaGetSymbolAddress((void**)&qkvl, g_qkvl);
    cudaGetSymbolAddress((void**)&q2h, g_q2h);   cudaGetSymbolAddress((void**)&q2l, g_q2l);
    cudaGetSymbolAddress((void**)&kv2h, g_kv2h); cudaGetSymbolAddress((void**)&kv2l, g_kv2l);
    cudaGetSymbolAddress((void**)&cath, g_cath); cudaGetSymbolAddress((void**)&catl, g_catl);
    cudaGetSymbolAddress((void**)&wqh, g_wqkv_h); cudaGetSymbolAddress((void**)&wql, g_wqkv_l);
    cudaGetSymbolAddress((void**)&wah, g_w2a_h);  cudaGetSymbolAddress((void**)&wal, g_w2a_l);
    cudaGetSymbolAddress((void**)&wbh, g_w2b_h);  cudaGetSymbolAddress((void**)&wbl, g_w2b_l);
    cudaGetSymbolAddress((void**)&wph, g_wpj_h);  cudaGetSymbolAddress((void**)&wpl, g_wpj_l);

    const int SMEM_GEMM = 8 * TS * 2;                  // 81920 B
    const int SMEM_ATTN = 6 * 64 * AST * 2 + 64 * 4;   // 55552 B
    cudaFuncSetAttribute((const void*)gemm_mma,       cudaFuncAttributeMaxDynamicSharedMemorySize, SMEM_GEMM);
    cudaFuncSetAttribute((const void*)attn_self_mma,  cudaFuncAttributeMaxDynamicSharedMemorySize, SMEM_ATTN);
    cudaFuncSetAttribute((const void*)attn_cross_mma, cudaFuncAttributeMaxDynamicSharedMemorySize, SMEM_ATTN);

    lens_kernel<<<1, 256>>>(xtb, in_sizes[11], ytb, in_sizes[15]);

    split_fp32<<<2048, 256>>>(x, xh, xl, 2048 * 1024 / 4);
    split_fp32<<<2048, 256>>>(y, yh, yl, 2048 * 1024 / 4);
    transpose_split<<<dim3(96, 32), 256>>>(W_attn, wqh, wql, 1024, 3072);
    transpose_split<<<dim3(32, 32), 256>>>(W_2a,   wah, wal, 1024, 1024);
    transpose_split<<<dim3(64, 32), 256>>>(W_2b,   wbh, wbl, 1024, 2048);
    transpose_split<<<dim3(32, 64), 256>>>(W_proj, wph, wpl, 2048, 1024);

    gemm_mma<<<dim3(24, 16), 256, SMEM_GEMM>>>(xh, xl, wqh, wql, b_attn, nullptr, qkvh, qkvl, 2048, 3072, 1024);
    gemm_mma<<<dim3(8,  16), 256, SMEM_GEMM>>>(xh, xl, wah, wal, b_2a,   nullptr, q2h,  q2l,  2048, 1024, 1024);
    gemm_mma<<<dim3(16, 16), 256, SMEM_GEMM>>>(yh, yl, wbh, wbl, b_2b,   nullptr, kv2h, kv2l, 2048, 2048, 1024);

    attn_self_mma <<<dim3(16, 16, 2), 128, SMEM_ATTN>>>(qkvh, qkvl, maskx, cath, catl);
    attn_cross_mma<<<dim3(16, 16, 2), 128, SMEM_ATTN>>>(q2h, q2l, kv2h, kv2l, cath, catl);

    gemm_mma<<<dim3(8, 16), 256, SMEM_GEMM>>>(cath, catl, wph, wpl, b_proj, (float*)d_out, nullptr, nullptr, 2048, 1024, 2048);
}

// round 6
// speedup vs baseline: 2.7778x; 1.2785x over previous
#include <cuda_runtime.h>
#include <cuda_fp16.h>
#include <cstdint>

#define NB    2
#define SXX   1024
#define SYY   1024
#define DIM   1024
#define NH    16
#define HDIM  64
#define FULLN 1536

// ---------------- scratch (device globals) ----------------
__device__ int g_lens[4];

// fp16 hi/lo activation splits
__device__ unsigned short g_xh [2048 * 1024], g_xl [2048 * 1024];
__device__ unsigned short g_yh [2048 * 1024], g_yl [2048 * 1024];
// GEMM outputs fp16 hi/lo
__device__ unsigned short g_qkvh[2048 * 3072], g_qkvl[2048 * 3072];
__device__ unsigned short g_q2h [2048 * 1024], g_q2l [2048 * 1024];
__device__ unsigned short g_kv2h[2048 * 2048], g_kv2l[2048 * 2048];
__device__ unsigned short g_cath[2048 * 2048], g_catl[2048 * 2048];
// weights [N,K] K-major: single fp16 except proj (hi/lo)
__device__ unsigned short g_wqkv_h[3072 * 1024];
__device__ unsigned short g_w2a_h [1024 * 1024];
__device__ unsigned short g_w2b_h [2048 * 1024];
__device__ unsigned short g_wpj_h [1024 * 2048], g_wpj_l [1024 * 2048];

// ---------------- helpers ----------------
__device__ __forceinline__ uint32_t smem_u32(const void* p) {
    uint32_t a;
    asm("{ .reg .u64 t; cvta.to.shared.u64 t, %1; cvt.u32.u64 %0, t; }" : "=r"(a) : "l"(p));
    return a;
}
#define CP_ASYNC16(dst, src) \
    asm volatile("cp.async.ca.shared.global [%0], [%1], 16;" :: "r"(dst), "l"(src) : "memory")
#define CP_COMMIT() asm volatile("cp.async.commit_group;" ::: "memory")
#define CP_WAIT1()  asm volatile("cp.async.wait_group 1;" ::: "memory")
#define CP_WAIT0()  asm volatile("cp.async.wait_group 0;" ::: "memory")

#define MMA_F16(c, a0, a1, a2, a3, b0, b1) \
    asm volatile("mma.sync.aligned.m16n8k16.row.col.f32.f16.f16.f32 " \
        "{%0,%1,%2,%3}, {%4,%5,%6,%7}, {%8,%9}, {%0,%1,%2,%3};" \
        : "+f"((c)[0]), "+f"((c)[1]), "+f"((c)[2]), "+f"((c)[3]) \
        : "r"(a0), "r"(a1), "r"(a2), "r"(a3), "r"(b0), "r"(b1))

__device__ __forceinline__ void split_pack_h(float a, float b, uint32_t& h, uint32_t& l) {
    __half ha = __float2half_rn(a), hb = __float2half_rn(b);
    __half la = __float2half_rn(a - __half2float(ha));
    __half lb = __float2half_rn(b - __half2float(hb));
    h = (uint32_t)*(unsigned short*)&ha | ((uint32_t)*(unsigned short*)&hb << 16);
    l = (uint32_t)*(unsigned short*)&la | ((uint32_t)*(unsigned short*)&lb << 16);
}

// ---------------- per-batch lengths ----------------
__global__ void lens_kernel(const int* __restrict__ xb, int nx,
                            const int* __restrict__ yb, int ny)
{
    __shared__ int cnt[4];
    int t = threadIdx.x;
    if (t < 4) cnt[t] = 0;
    __syncthreads();
    for (int i = t; i < nx; i += blockDim.x) atomicAdd(&cnt[xb[i]], 1);
    for (int i = t; i < ny; i += blockDim.x) atomicAdd(&cnt[2 + yb[i]], 1);
    __syncthreads();
    if (t < 4) g_lens[t] = cnt[t];
}

// ---------------- fp32 -> fp16 hi/lo split ----------------
__global__ __launch_bounds__(256)
void split_fp32(const float* __restrict__ in, unsigned short* __restrict__ oh,
                unsigned short* __restrict__ ol, int n4)
{
    int i = blockIdx.x * 256 + threadIdx.x;
    if (i >= n4) return;
    float4 v = ((const float4*)in)[i];
    uint32_t h0, l0, h1, l1;
    split_pack_h(v.x, v.y, h0, l0);
    split_pack_h(v.z, v.w, h1, l1);
    ((uint2*)oh)[i] = make_uint2(h0, h1);
    ((uint2*)ol)[i] = make_uint2(l0, l1);
}

// ---------------- W[K,N] -> Wt[N,K] fp16 (single, or hi/lo) ----------------
__global__ __launch_bounds__(256)
void transpose_cvt(const float* __restrict__ in, unsigned short* __restrict__ oh,
                   unsigned short* __restrict__ ol, int K, int N)
{
    __shared__ float tile[32][33];
    int n0 = blockIdx.x << 5, k0 = blockIdx.y << 5;
    int tx = threadIdx.x & 31, ty = threadIdx.x >> 5;
    for (int i = ty; i < 32; i += 8)
        tile[i][tx] = in[(size_t)(k0 + i) * N + n0 + tx];
    __syncthreads();
    for (int i = ty; i < 32; i += 8) {
        float v = tile[tx][i];
        __half h = __float2half_rn(v);
        size_t o = (size_t)(n0 + i) * K + k0 + tx;
        oh[o] = *(unsigned short*)&h;
        if (ol) {
            __half l = __float2half_rn(v - __half2float(h));
            ol[o] = *(unsigned short*)&l;
        }
    }
}

// ---------------- mma.sync fp16 split GEMM ----------------
// NT=2: C = (Ah+Al) @ Bh^T       (weights single fp16)
// NT=3: C = Ah*Bh + Ah*Bl + Al*Bh (both 2-term)
#define TS   (128 * 40)
template<int NT>
__global__ __launch_bounds__(256)
void gemm_mma(const unsigned short* __restrict__ Ah, const unsigned short* __restrict__ Al,
              const unsigned short* __restrict__ Bh, const unsigned short* __restrict__ Bl,
              const float* __restrict__ bias, float* __restrict__ Cf,
              unsigned short* __restrict__ Ch, unsigned short* __restrict__ Cl,
              int M, int N, int K)
{
    extern __shared__ unsigned short sm16[];
    unsigned short* sAh = sm16;
    unsigned short* sAl = sm16 + 2 * TS;
    unsigned short* sBh = sm16 + 4 * TS;
    unsigned short* sBl = sm16 + 6 * TS;   // only used when NT==3
    const uint32_t uAh = smem_u32(sAh), uAl = smem_u32(sAl);
    const uint32_t uBh = smem_u32(sBh), uBl = smem_u32(sBl);

    const int tid  = threadIdx.x;
    const int lane = tid & 31, wid = tid >> 5;
    const int wm = (wid >> 2) << 6;
    const int wn = (wid & 3) << 5;
    const int bm = blockIdx.y << 7, bn = blockIdx.x << 7;

    float acc[4][4][4];
#pragma unroll
    for (int i = 0; i < 4; i++)
#pragma unroll
        for (int j = 0; j < 4; j++)
#pragma unroll
            for (int k = 0; k < 4; k++) acc[i][j][k] = 0.f;

    const int lr = tid >> 2;
    const int ls = tid & 3;
    const int nchunk = K >> 5;

#define PREFETCH(t) do { \
        int buf_ = (t) & 1; \
        int k0_  = (t) << 5; \
        _Pragma("unroll") \
        for (int p_ = 0; p_ < 2; p_++) { \
            int row_ = lr + (p_ << 6); \
            uint32_t so_ = (uint32_t)(buf_ * TS + row_ * 40 + ls * 8) * 2; \
            size_t ao_ = (size_t)(bm + row_) * K + k0_ + ls * 8; \
            size_t bo_ = (size_t)(bn + row_) * K + k0_ + ls * 8; \
            CP_ASYNC16(uAh + so_, Ah + ao_); \
            CP_ASYNC16(uAl + so_, Al + ao_); \
            CP_ASYNC16(uBh + so_, Bh + bo_); \
            if (NT == 3) CP_ASYNC16(uBl + so_, Bl + bo_); \
        } \
    } while (0)

    PREFETCH(0);
    CP_COMMIT();

    const int fr = lane >> 2;
    const int fc = (lane & 3) << 1;

    for (int t = 0; t < nchunk; t++) {
        if (t + 1 < nchunk) { PREFETCH(t + 1); CP_COMMIT(); CP_WAIT1(); }
        else                { CP_WAIT0(); }
        __syncthreads();
        const int buf = (t & 1) * TS;
#pragma unroll
        for (int kk = 0; kk < 32; kk += 16) {
            uint32_t bhf[4][2], blf[4][2];
#pragma unroll
            for (int ni = 0; ni < 4; ni++) {
                int nrow = buf + (wn + (ni << 3) + fr) * 40 + kk + fc;
                bhf[ni][0] = *(const uint32_t*)&sBh[nrow];
                bhf[ni][1] = *(const uint32_t*)&sBh[nrow + 8];
                if (NT == 3) {
                    blf[ni][0] = *(const uint32_t*)&sBl[nrow];
                    blf[ni][1] = *(const uint32_t*)&sBl[nrow + 8];
                }
            }
#pragma unroll
            for (int mi = 0; mi < 4; mi++) {
                int ar0 = buf + (wm + (mi << 4) + fr) * 40 + kk + fc;
                int ar1 = ar0 + 8 * 40;
                uint32_t ah0 = *(const uint32_t*)&sAh[ar0];
                uint32_t ah1 = *(const uint32_t*)&sAh[ar1];
                uint32_t ah2 = *(const uint32_t*)&sAh[ar0 + 8];
                uint32_t ah3 = *(const uint32_t*)&sAh[ar1 + 8];
                uint32_t al0 = *(const uint32_t*)&sAl[ar0];
                uint32_t al1 = *(const uint32_t*)&sAl[ar1];
                uint32_t al2 = *(const uint32_t*)&sAl[ar0 + 8];
                uint32_t al3 = *(const uint32_t*)&sAl[ar1 + 8];
#pragma unroll
                for (int ni = 0; ni < 4; ni++) {
                    MMA_F16(acc[mi][ni], ah0, ah1, ah2, ah3, bhf[ni][0], bhf[ni][1]);
                    if (NT == 3)
                        MMA_F16(acc[mi][ni], ah0, ah1, ah2, ah3, blf[ni][0], blf[ni][1]);
                    MMA_F16(acc[mi][ni], al0, al1, al2, al3, bhf[ni][0], bhf[ni][1]);
                }
            }
        }
        __syncthreads();
    }

    if (Cf) {
#pragma unroll
        for (int mi = 0; mi < 4; mi++) {
            int row = bm + wm + (mi << 4) + fr;
#pragma unroll
            for (int ni = 0; ni < 4; ni++) {
                int col = bn + wn + (ni << 3) + fc;
                float bx = bias[col], by = bias[col + 1];
                float2 v0 = { acc[mi][ni][0] + bx, acc[mi][ni][1] + by };
                float2 v1 = { acc[mi][ni][2] + bx, acc[mi][ni][3] + by };
                *(float2*)(Cf + (size_t)row * N + col)       = v0;
                *(float2*)(Cf + (size_t)(row + 8) * N + col) = v1;
            }
        }
    } else {
#pragma unroll
        for (int mi = 0; mi < 4; mi++) {
            int row = bm + wm + (mi << 4) + fr;
#pragma unroll
            for (int ni = 0; ni < 4; ni++) {
                int col = bn + wn + (ni << 3) + fc;
                float bx = bias[col], by = bias[col + 1];
                uint32_t hh, ll;
                split_pack_h(acc[mi][ni][0] + bx, acc[mi][ni][1] + by, hh, ll);
                *(uint32_t*)&Ch[(size_t)row * N + col] = hh;
                *(uint32_t*)&Cl[(size_t)row * N + col] = ll;
                split_pack_h(acc[mi][ni][2] + bx, acc[mi][ni][3] + by, hh, ll);
                *(uint32_t*)&Ch[(size_t)(row + 8) * N + col] = hh;
                *(uint32_t*)&Cl[(size_t)(row + 8) * N + col] = ll;
            }
        }
    }
}

// ================= MMA flash attention (fp16 2-product) =================
// Scores: (Qh+Ql)*K ;  PV: (Ph+Pl)*V.   K, V single fp16.
#define AST 72

// ---------------- self attention ----------------
__global__ __launch_bounds__(128)
void attn_self_mma(const unsigned short* __restrict__ qkvh,
                   const unsigned short* __restrict__ qkvl,
                   const float* __restrict__ mask,
                   unsigned short* __restrict__ cath,
                   unsigned short* __restrict__ catl)
{
    extern __shared__ char smraw[];
    unsigned short* sQh = (unsigned short*)smraw;
    unsigned short* sQl = sQh + 64 * AST;
    unsigned short* sK  = sQl + 64 * AST;
    unsigned short* sV  = sK  + 64 * AST;   // transposed [dim][key]
    float* sMs = (float*)(sV + 64 * AST);

    const int qt = blockIdx.x, h = blockIdx.y, b = blockIdx.z;
    const int tid = threadIdx.x, lane = tid & 31, wid = tid >> 5;
    const int q0 = wid << 4;
    const int r = lane >> 2, cq = (lane & 3) << 1;

    const size_t gb = (size_t)b * SXX * 3072;
    for (int i = tid; i < 512; i += 128) {
        int rr = i >> 3, seg = i & 7;
        size_t src = gb + (size_t)(qt * 64 + rr) * 3072 + h * 64 + seg * 8;
        *(uint4*)&sQh[rr * AST + seg * 8] = *(const uint4*)&qkvh[src];
        *(uint4*)&sQl[rr * AST + seg * 8] = *(const uint4*)&qkvl[src];
    }

    float o[8][4];
#pragma unroll
    for (int i = 0; i < 8; i++)
#pragma unroll
        for (int j = 0; j < 4; j++) o[i][j] = 0.f;
    float mrow0 = -1e30f, mrow1 = -1e30f, lrow0 = 0.f, lrow1 = 0.f;

    const float* maskb = mask + b * SXX;
    const int lenx = g_lens[b];
    int nt1 = qt + 1, nt2 = (lenx + 63) >> 6;
    const int ntile = nt1 < nt2 ? nt1 : nt2;

    for (int t = 0; t < ntile; t++) {
        __syncthreads();
        for (int i = tid; i < 512; i += 128) {
            int rr = i >> 3, seg = i & 7;
            size_t src = gb + (size_t)(t * 64 + rr) * 3072 + 1024 + h * 64 + seg * 8;
            *(uint4*)&sK[rr * AST + seg * 8] = *(const uint4*)&qkvh[src];
        }
        for (int i = tid; i < 4096; i += 128) {
            int rr = i >> 6, c = i & 63;
            sV[c * AST + rr] = qkvh[gb + (size_t)(t * 64 + rr) * 3072 + 2048 + h * 64 + c];
        }
        if (tid < 64) sMs[tid] = maskb[t * 64 + tid];
        __syncthreads();

        float sc[8][4];
#pragma unroll
        for (int i = 0; i < 8; i++)
#pragma unroll
            for (int j = 0; j < 4; j++) sc[i][j] = 0.f;

#pragma unroll
        for (int kt = 0; kt < 4; kt++) {
            int ro0 = (q0 + r) * AST + kt * 16 + cq;
            int ro1 = ro0 + 8 * AST;
            uint32_t ah0 = *(uint32_t*)&sQh[ro0], ah1 = *(uint32_t*)&sQh[ro1];
            uint32_t ah2 = *(uint32_t*)&sQh[ro0 + 8], ah3 = *(uint32_t*)&sQh[ro1 + 8];
            uint32_t al0 = *(uint32_t*)&sQl[ro0], al1 = *(uint32_t*)&sQl[ro1];
            uint32_t al2 = *(uint32_t*)&sQl[ro0 + 8], al3 = *(uint32_t*)&sQl[ro1 + 8];
#pragma unroll
            for (int nt = 0; nt < 8; nt++) {
                int bo = (nt * 8 + r) * AST + kt * 16 + cq;
                uint32_t bh0 = *(uint32_t*)&sK[bo], bh1 = *(uint32_t*)&sK[bo + 8];
                MMA_F16(sc[nt], ah0, ah1, ah2, ah3, bh0, bh1);
                MMA_F16(sc[nt], al0, al1, al2, al3, bh0, bh1);
            }
        }

        const int grow = qt * 64 + q0 + r;
#pragma unroll
        for (int nt = 0; nt < 8; nt++) {
            int c0 = t * 64 + nt * 8 + cq;
            float m0 = sMs[nt * 8 + cq], m1 = sMs[nt * 8 + cq + 1];
            float v;
            v = sc[nt][0] * 0.125f; sc[nt][0] = ((c0     <= grow    ) ? v : -10000.f) + m0;
            v = sc[nt][1] * 0.125f; sc[nt][1] = ((c0 + 1 <= grow    ) ? v : -10000.f) + m1;
            v = sc[nt][2] * 0.125f; sc[nt][2] = ((c0     <= grow + 8) ? v : -10000.f) + m0;
            v = sc[nt][3] * 0.125f; sc[nt][3] = ((c0 + 1 <= grow + 8) ? v : -10000.f) + m1;
        }

        float mx0 = -1e30f, mx1 = -1e30f;
#pragma unroll
        for (int nt = 0; nt < 8; nt++) {
            mx0 = fmaxf(mx0, fmaxf(sc[nt][0], sc[nt][1]));
            mx1 = fmaxf(mx1, fmaxf(sc[nt][2], sc[nt][3]));
        }
        mx0 = fmaxf(mx0, __shfl_xor_sync(0xffffffffu, mx0, 1));
        mx0 = fmaxf(mx0, __shfl_xor_sync(0xffffffffu, mx0, 2));
        mx1 = fmaxf(mx1, __shfl_xor_sync(0xffffffffu, mx1, 1));
        mx1 = fmaxf(mx1, __shfl_xor_sync(0xffffffffu, mx1, 2));
        float mn0 = fmaxf(mrow0, mx0), mn1 = fmaxf(mrow1, mx1);
        float al0f = __expf(mrow0 - mn0), al1f = __expf(mrow1 - mn1);
        float s0 = 0.f, s1 = 0.f;
#pragma unroll
        for (int nt = 0; nt < 8; nt++) {
            sc[nt][0] = __expf(sc[nt][0] - mn0); s0 += sc[nt][0];
            sc[nt][1] = __expf(sc[nt][1] - mn0); s0 += sc[nt][1];
            sc[nt][2] = __expf(sc[nt][2] - mn1); s1 += sc[nt][2];
            sc[nt][3] = __expf(sc[nt][3] - mn1); s1 += sc[nt][3];
        }
        s0 += __shfl_xor_sync(0xffffffffu, s0, 1);
        s0 += __shfl_xor_sync(0xffffffffu, s0, 2);
        s1 += __shfl_xor_sync(0xffffffffu, s1, 1);
        s1 += __shfl_xor_sync(0xffffffffu, s1, 2);
        lrow0 = lrow0 * al0f + s0; mrow0 = mn0;
        lrow1 = lrow1 * al1f + s1; mrow1 = mn1;
#pragma unroll
        for (int nt = 0; nt < 8; nt++) {
            o[nt][0] *= al0f; o[nt][1] *= al0f;
            o[nt][2] *= al1f; o[nt][3] *= al1f;
        }

#pragma unroll
        for (int kc = 0; kc < 4; kc++) {
            uint32_t ph[4], pl[4];
            split_pack_h(sc[2*kc][0],   sc[2*kc][1],   ph[0], pl[0]);
            split_pack_h(sc[2*kc][2],   sc[2*kc][3],   ph[1], pl[1]);
            split_pack_h(sc[2*kc+1][0], sc[2*kc+1][1], ph[2], pl[2]);
            split_pack_h(sc[2*kc+1][2], sc[2*kc+1][3], ph[3], pl[3]);
#pragma unroll
            for (int dn = 0; dn < 8; dn++) {
                int vo = (dn * 8 + r) * AST + kc * 16 + cq;
                uint32_t vh0 = *(uint32_t*)&sV[vo], vh1 = *(uint32_t*)&sV[vo + 8];
                MMA_F16(o[dn], ph[0], ph[1], ph[2], ph[3], vh0, vh1);
                MMA_F16(o[dn], pl[0], pl[1], pl[2], pl[3], vh0, vh1);
            }
        }
    }

    float i0 = 1.f / lrow0, i1 = 1.f / lrow1;
    size_t ob = (size_t)b * SXX * 2048 + (size_t)(qt * 64 + q0 + r) * 2048 + h * 64;
#pragma unroll
    for (int dn = 0; dn < 8; dn++) {
        uint32_t hh, ll;
        split_pack_h(o[dn][0] * i0, o[dn][1] * i0, hh, ll);
        *(uint32_t*)&cath[ob + dn * 8 + cq] = hh;
        *(uint32_t*)&catl[ob + dn * 8 + cq] = ll;
        split_pack_h(o[dn][2] * i1, o[dn][3] * i1, hh, ll);
        *(uint32_t*)&cath[ob + (size_t)8 * 2048 + dn * 8 + cq] = hh;
        *(uint32_t*)&catl[ob + (size_t)8 * 2048 + dn * 8 + cq] = ll;
    }
}

// ---------------- cross attention ----------------
__global__ __launch_bounds__(128)
void attn_cross_mma(const unsigned short* __restrict__ q2h,
                    const unsigned short* __restrict__ q2l,
                    const unsigned short* __restrict__ kvh,
                    unsigned short* __restrict__ cath,
                    unsigned short* __restrict__ catl)
{
    extern __shared__ char smraw[];
    unsigned short* sQh = (unsigned short*)smraw;
    unsigned short* sQl = sQh + 64 * AST;
    unsigned short* sK  = sQl + 64 * AST;
    unsigned short* sV  = sK  + 64 * AST;

    const int qt = blockIdx.x, h = blockIdx.y, b = blockIdx.z;
    const int tid = threadIdx.x, lane = tid & 31, wid = tid >> 5;
    const int q0 = wid << 4;
    const int r = lane >> 2, cq = (lane & 3) << 1;

    const int lenx = g_lens[b], leny = g_lens[2 + b];
    const int off  = FULLN - lenx;

    size_t obase = (size_t)b * SXX * 2048 + (size_t)(qt * 64) * 2048 + 1024 + h * 64;
    if (qt * 64 >= lenx) {
        const uint4 z = {0, 0, 0, 0};
        for (int i = tid; i < 512; i += 128) {
            int rr = i >> 3, seg = i & 7;
            *(uint4*)&cath[obase + (size_t)rr * 2048 + seg * 8] = z;
            *(uint4*)&catl[obase + (size_t)rr * 2048 + seg * 8] = z;
        }
        return;
    }

    const size_t qgb = (size_t)b * SXX * 1024;
    for (int i = tid; i < 512; i += 128) {
        int rr = i >> 3, seg = i & 7;
        size_t src = qgb + (size_t)(qt * 64 + rr) * 1024 + h * 64 + seg * 8;
        *(uint4*)&sQh[rr * AST + seg * 8] = *(const uint4*)&q2h[src];
        *(uint4*)&sQl[rr * AST + seg * 8] = *(const uint4*)&q2l[src];
    }

    float o[8][4];
#pragma unroll
    for (int i = 0; i < 8; i++)
#pragma unroll
        for (int j = 0; j < 4; j++) o[i][j] = 0.f;
    float mrow0 = -1e30f, mrow1 = -1e30f, lrow0 = 0.f, lrow1 = 0.f;

    int qlast = qt * 64 + 63;
    if (qlast >= lenx) qlast = lenx - 1;
    int jmax = off + qlast + 1;
    if (jmax > leny) jmax = leny;
    const int ntile = (jmax + 63) >> 6;

    const size_t kgb = (size_t)b * SYY * 2048;
    for (int t = 0; t < ntile; t++) {
        __syncthreads();
        for (int i = tid; i < 512; i += 128) {
            int rr = i >> 3, seg = i & 7;
            size_t src = kgb + (size_t)(t * 64 + rr) * 2048 + h * 64 + seg * 8;
            *(uint4*)&sK[rr * AST + seg * 8] = *(const uint4*)&kvh[src];
        }
        for (int i = tid; i < 4096; i += 128) {
            int rr = i >> 6, c = i & 63;
            sV[c * AST + rr] = kvh[kgb + (size_t)(t * 64 + rr) * 2048 + 1024 + h * 64 + c];
        }
        __syncthreads();

        float sc[8][4];
#pragma unroll
        for (int i = 0; i < 8; i++)
#pragma unroll
            for (int j = 0; j < 4; j++) sc[i][j] = 0.f;

#pragma unroll
        for (int kt = 0; kt < 4; kt++) {
            int ro0 = (q0 + r) * AST + kt * 16 + cq;
            int ro1 = ro0 + 8 * AST;
            uint32_t ah0 = *(uint32_t*)&sQh[ro0], ah1 = *(uint32_t*)&sQh[ro1];
            uint32_t ah2 = *(uint32_t*)&sQh[ro0 + 8], ah3 = *(uint32_t*)&sQh[ro1 + 8];
            uint32_t al0 = *(uint32_t*)&sQl[ro0], al1 = *(uint32_t*)&sQl[ro1];
            uint32_t al2 = *(uint32_t*)&sQl[ro0 + 8], al3 = *(uint32_t*)&sQl[ro1 + 8];
#pragma unroll
            for (int nt = 0; nt < 8; nt++) {
                int bo = (nt * 8 + r) * AST + kt * 16 + cq;
                uint32_t bh0 = *(uint32_t*)&sK[bo], bh1 = *(uint32_t*)&sK[bo + 8];
                MMA_F16(sc[nt], ah0, ah1, ah2, ah3, bh0, bh1);
                MMA_F16(sc[nt], al0, al1, al2, al3, bh0, bh1);
            }
        }

        const int grow = off + qt * 64 + q0 + r;
#pragma unroll
        for (int nt = 0; nt < 8; nt++) {
            int c0 = t * 64 + nt * 8 + cq;
            sc[nt][0] = (c0     <= grow     && c0     < leny) ? sc[nt][0] * 0.125f : -1e30f;
            sc[nt][1] = (c0 + 1 <= grow     && c0 + 1 < leny) ? sc[nt][1] * 0.125f : -1e30f;
            sc[nt][2] = (c0     <= grow + 8 && c0     < leny) ? sc[nt][2] * 0.125f : -1e30f;
            sc[nt][3] = (c0 + 1 <= grow + 8 && c0 + 1 < leny) ? sc[nt][3] * 0.125f : -1e30f;
        }

        float mx0 = -1e30f, mx1 = -1e30f;
#pragma unroll
        for (int nt = 0; nt < 8; nt++) {
            mx0 = fmaxf(mx0, fmaxf(sc[nt][0], sc[nt][1]));
            mx1 = fmaxf(mx1, fmaxf(sc[nt][2], sc[nt][3]));
        }
        mx0 = fmaxf(mx0, __shfl_xor_sync(0xffffffffu, mx0, 1));
        mx0 = fmaxf(mx0, __shfl_xor_sync(0xffffffffu, mx0, 2));
        mx1 = fmaxf(mx1, __shfl_xor_sync(0xffffffffu, mx1, 1));
        mx1 = fmaxf(mx1, __shfl_xor_sync(0xffffffffu, mx1, 2));
        float mn0 = fmaxf(mrow0, mx0), mn1 = fmaxf(mrow1, mx1);
        float al0f = __expf(mrow0 - mn0), al1f = __expf(mrow1 - mn1);
        float s0 = 0.f, s1 = 0.f;
#pragma unroll
        for (int nt = 0; nt < 8; nt++) {
            sc[nt][0] = __expf(sc[nt][0] - mn0); s0 += sc[nt][0];
            sc[nt][1] = __expf(sc[nt][1] - mn0); s0 += sc[nt][1];
            sc[nt][2] = __expf(sc[nt][2] - mn1); s1 += sc[nt][2];
            sc[nt][3] = __expf(sc[nt][3] - mn1); s1 += sc[nt][3];
        }
        s0 += __shfl_xor_sync(0xffffffffu, s0, 1);
        s0 += __shfl_xor_sync(0xffffffffu, s0, 2);
        s1 += __shfl_xor_sync(0xffffffffu, s1, 1);
        s1 += __shfl_xor_sync(0xffffffffu, s1, 2);
        lrow0 = lrow0 * al0f + s0; mrow0 = mn0;
        lrow1 = lrow1 * al1f + s1; mrow1 = mn1;
#pragma unroll
        for (int nt = 0; nt < 8; nt++) {
            o[nt][0] *= al0f; o[nt][1] *= al0f;
            o[nt][2] *= al1f; o[nt][3] *= al1f;
        }

#pragma unroll
        for (int kc = 0; kc < 4; kc++) {
            uint32_t ph[4], pl[4];
            split_pack_h(sc[2*kc][0],   sc[2*kc][1],   ph[0], pl[0]);
            split_pack_h(sc[2*kc][2],   sc[2*kc][3],   ph[1], pl[1]);
            split_pack_h(sc[2*kc+1][0], sc[2*kc+1][1], ph[2], pl[2]);
            split_pack_h(sc[2*kc+1][2], sc[2*kc+1][3], ph[3], pl[3]);
#pragma unroll
            for (int dn = 0; dn < 8; dn++) {
                int vo = (dn * 8 + r) * AST + kc * 16 + cq;
                uint32_t vh0 = *(uint32_t*)&sV[vo], vh1 = *(uint32_t*)&sV[vo + 8];
                MMA_F16(o[dn], ph[0], ph[1], ph[2], ph[3], vh0, vh1);
                MMA_F16(o[dn], pl[0], pl[1], pl[2], pl[3], vh0, vh1);
            }
        }
    }

    float i0 = 1.f / lrow0, i1 = 1.f / lrow1;
    int row0 = qt * 64 + q0 + r, row1 = row0 + 8;
    bool v0 = row0 < lenx, v1 = row1 < lenx;
    size_t ob = (size_t)b * SXX * 2048 + (size_t)row0 * 2048 + 1024 + h * 64;
#pragma unroll
    for (int dn = 0; dn < 8; dn++) {
        uint32_t hh = 0, ll = 0;
        if (v0) split_pack_h(o[dn][0] * i0, o[dn][1] * i0, hh, ll);
        *(uint32_t*)&cath[ob + dn * 8 + cq] = hh;
        *(uint32_t*)&catl[ob + dn * 8 + cq] = ll;
        hh = 0; ll = 0;
        if (v1) split_pack_h(o[dn][2] * i1, o[dn][3] * i1, hh, ll);
        *(uint32_t*)&cath[ob + (size_t)8 * 2048 + dn * 8 + cq] = hh;
        *(uint32_t*)&catl[ob + (size_t)8 * 2048 + dn * 8 + cq] = ll;
    }
}

// ---------------- launch ----------------
extern "C" void kernel_launch(void* const* d_in, const int* in_sizes, int n_in,
                              void* d_out, int out_size)
{
    const float* x      = (const float*)d_in[0];
    const float* y      = (const float*)d_in[1];
    const float* maskx  = (const float*)d_in[2];
    const float* W_attn = (const float*)d_in[3];
    const float* b_attn = (const float*)d_in[4];
    const float* W_2a   = (const float*)d_in[5];
    const float* b_2a   = (const float*)d_in[6];
    const float* W_2b   = (const float*)d_in[7];
    const float* b_2b   = (const float*)d_in[8];
    const float* W_proj = (const float*)d_in[9];
    const float* b_proj = (const float*)d_in[10];
    const int*   xtb    = (const int*)d_in[11];
    const int*   ytb    = (const int*)d_in[15];

    unsigned short *xh, *xl, *yh, *yl;
    unsigned short *qkvh, *qkvl, *q2h, *q2l, *kv2h, *kv2l, *cath, *catl;
    unsigned short *wqh, *wah, *wbh, *wph, *wpl;
    cudaGetSymbolAddress((void**)&xh, g_xh);     cudaGetSymbolAddress((void**)&xl, g_xl);
    cudaGetSymbolAddress((void**)&yh, g_yh);     cudaGetSymbolAddress((void**)&yl, g_yl);
    cudaGetSymbolAddress((void**)&qkvh, g_qkvh); cudaGetSymbolAddress((void**)&qkvl, g_qkvl);
    cudaGetSymbolAddress((void**)&q2h, g_q2h);   cudaGetSymbolAddress((void**)&q2l, g_q2l);
    cudaGetSymbolAddress((void**)&kv2h, g_kv2h); cudaGetSymbolAddress((void**)&kv2l, g_kv2l);
    cudaGetSymbolAddress((void**)&cath, g_cath); cudaGetSymbolAddress((void**)&catl, g_catl);
    cudaGetSymbolAddress((void**)&wqh, g_wqkv_h);
    cudaGetSymbolAddress((void**)&wah, g_w2a_h);
    cudaGetSymbolAddress((void**)&wbh, g_w2b_h);
    cudaGetSymbolAddress((void**)&wph, g_wpj_h); cudaGetSymbolAddress((void**)&wpl, g_wpj_l);

    const int SMEM_G2 = 6 * TS * 2;                   // 61440 B
    const int SMEM_G3 = 8 * TS * 2;                   // 81920 B
    const int SMEM_ATTN = 4 * 64 * AST * 2 + 64 * 4;  // 37120 B
    cudaFuncSetAttribute((const void*)gemm_mma<2>,    cudaFuncAttributeMaxDynamicSharedMemorySize, SMEM_G2);
    cudaFuncSetAttribute((const void*)gemm_mma<3>,    cudaFuncAttributeMaxDynamicSharedMemorySize, SMEM_G3);
    cudaFuncSetAttribute((const void*)attn_self_mma,  cudaFuncAttributeMaxDynamicSharedMemorySize, SMEM_ATTN);
    cudaFuncSetAttribute((const void*)attn_cross_mma, cudaFuncAttributeMaxDynamicSharedMemorySize, SMEM_ATTN);

    lens_kernel<<<1, 256>>>(xtb, in_sizes[11], ytb, in_sizes[15]);

    split_fp32<<<2048, 256>>>(x, xh, xl, 2048 * 1024 / 4);
    split_fp32<<<2048, 256>>>(y, yh, yl, 2048 * 1024 / 4);
    transpose_cvt<<<dim3(96, 32), 256>>>(W_attn, wqh, nullptr, 1024, 3072);
    transpose_cvt<<<dim3(32, 32), 256>>>(W_2a,   wah, nullptr, 1024, 1024);
    transpose_cvt<<<dim3(64, 32), 256>>>(W_2b,   wbh, nullptr, 1024, 2048);
    transpose_cvt<<<dim3(32, 64), 256>>>(W_proj, wph, wpl,     2048, 1024);

    gemm_mma<2><<<dim3(24, 16), 256, SMEM_G2>>>(xh, xl, wqh, nullptr, b_attn, nullptr, qkvh, qkvl, 2048, 3072, 1024);
    gemm_mma<2><<<dim3(8,  16), 256, SMEM_G2>>>(xh, xl, wah, nullptr, b_2a,   nullptr, q2h,  q2l,  2048, 1024, 1024);
    gemm_mma<2><<<dim3(16, 16), 256, SMEM_G2>>>(yh, yl, wbh, nullptr, b_2b,   nullptr, kv2h, kv2l, 2048, 2048, 1024);

    attn_self_mma <<<dim3(16, 16, 2), 128, SMEM_ATTN>>>(qkvh, qkvl, maskx, cath, catl);
    attn_cross_mma<<<dim3(16, 16, 2), 128, SMEM_ATTN>>>(q2h, q2l, kv2h, cath, catl);

    gemm_mma<3><<<dim3(8, 16), 256, SMEM_G3>>>(cath, catl, wph, wpl, b_proj, (float*)d_out, nullptr, nullptr, 2048, 1024, 2048);
}

// round 7
// speedup vs baseline: 3.6641x; 1.3191x over previous
#include <cuda_runtime.h>
#include <cuda_fp16.h>
#include <cstdint>

#define NB    2
#define SXX   1024
#define SYY   1024
#define DIM   1024
#define NH    16
#define HDIM  64
#define FULLN 1536

// ---------------- scratch (device globals) ----------------
__device__ int g_lens[4];

__device__ unsigned short g_xh [2048 * 1024], g_xl [2048 * 1024];
__device__ unsigned short g_yh [2048 * 1024], g_yl [2048 * 1024];
__device__ unsigned short g_qkvh[2048 * 3072], g_qkvl[2048 * 3072];
__device__ unsigned short g_q2h [2048 * 1024], g_q2l [2048 * 1024];
__device__ unsigned short g_kv2h[2048 * 2048], g_kv2l[2048 * 2048];
__device__ unsigned short g_cath[2048 * 2048], g_catl[2048 * 2048];
__device__ unsigned short g_wqkv_h[3072 * 1024];
__device__ unsigned short g_w2a_h [1024 * 1024];
__device__ unsigned short g_w2b_h [2048 * 1024];
__device__ unsigned short g_wpj_h [1024 * 2048], g_wpj_l [1024 * 2048];

// ---------------- helpers ----------------
__device__ __forceinline__ uint32_t smem_u32(const void* p) {
    uint32_t a;
    asm("{ .reg .u64 t; cvta.to.shared.u64 t, %1; cvt.u32.u64 %0, t; }" : "=r"(a) : "l"(p));
    return a;
}
#define CP_ASYNC16(dst, src) \
    asm volatile("cp.async.ca.shared.global [%0], [%1], 16;" :: "r"(dst), "l"(src) : "memory")
#define CP_COMMIT() asm volatile("cp.async.commit_group;" ::: "memory")
#define CP_WAIT1()  asm volatile("cp.async.wait_group 1;" ::: "memory")
#define CP_WAIT0()  asm volatile("cp.async.wait_group 0;" ::: "memory")

#define MMA_F16(c, a0, a1, a2, a3, b0, b1) \
    asm volatile("mma.sync.aligned.m16n8k16.row.col.f32.f16.f16.f32 " \
        "{%0,%1,%2,%3}, {%4,%5,%6,%7}, {%8,%9}, {%0,%1,%2,%3};" \
        : "+f"((c)[0]), "+f"((c)[1]), "+f"((c)[2]), "+f"((c)[3]) \
        : "r"(a0), "r"(a1), "r"(a2), "r"(a3), "r"(b0), "r"(b1))

#define LDSM4(r0, r1, r2, r3, a) \
    asm volatile("ldmatrix.sync.aligned.m8n8.x4.shared.b16 {%0,%1,%2,%3}, [%4];" \
        : "=r"(r0), "=r"(r1), "=r"(r2), "=r"(r3) : "r"(a))
#define LDSM4T(r0, r1, r2, r3, a) \
    asm volatile("ldmatrix.sync.aligned.m8n8.x4.trans.shared.b16 {%0,%1,%2,%3}, [%4];" \
        : "=r"(r0), "=r"(r1), "=r"(r2), "=r"(r3) : "r"(a))

__device__ __forceinline__ void split_pack_h(float a, float b, uint32_t& h, uint32_t& l) {
    __half ha = __float2half_rn(a), hb = __float2half_rn(b);
    __half la = __float2half_rn(a - __half2float(ha));
    __half lb = __float2half_rn(b - __half2float(hb));
    h = (uint32_t)*(unsigned short*)&ha | ((uint32_t)*(unsigned short*)&hb << 16);
    l = (uint32_t)*(unsigned short*)&la | ((uint32_t)*(unsigned short*)&lb << 16);
}

// ---------------- per-batch lengths ----------------
__global__ void lens_kernel(const int* __restrict__ xb, int nx,
                            const int* __restrict__ yb, int ny)
{
    __shared__ int cnt[4];
    int t = threadIdx.x;
    if (t < 4) cnt[t] = 0;
    __syncthreads();
    for (int i = t; i < nx; i += blockDim.x) atomicAdd(&cnt[xb[i]], 1);
    for (int i = t; i < ny; i += blockDim.x) atomicAdd(&cnt[2 + yb[i]], 1);
    __syncthreads();
    if (t < 4) g_lens[t] = cnt[t];
}

// ---------------- fp32 -> fp16 hi/lo split ----------------
__global__ __launch_bounds__(256)
void split_fp32(const float* __restrict__ in, unsigned short* __restrict__ oh,
                unsigned short* __restrict__ ol, int n4)
{
    int i = blockIdx.x * 256 + threadIdx.x;
    if (i >= n4) return;
    float4 v = ((const float4*)in)[i];
    uint32_t h0, l0, h1, l1;
    split_pack_h(v.x, v.y, h0, l0);
    split_pack_h(v.z, v.w, h1, l1);
    ((uint2*)oh)[i] = make_uint2(h0, h1);
    ((uint2*)ol)[i] = make_uint2(l0, l1);
}

// ---------------- W[K,N] -> Wt[N,K] fp16 ----------------
__global__ __launch_bounds__(256)
void transpose_cvt(const float* __restrict__ in, unsigned short* __restrict__ oh,
                   unsigned short* __restrict__ ol, int K, int N)
{
    __shared__ float tile[32][33];
    int n0 = blockIdx.x << 5, k0 = blockIdx.y << 5;
    int tx = threadIdx.x & 31, ty = threadIdx.x >> 5;
    for (int i = ty; i < 32; i += 8)
        tile[i][tx] = in[(size_t)(k0 + i) * N + n0 + tx];
    __syncthreads();
    for (int i = ty; i < 32; i += 8) {
        float v = tile[tx][i];
        __half h = __float2half_rn(v);
        size_t o = (size_t)(n0 + i) * K + k0 + tx;
        oh[o] = *(unsigned short*)&h;
        if (ol) {
            __half l = __float2half_rn(v - __half2float(h));
            ol[o] = *(unsigned short*)&l;
        }
    }
}

// ---------------- mma.sync fp16 split GEMM (ldmatrix mainloop) ----------------
#define TS   (128 * 40)
template<int NT>
__global__ __launch_bounds__(256)
void gemm_mma(const unsigned short* __restrict__ Ah, const unsigned short* __restrict__ Al,
              const unsigned short* __restrict__ Bh, const unsigned short* __restrict__ Bl,
              const float* __restrict__ bias, float* __restrict__ Cf,
              unsigned short* __restrict__ Ch, unsigned short* __restrict__ Cl,
              int M, int N, int K)
{
    extern __shared__ unsigned short sm16[];
    unsigned short* sAh = sm16;
    unsigned short* sAl = sm16 + 2 * TS;
    unsigned short* sBh = sm16 + 4 * TS;
    unsigned short* sBl = sm16 + 6 * TS;
    const uint32_t uAh = smem_u32(sAh), uAl = smem_u32(sAl);
    const uint32_t uBh = smem_u32(sBh), uBl = smem_u32(sBl);

    const int tid  = threadIdx.x;
    const int lane = tid & 31, wid = tid >> 5;
    const int wm = (wid >> 2) << 6;
    const int wn = (wid & 3) << 5;
    const int bm = blockIdx.y << 7, bn = blockIdx.x << 7;

    float acc[4][4][4];
#pragma unroll
    for (int i = 0; i < 4; i++)
#pragma unroll
        for (int j = 0; j < 4; j++)
#pragma unroll
            for (int k = 0; k < 4; k++) acc[i][j][k] = 0.f;

    const int lr = tid >> 2;
    const int ls = tid & 3;
    const int nchunk = K >> 5;

#define PREFETCH(t) do { \
        int buf_ = (t) & 1; \
        int k0_  = (t) << 5; \
        _Pragma("unroll") \
        for (int p_ = 0; p_ < 2; p_++) { \
            int row_ = lr + (p_ << 6); \
            uint32_t so_ = (uint32_t)(buf_ * TS + row_ * 40 + ls * 8) * 2; \
            size_t ao_ = (size_t)(bm + row_) * K + k0_ + ls * 8; \
            size_t bo_ = (size_t)(bn + row_) * K + k0_ + ls * 8; \
            CP_ASYNC16(uAh + so_, Ah + ao_); \
            CP_ASYNC16(uAl + so_, Al + ao_); \
            CP_ASYNC16(uBh + so_, Bh + bo_); \
            if (NT == 3) CP_ASYNC16(uBl + so_, Bl + bo_); \
        } \
    } while (0)

    PREFETCH(0);
    CP_COMMIT();

    // ldmatrix fragment offsets
    const int l8 = lane & 7, g = lane >> 3;
    uint32_t aoff[4], boff[2];
#pragma unroll
    for (int mi = 0; mi < 4; mi++)
        aoff[mi] = (uint32_t)((wm + (mi << 4) + ((g & 1) << 3) + l8) * 40 + ((g >> 1) << 3)) * 2;
#pragma unroll
    for (int p = 0; p < 2; p++)
        boff[p] = (uint32_t)((wn + (p << 4) + ((g >> 1) << 3) + l8) * 40 + ((g & 1) << 3)) * 2;

    const int fr = lane >> 2;
    const int fc = (lane & 3) << 1;

    for (int t = 0; t < nchunk; t++) {
        if (t + 1 < nchunk) { PREFETCH(t + 1); CP_COMMIT(); CP_WAIT1(); }
        else                { CP_WAIT0(); }
        __syncthreads();
        const uint32_t bufB = (uint32_t)(t & 1) * (TS * 2);
#pragma unroll
        for (int kk = 0; kk < 2; kk++) {
            const uint32_t kof = bufB + (kk << 5);
            uint32_t bh[2][4], bl[2][4];
#pragma unroll
            for (int p = 0; p < 2; p++) {
                LDSM4(bh[p][0], bh[p][1], bh[p][2], bh[p][3], uBh + kof + boff[p]);
                if (NT == 3)
                    LDSM4(bl[p][0], bl[p][1], bl[p][2], bl[p][3], uBl + kof + boff[p]);
            }
#pragma unroll
            for (int mi = 0; mi < 4; mi++) {
                uint32_t ah0, ah1, ah2, ah3, al0, al1, al2, al3;
                LDSM4(ah0, ah1, ah2, ah3, uAh + kof + aoff[mi]);
                LDSM4(al0, al1, al2, al3, uAl + kof + aoff[mi]);
#pragma unroll
                for (int p = 0; p < 2; p++) {
                    MMA_F16(acc[mi][2*p],   ah0, ah1, ah2, ah3, bh[p][0], bh[p][1]);
                    if (NT == 3)
                        MMA_F16(acc[mi][2*p], ah0, ah1, ah2, ah3, bl[p][0], bl[p][1]);
                    MMA_F16(acc[mi][2*p],   al0, al1, al2, al3, bh[p][0], bh[p][1]);
                    MMA_F16(acc[mi][2*p+1], ah0, ah1, ah2, ah3, bh[p][2], bh[p][3]);
                    if (NT == 3)
                        MMA_F16(acc[mi][2*p+1], ah0, ah1, ah2, ah3, bl[p][2], bl[p][3]);
                    MMA_F16(acc[mi][2*p+1], al0, al1, al2, al3, bh[p][2], bh[p][3]);
                }
            }
        }
        __syncthreads();
    }

    if (Cf) {
#pragma unroll
        for (int mi = 0; mi < 4; mi++) {
            int row = bm + wm + (mi << 4) + fr;
#pragma unroll
            for (int ni = 0; ni < 4; ni++) {
                int col = bn + wn + (ni << 3) + fc;
                float bx = bias[col], by = bias[col + 1];
                float2 v0 = { acc[mi][ni][0] + bx, acc[mi][ni][1] + by };
                float2 v1 = { acc[mi][ni][2] + bx, acc[mi][ni][3] + by };
                *(float2*)(Cf + (size_t)row * N + col)       = v0;
                *(float2*)(Cf + (size_t)(row + 8) * N + col) = v1;
            }
        }
    } else {
#pragma unroll
        for (int mi = 0; mi < 4; mi++) {
            int row = bm + wm + (mi << 4) + fr;
#pragma unroll
            for (int ni = 0; ni < 4; ni++) {
                int col = bn + wn + (ni << 3) + fc;
                float bx = bias[col], by = bias[col + 1];
                uint32_t hh, ll;
                split_pack_h(acc[mi][ni][0] + bx, acc[mi][ni][1] + by, hh, ll);
                *(uint32_t*)&Ch[(size_t)row * N + col] = hh;
                *(uint32_t*)&Cl[(size_t)row * N + col] = ll;
                split_pack_h(acc[mi][ni][2] + bx, acc[mi][ni][3] + by, hh, ll);
                *(uint32_t*)&Ch[(size_t)(row + 8) * N + col] = hh;
                *(uint32_t*)&Cl[(size_t)(row + 8) * N + col] = ll;
            }
        }
    }
}

// ================= MMA flash attention (ldmatrix + cp.async pipeline) =================
#define AST 72
#define QB  (64 * AST)          // u16 elems per 64x64 tile
#define KVB (QB * 2)            // bytes per tile buffer

// ---------------- self attention ----------------
__global__ __launch_bounds__(128)
void attn_self_mma(const unsigned short* __restrict__ qkvh,
                   const unsigned short* __restrict__ qkvl,
                   const float* __restrict__ mask,
                   unsigned short* __restrict__ cath,
                   unsigned short* __restrict__ catl)
{
    extern __shared__ char smraw[];
    unsigned short* sQh = (unsigned short*)smraw;
    unsigned short* sQl = sQh + QB;
    unsigned short* sK  = sQl + QB;       // [2][QB]
    unsigned short* sV  = sK  + 2 * QB;   // [2][QB]  row-major [key][dim]
    float* sMsf = (float*)(sV + 2 * QB);  // [2][64]
    const uint32_t uQh = smem_u32(sQh), uQl = smem_u32(sQl);
    const uint32_t uK = smem_u32(sK), uV = smem_u32(sV);
    const uint32_t uMs = smem_u32(sMsf);

    const int qt = blockIdx.x, h = blockIdx.y, b = blockIdx.z;
    const int tid = threadIdx.x, lane = tid & 31, wid = tid >> 5;
    const int q0 = wid << 4;
    const int r = lane >> 2, cq = (lane & 3) << 1;
    const int l8 = lane & 7, g = lane >> 3;

    const size_t gb = (size_t)b * SXX * 3072;
    for (int i = tid; i < 512; i += 128) {
        int rr = i >> 3, seg = i & 7;
        size_t src = gb + (size_t)(qt * 64 + rr) * 3072 + h * 64 + seg * 8;
        *(uint4*)&sQh[rr * AST + seg * 8] = *(const uint4*)&qkvh[src];
        *(uint4*)&sQl[rr * AST + seg * 8] = *(const uint4*)&qkvl[src];
    }

    const float* maskb = mask + b * SXX;
    const int lenx = g_lens[b];
    int nt1 = qt + 1, nt2 = (lenx + 63) >> 6;
    const int ntile = nt1 < nt2 ? nt1 : nt2;

#define APREF_SELF(t) do { \
        uint32_t kd_ = uK + (uint32_t)((t) & 1) * KVB; \
        uint32_t vd_ = uV + (uint32_t)((t) & 1) * KVB; \
        _Pragma("unroll") \
        for (int it_ = 0; it_ < 4; it_++) { \
            int i_ = tid + it_ * 128; \
            int rr_ = i_ >> 3, sg_ = i_ & 7; \
            size_t kr_ = gb + (size_t)((t) * 64 + rr_) * 3072 + 1024 + h * 64 + sg_ * 8; \
            uint32_t so_ = (uint32_t)(rr_ * AST + sg_ * 8) * 2; \
            CP_ASYNC16(kd_ + so_, qkvh + kr_); \
            CP_ASYNC16(vd_ + so_, qkvh + kr_ + 1024); \
        } \
        if (tid < 16) CP_ASYNC16(uMs + ((t) & 1) * 256 + tid * 16, maskb + (t) * 64 + tid * 4); \
    } while (0)

    // fragment base offsets
    uint32_t qfo = (uint32_t)((q0 + ((g & 1) << 3) + l8) * AST + ((g >> 1) << 3)) * 2;
    uint32_t kfo[4], vfo[4];
#pragma unroll
    for (int p = 0; p < 4; p++) {
        kfo[p] = (uint32_t)(((p << 4) + ((g >> 1) << 3) + l8) * AST + ((g & 1) << 3)) * 2;
        vfo[p] = (uint32_t)((((g & 1) << 3) + l8) * AST + (((p << 1) + (g >> 1)) << 3)) * 2;
    }

    float o[8][4];
#pragma unroll
    for (int i = 0; i < 8; i++)
#pragma unroll
        for (int j = 0; j < 4; j++) o[i][j] = 0.f;
    float mrow0 = -1e30f, mrow1 = -1e30f, lrow0 = 0.f, lrow1 = 0.f;

    APREF_SELF(0);
    CP_COMMIT();

    for (int t = 0; t < ntile; t++) {
        if (t + 1 < ntile) { APREF_SELF(t + 1); CP_COMMIT(); CP_WAIT1(); }
        else               { CP_WAIT0(); }
        __syncthreads();
        const uint32_t kb = (uint32_t)(t & 1) * KVB;
        const int mb = (t & 1) * 64;

        float sc[8][4];
#pragma unroll
        for (int i = 0; i < 8; i++)
#pragma unroll
            for (int j = 0; j < 4; j++) sc[i][j] = 0.f;

#pragma unroll
        for (int kt = 0; kt < 4; kt++) {
            const uint32_t ko = (uint32_t)(kt << 5);
            uint32_t ah0, ah1, ah2, ah3, al0, al1, al2, al3;
            LDSM4(ah0, ah1, ah2, ah3, uQh + qfo + ko);
            LDSM4(al0, al1, al2, al3, uQl + qfo + ko);
#pragma unroll
            for (int p = 0; p < 4; p++) {
                uint32_t k0r, k1r, k2r, k3r;
                LDSM4(k0r, k1r, k2r, k3r, uK + kb + kfo[p] + ko);
                MMA_F16(sc[2*p],   ah0, ah1, ah2, ah3, k0r, k1r);
                MMA_F16(sc[2*p],   al0, al1, al2, al3, k0r, k1r);
                MMA_F16(sc[2*p+1], ah0, ah1, ah2, ah3, k2r, k3r);
                MMA_F16(sc[2*p+1], al0, al1, al2, al3, k2r, k3r);
            }
        }

        const int grow = qt * 64 + q0 + r;
#pragma unroll
        for (int nt = 0; nt < 8; nt++) {
            int c0 = t * 64 + nt * 8 + cq;
            float m0 = sMsf[mb + nt * 8 + cq], m1 = sMsf[mb + nt * 8 + cq + 1];
            float v;
            v = sc[nt][0] * 0.125f; sc[nt][0] = ((c0     <= grow    ) ? v : -10000.f) + m0;
            v = sc[nt][1] * 0.125f; sc[nt][1] = ((c0 + 1 <= grow    ) ? v : -10000.f) + m1;
            v = sc[nt][2] * 0.125f; sc[nt][2] = ((c0     <= grow + 8) ? v : -10000.f) + m0;
            v = sc[nt][3] * 0.125f; sc[nt][3] = ((c0 + 1 <= grow + 8) ? v : -10000.f) + m1;
        }

        float mx0 = -1e30f, mx1 = -1e30f;
#pragma unroll
        for (int nt = 0; nt < 8; nt++) {
            mx0 = fmaxf(mx0, fmaxf(sc[nt][0], sc[nt][1]));
            mx1 = fmaxf(mx1, fmaxf(sc[nt][2], sc[nt][3]));
        }
        mx0 = fmaxf(mx0, __shfl_xor_sync(0xffffffffu, mx0, 1));
        mx0 = fmaxf(mx0, __shfl_xor_sync(0xffffffffu, mx0, 2));
        mx1 = fmaxf(mx1, __shfl_xor_sync(0xffffffffu, mx1, 1));
        mx1 = fmaxf(mx1, __shfl_xor_sync(0xffffffffu, mx1, 2));
        float mn0 = fmaxf(mrow0, mx0), mn1 = fmaxf(mrow1, mx1);
        float al0f = __expf(mrow0 - mn0), al1f = __expf(mrow1 - mn1);
        float s0 = 0.f, s1 = 0.f;
#pragma unroll
        for (int nt = 0; nt < 8; nt++) {
            sc[nt][0] = __expf(sc[nt][0] - mn0); s0 += sc[nt][0];
            sc[nt][1] = __expf(sc[nt][1] - mn0); s0 += sc[nt][1];
            sc[nt][2] = __expf(sc[nt][2] - mn1); s1 += sc[nt][2];
            sc[nt][3] = __expf(sc[nt][3] - mn1); s1 += sc[nt][3];
        }
        s0 += __shfl_xor_sync(0xffffffffu, s0, 1);
        s0 += __shfl_xor_sync(0xffffffffu, s0, 2);
        s1 += __shfl_xor_sync(0xffffffffu, s1, 1);
        s1 += __shfl_xor_sync(0xffffffffu, s1, 2);
        lrow0 = lrow0 * al0f + s0; mrow0 = mn0;
        lrow1 = lrow1 * al1f + s1; mrow1 = mn1;
#pragma unroll
        for (int nt = 0; nt < 8; nt++) {
            o[nt][0] *= al0f; o[nt][1] *= al0f;
            o[nt][2] *= al1f; o[nt][3] *= al1f;
        }

#pragma unroll
        for (int kc = 0; kc < 4; kc++) {
            uint32_t ph[4], pl[4];
            split_pack_h(sc[2*kc][0],   sc[2*kc][1],   ph[0], pl[0]);
            split_pack_h(sc[2*kc][2],   sc[2*kc][3],   ph[1], pl[1]);
            split_pack_h(sc[2*kc+1][0], sc[2*kc+1][1], ph[2], pl[2]);
            split_pack_h(sc[2*kc+1][2], sc[2*kc+1][3], ph[3], pl[3]);
            const uint32_t vrow = kb + (uint32_t)(kc * 16 * AST) * 2;
#pragma unroll
            for (int p = 0; p < 4; p++) {
                uint32_t v0r, v1r, v2r, v3r;
                LDSM4T(v0r, v1r, v2r, v3r, uV + vrow + vfo[p]);
                MMA_F16(o[2*p],   ph[0], ph[1], ph[2], ph[3], v0r, v1r);
                MMA_F16(o[2*p],   pl[0], pl[1], pl[2], pl[3], v0r, v1r);
                MMA_F16(o[2*p+1], ph[0], ph[1], ph[2], ph[3], v2r, v3r);
                MMA_F16(o[2*p+1], pl[0], pl[1], pl[2], pl[3], v2r, v3r);
            }
        }
        __syncthreads();
    }

    float i0 = 1.f / lrow0, i1 = 1.f / lrow1;
    size_t ob = (size_t)b * SXX * 2048 + (size_t)(qt * 64 + q0 + r) * 2048 + h * 64;
#pragma unroll
    for (int dn = 0; dn < 8; dn++) {
        uint32_t hh, ll;
        split_pack_h(o[dn][0] * i0, o[dn][1] * i0, hh, ll);
        *(uint32_t*)&cath[ob + dn * 8 + cq] = hh;
        *(uint32_t*)&catl[ob + dn * 8 + cq] = ll;
        split_pack_h(o[dn][2] * i1, o[dn][3] * i1, hh, ll);
        *(uint32_t*)&cath[ob + (size_t)8 * 2048 + dn * 8 + cq] = hh;
        *(uint32_t*)&catl[ob + (size_t)8 * 2048 + dn * 8 + cq] = ll;
    }
}

// ---------------- cross attention ----------------
__global__ __launch_bounds__(128)
void attn_cross_mma(const unsigned short* __restrict__ q2h,
                    const unsigned short* __restrict__ q2l,
                    const unsigned short* __restrict__ kvh,
                    unsigned short* __restrict__ cath,
                    unsigned short* __restrict__ catl)
{
    extern __shared__ char smraw[];
    unsigned short* sQh = (unsigned short*)smraw;
    unsigned short* sQl = sQh + QB;
    unsigned short* sK  = sQl + QB;
    unsigned short* sV  = sK  + 2 * QB;
    const uint32_t uQh = smem_u32(sQh), uQl = smem_u32(sQl);
    const uint32_t uK = smem_u32(sK), uV = smem_u32(sV);

    const int qt = blockIdx.x, h = blockIdx.y, b = blockIdx.z;
    const int tid = threadIdx.x, lane = tid & 31, wid = tid >> 5;
    const int q0 = wid << 4;
    const int r = lane >> 2, cq = (lane & 3) << 1;
    const int l8 = lane & 7, g = lane >> 3;

    const int lenx = g_lens[b], leny = g_lens[2 + b];
    const int off  = FULLN - lenx;

    size_t obase = (size_t)b * SXX * 2048 + (size_t)(qt * 64) * 2048 + 1024 + h * 64;
    if (qt * 64 >= lenx) {
        const uint4 z = {0, 0, 0, 0};
        for (int i = tid; i < 512; i += 128) {
            int rr = i >> 3, seg = i & 7;
            *(uint4*)&cath[obase + (size_t)rr * 2048 + seg * 8] = z;
            *(uint4*)&catl[obase + (size_t)rr * 2048 + seg * 8] = z;
        }
        return;
    }

    const size_t qgb = (size_t)b * SXX * 1024;
    for (int i = tid; i < 512; i += 128) {
        int rr = i >> 3, seg = i & 7;
        size_t src = qgb + (size_t)(qt * 64 + rr) * 1024 + h * 64 + seg * 8;
        *(uint4*)&sQh[rr * AST + seg * 8] = *(const uint4*)&q2h[src];
        *(uint4*)&sQl[rr * AST + seg * 8] = *(const uint4*)&q2l[src];
    }

    int qlast = qt * 64 + 63;
    if (qlast >= lenx) qlast = lenx - 1;
    int jmax = off + qlast + 1;
    if (jmax > leny) jmax = leny;
    const int ntile = (jmax + 63) >> 6;
    const size_t kgb = (size_t)b * SYY * 2048;

#define APREF_CROSS(t) do { \
        uint32_t kd_ = uK + (uint32_t)((t) & 1) * KVB; \
        uint32_t vd_ = uV + (uint32_t)((t) & 1) * KVB; \
        _Pragma("unroll") \
        for (int it_ = 0; it_ < 4; it_++) { \
            int i_ = tid + it_ * 128; \
            int rr_ = i_ >> 3, sg_ = i_ & 7; \
            size_t kr_ = kgb + (size_t)((t) * 64 + rr_) * 2048 + h * 64 + sg_ * 8; \
            uint32_t so_ = (uint32_t)(rr_ * AST + sg_ * 8) * 2; \
            CP_ASYNC16(kd_ + so_, kvh + kr_); \
            CP_ASYNC16(vd_ + so_, kvh + kr_ + 1024); \
        } \
    } while (0)

    uint32_t qfo = (uint32_t)((q0 + ((g & 1) << 3) + l8) * AST + ((g >> 1) << 3)) * 2;
    uint32_t kfo[4], vfo[4];
#pragma unroll
    for (int p = 0; p < 4; p++) {
        kfo[p] = (uint32_t)(((p << 4) + ((g >> 1) << 3) + l8) * AST + ((g & 1) << 3)) * 2;
        vfo[p] = (uint32_t)((((g & 1) << 3) + l8) * AST + (((p << 1) + (g >> 1)) << 3)) * 2;
    }

    float o[8][4];
#pragma unroll
    for (int i = 0; i < 8; i++)
#pragma unroll
        for (int j = 0; j < 4; j++) o[i][j] = 0.f;
    float mrow0 = -1e30f, mrow1 = -1e30f, lrow0 = 0.f, lrow1 = 0.f;

    APREF_CROSS(0);
    CP_COMMIT();

    for (int t = 0; t < ntile; t++) {
        if (t + 1 < ntile) { APREF_CROSS(t + 1); CP_COMMIT(); CP_WAIT1(); }
        else               { CP_WAIT0(); }
        __syncthreads();
        const uint32_t kb = (uint32_t)(t & 1) * KVB;

        float sc[8][4];
#pragma unroll
        for (int i = 0; i < 8; i++)
#pragma unroll
            for (int j = 0; j < 4; j++) sc[i][j] = 0.f;

#pragma unroll
        for (int kt = 0; kt < 4; kt++) {
            const uint32_t ko = (uint32_t)(kt << 5);
            uint32_t ah0, ah1, ah2, ah3, al0, al1, al2, al3;
            LDSM4(ah0, ah1, ah2, ah3, uQh + qfo + ko);
            LDSM4(al0, al1, al2, al3, uQl + qfo + ko);
#pragma unroll
            for (int p = 0; p < 4; p++) {
                uint32_t k0r, k1r, k2r, k3r;
                LDSM4(k0r, k1r, k2r, k3r, uK + kb + kfo[p] + ko);
                MMA_F16(sc[2*p],   ah0, ah1, ah2, ah3, k0r, k1r);
                MMA_F16(sc[2*p],   al0, al1, al2, al3, k0r, k1r);
                MMA_F16(sc[2*p+1], ah0, ah1, ah2, ah3, k2r, k3r);
                MMA_F16(sc[2*p+1], al0, al1, al2, al3, k2r, k3r);
            }
        }

        const int grow = off + qt * 64 + q0 + r;
#pragma unroll
        for (int nt = 0; nt < 8; nt++) {
            int c0 = t * 64 + nt * 8 + cq;
            sc[nt][0] = (c0     <= grow     && c0     < leny) ? sc[nt][0] * 0.125f : -1e30f;
            sc[nt][1] = (c0 + 1 <= grow     && c0 + 1 < leny) ? sc[nt][1] * 0.125f : -1e30f;
            sc[nt][2] = (c0     <= grow + 8 && c0     < leny) ? sc[nt][2] * 0.125f : -1e30f;
            sc[nt][3] = (c0 + 1 <= grow + 8 && c0 + 1 < leny) ? sc[nt][3] * 0.125f : -1e30f;
        }

        float mx0 = -1e30f, mx1 = -1e30f;
#pragma unroll
        for (int nt = 0; nt < 8; nt++) {
            mx0 = fmaxf(mx0, fmaxf(sc[nt][0], sc[nt][1]));
            mx1 = fmaxf(mx1, fmaxf(sc[nt][2], sc[nt][3]));
        }
        mx0 = fmaxf(mx0, __shfl_xor_sync(0xffffffffu, mx0, 1));
        mx0 = fmaxf(mx0, __shfl_xor_sync(0xffffffffu, mx0, 2));
        mx1 = fmaxf(mx1, __shfl_xor_sync(0xffffffffu, mx1, 1));
        mx1 = fmaxf(mx1, __shfl_xor_sync(0xffffffffu, mx1, 2));
        float mn0 = fmaxf(mrow0, mx0), mn1 = fmaxf(mrow1, mx1);
        float al0f = __expf(mrow0 - mn0), al1f = __expf(mrow1 - mn1);
        float s0 = 0.f, s1 = 0.f;
#pragma unroll
        for (int nt = 0; nt < 8; nt++) {
            sc[nt][0] = __expf(sc[nt][0] - mn0); s0 += sc[nt][0];
            sc[nt][1] = __expf(sc[nt][1] - mn0); s0 += sc[nt][1];
            sc[nt][2] = __expf(sc[nt][2] - mn1); s1 += sc[nt][2];
            sc[nt][3] = __expf(sc[nt][3] - mn1); s1 += sc[nt][3];
        }
        s0 += __shfl_xor_sync(0xffffffffu, s0, 1);
        s0 += __shfl_xor_sync(0xffffffffu, s0, 2);
        s1 += __shfl_xor_sync(0xffffffffu, s1, 1);
        s1 += __shfl_xor_sync(0xffffffffu, s1, 2);
        lrow0 = lrow0 * al0f + s0; mrow0 = mn0;
        lrow1 = lrow1 * al1f + s1; mrow1 = mn1;
#pragma unroll
        for (int nt = 0; nt < 8; nt++) {
            o[nt][0] *= al0f; o[nt][1] *= al0f;
            o[nt][2] *= al1f; o[nt][3] *= al1f;
        }

#pragma unroll
        for (int kc = 0; kc < 4; kc++) {
            uint32_t ph[4], pl[4];
            split_pack_h(sc[2*kc][0],   sc[2*kc][1],   ph[0], pl[0]);
            split_pack_h(sc[2*kc][2],   sc[2*kc][3],   ph[1], pl[1]);
            split_pack_h(sc[2*kc+1][0], sc[2*kc+1][1], ph[2], pl[2]);
            split_pack_h(sc[2*kc+1][2], sc[2*kc+1][3], ph[3], pl[3]);
            const uint32_t vrow = kb + (uint32_t)(kc * 16 * AST) * 2;
#pragma unroll
            for (int p = 0; p < 4; p++) {
                uint32_t v0r, v1r, v2r, v3r;
                LDSM4T(v0r, v1r, v2r, v3r, uV + vrow + vfo[p]);
                MMA_F16(o[2*p],   ph[0], ph[1], ph[2], ph[3], v0r, v1r);
                MMA_F16(o[2*p],   pl[0], pl[1], pl[2], pl[3], v0r, v1r);
                MMA_F16(o[2*p+1], ph[0], ph[1], ph[2], ph[3], v2r, v3r);
                MMA_F16(o[2*p+1], pl[0], pl[1], pl[2], pl[3], v2r, v3r);
            }
        }
        __syncthreads();
    }

    float i0 = 1.f / lrow0, i1 = 1.f / lrow1;
    int row0 = qt * 64 + q0 + r, row1 = row0 + 8;
    bool v0 = row0 < lenx, v1 = row1 < lenx;
    size_t ob = (size_t)b * SXX * 2048 + (size_t)row0 * 2048 + 1024 + h * 64;
#pragma unroll
    for (int dn = 0; dn < 8; dn++) {
        uint32_t hh = 0, ll = 0;
        if (v0) split_pack_h(o[dn][0] * i0, o[dn][1] * i0, hh, ll);
        *(uint32_t*)&cath[ob + dn * 8 + cq] = hh;
        *(uint32_t*)&catl[ob + dn * 8 + cq] = ll;
        hh = 0; ll = 0;
        if (v1) split_pack_h(o[dn][2] * i1, o[dn][3] * i1, hh, ll);
        *(uint32_t*)&cath[ob + (size_t)8 * 2048 + dn * 8 + cq] = hh;
        *(uint32_t*)&catl[ob + (size_t)8 * 2048 + dn * 8 + cq] = ll;
    }
}

// ---------------- launch ----------------
extern "C" void kernel_launch(void* const* d_in, const int* in_sizes, int n_in,
                              void* d_out, int out_size)
{
    const float* x      = (const float*)d_in[0];
    const float* y      = (const float*)d_in[1];
    const float* maskx  = (const float*)d_in[2];
    const float* W_attn = (const float*)d_in[3];
    const float* b_attn = (const float*)d_in[4];
    const float* W_2a   = (const float*)d_in[5];
    const float* b_2a   = (const float*)d_in[6];
    const float* W_2b   = (const float*)d_in[7];
    const float* b_2b   = (const float*)d_in[8];
    const float* W_proj = (const float*)d_in[9];
    const float* b_proj = (const float*)d_in[10];
    const int*   xtb    = (const int*)d_in[11];
    const int*   ytb    = (const int*)d_in[15];

    unsigned short *xh, *xl, *yh, *yl;
    unsigned short *qkvh, *qkvl, *q2h, *q2l, *kv2h, *kv2l, *cath, *catl;
    unsigned short *wqh, *wah, *wbh, *wph, *wpl;
    cudaGetSymbolAddress((void**)&xh, g_xh);     cudaGetSymbolAddress((void**)&xl, g_xl);
    cudaGetSymbolAddress((void**)&yh, g_yh);     cudaGetSymbolAddress((void**)&yl, g_yl);
    cudaGetSymbolAddress((void**)&qkvh, g_qkvh); cudaGetSymbolAddress((void**)&qkvl, g_qkvl);
    cudaGetSymbolAddress((void**)&q2h, g_q2h);   cudaGetSymbolAddress((void**)&q2l, g_q2l);
    cudaGetSymbolAddress((void**)&kv2h, g_kv2h); cudaGetSymbolAddress((void**)&kv2l, g_kv2l);
    cudaGetSymbolAddress((void**)&cath, g_cath); cudaGetSymbolAddress((void**)&catl, g_catl);
    cudaGetSymbolAddress((void**)&wqh, g_wqkv_h);
    cudaGetSymbolAddress((void**)&wah, g_w2a_h);
    cudaGetSymbolAddress((void**)&wbh, g_w2b_h);
    cudaGetSymbolAddress((void**)&wph, g_wpj_h); cudaGetSymbolAddress((void**)&wpl, g_wpj_l);

    const int SMEM_G2 = 6 * TS * 2;
    const int SMEM_G3 = 8 * TS * 2;
    const int SMEM_ATTN = 6 * QB * 2 + 2 * 64 * 4;   // 55808 B
    cudaFuncSetAttribute((const void*)gemm_mma<2>,    cudaFuncAttributeMaxDynamicSharedMemorySize, SMEM_G2);
    cudaFuncSetAttribute((const void*)gemm_mma<3>,    cudaFuncAttributeMaxDynamicSharedMemorySize, SMEM_G3);
    cudaFuncSetAttribute((const void*)attn_self_mma,  cudaFuncAttributeMaxDynamicSharedMemorySize, SMEM_ATTN);
    cudaFuncSetAttribute((const void*)attn_cross_mma, cudaFuncAttributeMaxDynamicSharedMemorySize, SMEM_ATTN);

    lens_kernel<<<1, 256>>>(xtb, in_sizes[11], ytb, in_sizes[15]);

    split_fp32<<<2048, 256>>>(x, xh, xl, 2048 * 1024 / 4);
    split_fp32<<<2048, 256>>>(y, yh, yl, 2048 * 1024 / 4);
    transpose_cvt<<<dim3(96, 32), 256>>>(W_attn, wqh, nullptr, 1024, 3072);
    transpose_cvt<<<dim3(32, 32), 256>>>(W_2a,   wah, nullptr, 1024, 1024);
    transpose_cvt<<<dim3(64, 32), 256>>>(W_2b,   wbh, nullptr, 1024, 2048);
    transpose_cvt<<<dim3(32, 64), 256>>>(W_proj, wph, wpl,     2048, 1024);

    gemm_mma<2><<<dim3(24, 16), 256, SMEM_G2>>>(xh, xl, wqh, nullptr, b_attn, nullptr, qkvh, qkvl, 2048, 3072, 1024);
    gemm_mma<2><<<dim3(8,  16), 256, SMEM_G2>>>(xh, xl, wah, nullptr, b_2a,   nullptr, q2h,  q2l,  2048, 1024, 1024);
    gemm_mma<2><<<dim3(16, 16), 256, SMEM_G2>>>(yh, yl, wbh, nullptr, b_2b,   nullptr, kv2h, kv2l, 2048, 2048, 1024);

    attn_self_mma <<<dim3(16, 16, 2), 128, SMEM_ATTN>>>(qkvh, qkvl, maskx, cath, catl);
    attn_cross_mma<<<dim3(16, 16, 2), 128, SMEM_ATTN>>>(q2h, q2l, kv2h, cath, catl);

    gemm_mma<3><<<dim3(8, 16), 256, SMEM_G3>>>(cath, catl, wph, wpl, b_proj, (float*)d_out, nullptr, nullptr, 2048, 1024, 2048);
}

// round 8
// speedup vs baseline: 4.0394x; 1.1024x over previous
#include <cuda_runtime.h>
#include <cuda_fp16.h>
#include <cstdint>

#define NB    2
#define SXX   1024
#define SYY   1024
#define DIM   1024
#define NH    16
#define HDIM  64
#define FULLN 1536

// ---------------- scratch (device globals) ----------------
__device__ int   g_lens[4];
__device__ float g_bias4k[4096];

__device__ unsigned short g_xh [2048 * 1024], g_xl [2048 * 1024];
__device__ unsigned short g_yh [2048 * 1024], g_yl [2048 * 1024];
// fused QKV|Q2 output: cols 0-1023 Q, 1024-2047 K, 2048-3071 V, 3072-4095 Q2
__device__ unsigned short g_qkvh[2048 * 4096], g_qkvl[2048 * 4096];
__device__ unsigned short g_kv2h[2048 * 2048];
__device__ unsigned short g_cath[2048 * 2048];
// weights [N,K] K-major
__device__ unsigned short g_wc_h [4096 * 1024];                    // W_attn|W_2a fused
__device__ unsigned short g_w2b_h[2048 * 1024];
__device__ unsigned short g_wpj_h[1024 * 2048], g_wpj_l[1024 * 2048];

// ---------------- helpers ----------------
__device__ __forceinline__ uint32_t smem_u32(const void* p) {
    uint32_t a;
    asm("{ .reg .u64 t; cvta.to.shared.u64 t, %1; cvt.u32.u64 %0, t; }" : "=r"(a) : "l"(p));
    return a;
}
#define CP_ASYNC16(dst, src) \
    asm volatile("cp.async.ca.shared.global [%0], [%1], 16;" :: "r"(dst), "l"(src) : "memory")
#define CP_COMMIT() asm volatile("cp.async.commit_group;" ::: "memory")
#define CP_WAIT1()  asm volatile("cp.async.wait_group 1;" ::: "memory")
#define CP_WAIT0()  asm volatile("cp.async.wait_group 0;" ::: "memory")

#define MMA_F16(c, a0, a1, a2, a3, b0, b1) \
    asm volatile("mma.sync.aligned.m16n8k16.row.col.f32.f16.f16.f32 " \
        "{%0,%1,%2,%3}, {%4,%5,%6,%7}, {%8,%9}, {%0,%1,%2,%3};" \
        : "+f"((c)[0]), "+f"((c)[1]), "+f"((c)[2]), "+f"((c)[3]) \
        : "r"(a0), "r"(a1), "r"(a2), "r"(a3), "r"(b0), "r"(b1))

#define LDSM4(r0, r1, r2, r3, a) \
    asm volatile("ldmatrix.sync.aligned.m8n8.x4.shared.b16 {%0,%1,%2,%3}, [%4];" \
        : "=r"(r0), "=r"(r1), "=r"(r2), "=r"(r3) : "r"(a))
#define LDSM4T(r0, r1, r2, r3, a) \
    asm volatile("ldmatrix.sync.aligned.m8n8.x4.trans.shared.b16 {%0,%1,%2,%3}, [%4];" \
        : "=r"(r0), "=r"(r1), "=r"(r2), "=r"(r3) : "r"(a))

__device__ __forceinline__ void split_pack_h(float a, float b, uint32_t& h, uint32_t& l) {
    __half ha = __float2half_rn(a), hb = __float2half_rn(b);
    __half la = __float2half_rn(a - __half2float(ha));
    __half lb = __float2half_rn(b - __half2float(hb));
    h = (uint32_t)*(unsigned short*)&ha | ((uint32_t)*(unsigned short*)&hb << 16);
    l = (uint32_t)*(unsigned short*)&la | ((uint32_t)*(unsigned short*)&lb << 16);
}
__device__ __forceinline__ uint32_t pack_h2(float a, float b) {
    __half2 v = __floats2half2_rn(a, b);
    return *(uint32_t*)&v;
}

// ---------------- per-batch lengths ----------------
__global__ void lens_kernel(const int* __restrict__ xb, int nx,
                            const int* __restrict__ yb, int ny)
{
    __shared__ int cnt[4];
    int t = threadIdx.x;
    if (t < 4) cnt[t] = 0;
    __syncthreads();
    for (int i = t; i < nx; i += blockDim.x) atomicAdd(&cnt[xb[i]], 1);
    for (int i = t; i < ny; i += blockDim.x) atomicAdd(&cnt[2 + yb[i]], 1);
    __syncthreads();
    if (t < 4) g_lens[t] = cnt[t];
}

__global__ void concat_bias(const float* __restrict__ a, const float* __restrict__ b,
                            float* __restrict__ out)
{
    int i = blockIdx.x * 256 + threadIdx.x;
    if (i < 3072) out[i] = a[i];
    else if (i < 4096) out[i] = b[i - 3072];
}

// ---------------- fp32 -> fp16 hi/lo split ----------------
__global__ __launch_bounds__(256)
void split_fp32(const float* __restrict__ in, unsigned short* __restrict__ oh,
                unsigned short* __restrict__ ol, int n4)
{
    int i = blockIdx.x * 256 + threadIdx.x;
    if (i >= n4) return;
    float4 v = ((const float4*)in)[i];
    uint32_t h0, l0, h1, l1;
    split_pack_h(v.x, v.y, h0, l0);
    split_pack_h(v.z, v.w, h1, l1);
    ((uint2*)oh)[i] = make_uint2(h0, h1);
    ((uint2*)ol)[i] = make_uint2(l0, l1);
}

// ---------------- W[K,N] -> Wt[N,K] fp16 ----------------
__global__ __launch_bounds__(256)
void transpose_cvt(const float* __restrict__ in, unsigned short* __restrict__ oh,
                   unsigned short* __restrict__ ol, int K, int N)
{
    __shared__ float tile[32][33];
    int n0 = blockIdx.x << 5, k0 = blockIdx.y << 5;
    int tx = threadIdx.x & 31, ty = threadIdx.x >> 5;
    for (int i = ty; i < 32; i += 8)
        tile[i][tx] = in[(size_t)(k0 + i) * N + n0 + tx];
    __syncthreads();
    for (int i = ty; i < 32; i += 8) {
        float v = tile[tx][i];
        __half h = __float2half_rn(v);
        size_t o = (size_t)(n0 + i) * K + k0 + tx;
        oh[o] = *(unsigned short*)&h;
        if (ol) {
            __half l = __float2half_rn(v - __half2float(h));
            ol[o] = *(unsigned short*)&l;
        }
    }
}

// ---------------- mma.sync fp16 2-product GEMM ----------------
// MODE 0: C = (Ah+Al)·Bh, out fp16 hi/lo     (fused qkv+q2)
// MODE 1: C = (Ah+Al)·Bh, out fp16 hi only   (kv2)
// MODE 2: C = Ah·(Bh+Bl), out fp32           (proj)
#define TS   (128 * 40)
template<int MODE>
__global__ __launch_bounds__(256)
void gemm_mma(const unsigned short* __restrict__ Ah, const unsigned short* __restrict__ Al,
              const unsigned short* __restrict__ Bh, const unsigned short* __restrict__ Bl,
              const float* __restrict__ bias, float* __restrict__ Cf,
              unsigned short* __restrict__ Ch, unsigned short* __restrict__ Cl,
              int M, int N, int K)
{
    constexpr bool A2 = (MODE != 2);
    constexpr bool B2 = (MODE == 2);

    extern __shared__ unsigned short sm16[];
    unsigned short* sAh = sm16;
    unsigned short* sX  = sm16 + 2 * TS;     // Al (A2) or Bl (B2)
    unsigned short* sBh = sm16 + 4 * TS;
    const uint32_t uAh = smem_u32(sAh), uX = smem_u32(sX), uBh = smem_u32(sBh);

    const int tid  = threadIdx.x;
    const int lane = tid & 31, wid = tid >> 5;
    const int wm = (wid >> 2) << 6;
    const int wn = (wid & 3) << 5;
    const int bm = blockIdx.y << 7, bn = blockIdx.x << 7;

    float acc[4][4][4];
#pragma unroll
    for (int i = 0; i < 4; i++)
#pragma unroll
        for (int j = 0; j < 4; j++)
#pragma unroll
            for (int k = 0; k < 4; k++) acc[i][j][k] = 0.f;

    const int lr = tid >> 2;
    const int ls = tid & 3;
    const int nchunk = K >> 5;

#define PREFETCH(t) do { \
        int buf_ = (t) & 1; \
        int k0_  = (t) << 5; \
        _Pragma("unroll") \
        for (int p_ = 0; p_ < 2; p_++) { \
            int row_ = lr + (p_ << 6); \
            uint32_t so_ = (uint32_t)(buf_ * TS + row_ * 40 + ls * 8) * 2; \
            size_t ao_ = (size_t)(bm + row_) * K + k0_ + ls * 8; \
            size_t bo_ = (size_t)(bn + row_) * K + k0_ + ls * 8; \
            CP_ASYNC16(uAh + so_, Ah + ao_); \
            if (A2) CP_ASYNC16(uX + so_, Al + ao_); \
            CP_ASYNC16(uBh + so_, Bh + bo_); \
            if (B2) CP_ASYNC16(uX + so_, Bl + bo_); \
        } \
    } while (0)

    PREFETCH(0);
    CP_COMMIT();

    const int l8 = lane & 7, g = lane >> 3;
    uint32_t aoff[4], boff[2];
#pragma unroll
    for (int mi = 0; mi < 4; mi++)
        aoff[mi] = (uint32_t)((wm + (mi << 4) + ((g & 1) << 3) + l8) * 40 + ((g >> 1) << 3)) * 2;
#pragma unroll
    for (int p = 0; p < 2; p++)
        boff[p] = (uint32_t)((wn + (p << 4) + ((g >> 1) << 3) + l8) * 40 + ((g & 1) << 3)) * 2;

    const int fr = lane >> 2;
    const int fc = (lane & 3) << 1;

    for (int t = 0; t < nchunk; t++) {
        if (t + 1 < nchunk) { PREFETCH(t + 1); CP_COMMIT(); CP_WAIT1(); }
        else                { CP_WAIT0(); }
        __syncthreads();
        const uint32_t bufB = (uint32_t)(t & 1) * (TS * 2);
#pragma unroll
        for (int kk = 0; kk < 2; kk++) {
            const uint32_t kof = bufB + (kk << 5);
            uint32_t bh[2][4], bl[2][4];
#pragma unroll
            for (int p = 0; p < 2; p++) {
                LDSM4(bh[p][0], bh[p][1], bh[p][2], bh[p][3], uBh + kof + boff[p]);
                if (B2)
                    LDSM4(bl[p][0], bl[p][1], bl[p][2], bl[p][3], uX + kof + boff[p]);
            }
#pragma unroll
            for (int mi = 0; mi < 4; mi++) {
                uint32_t ah0, ah1, ah2, ah3, al0, al1, al2, al3;
                LDSM4(ah0, ah1, ah2, ah3, uAh + kof + aoff[mi]);
                if (A2) LDSM4(al0, al1, al2, al3, uX + kof + aoff[mi]);
#pragma unroll
                for (int p = 0; p < 2; p++) {
                    MMA_F16(acc[mi][2*p],   ah0, ah1, ah2, ah3, bh[p][0], bh[p][1]);
                    if (B2)
                        MMA_F16(acc[mi][2*p], ah0, ah1, ah2, ah3, bl[p][0], bl[p][1]);
                    if (A2)
                        MMA_F16(acc[mi][2*p], al0, al1, al2, al3, bh[p][0], bh[p][1]);
                    MMA_F16(acc[mi][2*p+1], ah0, ah1, ah2, ah3, bh[p][2], bh[p][3]);
                    if (B2)
                        MMA_F16(acc[mi][2*p+1], ah0, ah1, ah2, ah3, bl[p][2], bl[p][3]);
                    if (A2)
                        MMA_F16(acc[mi][2*p+1], al0, al1, al2, al3, bh[p][2], bh[p][3]);
                }
            }
        }
        __syncthreads();
    }

    if (MODE == 2) {
#pragma unroll
        for (int mi = 0; mi < 4; mi++) {
            int row = bm + wm + (mi << 4) + fr;
#pragma unroll
            for (int ni = 0; ni < 4; ni++) {
                int col = bn + wn + (ni << 3) + fc;
                float bx = bias[col], by = bias[col + 1];
                float2 v0 = { acc[mi][ni][0] + bx, acc[mi][ni][1] + by };
                float2 v1 = { acc[mi][ni][2] + bx, acc[mi][ni][3] + by };
                *(float2*)(Cf + (size_t)row * N + col)       = v0;
                *(float2*)(Cf + (size_t)(row + 8) * N + col) = v1;
            }
        }
    } else if (MODE == 0) {
#pragma unroll
        for (int mi = 0; mi < 4; mi++) {
            int row = bm + wm + (mi << 4) + fr;
#pragma unroll
            for (int ni = 0; ni < 4; ni++) {
                int col = bn + wn + (ni << 3) + fc;
                float bx = bias[col], by = bias[col + 1];
                uint32_t hh, ll;
                split_pack_h(acc[mi][ni][0] + bx, acc[mi][ni][1] + by, hh, ll);
                *(uint32_t*)&Ch[(size_t)row * N + col] = hh;
                *(uint32_t*)&Cl[(size_t)row * N + col] = ll;
                split_pack_h(acc[mi][ni][2] + bx, acc[mi][ni][3] + by, hh, ll);
                *(uint32_t*)&Ch[(size_t)(row + 8) * N + col] = hh;
                *(uint32_t*)&Cl[(size_t)(row + 8) * N + col] = ll;
            }
        }
    } else {
#pragma unroll
        for (int mi = 0; mi < 4; mi++) {
            int row = bm + wm + (mi << 4) + fr;
#pragma unroll
            for (int ni = 0; ni < 4; ni++) {
                int col = bn + wn + (ni << 3) + fc;
                float bx = bias[col], by = bias[col + 1];
                *(uint32_t*)&Ch[(size_t)row * N + col] =
                    pack_h2(acc[mi][ni][0] + bx, acc[mi][ni][1] + by);
                *(uint32_t*)&Ch[(size_t)(row + 8) * N + col] =
                    pack_h2(acc[mi][ni][2] + bx, acc[mi][ni][3] + by);
            }
        }
    }
}

// ================= MMA flash attention =================
#define AST 72
#define QB  (64 * AST)
#define KVB (QB * 2)
#define QSTRIDE 4096

// ---------------- self attention ----------------
__global__ __launch_bounds__(128)
void attn_self_mma(const unsigned short* __restrict__ qkvh,
                   const unsigned short* __restrict__ qkvl,
                   const float* __restrict__ mask,
                   unsigned short* __restrict__ cath)
{
    extern __shared__ char smraw[];
    unsigned short* sQh = (unsigned short*)smraw;
    unsigned short* sQl = sQh + QB;
    unsigned short* sK  = sQl + QB;
    unsigned short* sV  = sK  + 2 * QB;
    float* sMsf = (float*)(sV + 2 * QB);
    const uint32_t uQh = smem_u32(sQh), uQl = smem_u32(sQl);
    const uint32_t uK = smem_u32(sK), uV = smem_u32(sV);
    const uint32_t uMs = smem_u32(sMsf);

    const int qt = blockIdx.x, h = blockIdx.y, b = blockIdx.z;
    const int tid = threadIdx.x, lane = tid & 31, wid = tid >> 5;
    const int q0 = wid << 4;
    const int r = lane >> 2, cq = (lane & 3) << 1;
    const int l8 = lane & 7, g = lane >> 3;

    const size_t gb = (size_t)b * SXX * QSTRIDE;
    for (int i = tid; i < 512; i += 128) {
        int rr = i >> 3, seg = i & 7;
        size_t src = gb + (size_t)(qt * 64 + rr) * QSTRIDE + h * 64 + seg * 8;
        *(uint4*)&sQh[rr * AST + seg * 8] = *(const uint4*)&qkvh[src];
        *(uint4*)&sQl[rr * AST + seg * 8] = *(const uint4*)&qkvl[src];
    }

    const float* maskb = mask + b * SXX;
    const int lenx = g_lens[b];
    int nt1 = qt + 1, nt2 = (lenx + 63) >> 6;
    const int ntile = nt1 < nt2 ? nt1 : nt2;

#define APREF_SELF(t) do { \
        uint32_t kd_ = uK + (uint32_t)((t) & 1) * KVB; \
        uint32_t vd_ = uV + (uint32_t)((t) & 1) * KVB; \
        _Pragma("unroll") \
        for (int it_ = 0; it_ < 4; it_++) { \
            int i_ = tid + it_ * 128; \
            int rr_ = i_ >> 3, sg_ = i_ & 7; \
            size_t kr_ = gb + (size_t)((t) * 64 + rr_) * QSTRIDE + 1024 + h * 64 + sg_ * 8; \
            uint32_t so_ = (uint32_t)(rr_ * AST + sg_ * 8) * 2; \
            CP_ASYNC16(kd_ + so_, qkvh + kr_); \
            CP_ASYNC16(vd_ + so_, qkvh + kr_ + 1024); \
        } \
        if (tid < 16) CP_ASYNC16(uMs + ((t) & 1) * 256 + tid * 16, maskb + (t) * 64 + tid * 4); \
    } while (0)

    uint32_t qfo = (uint32_t)((q0 + ((g & 1) << 3) + l8) * AST + ((g >> 1) << 3)) * 2;
    uint32_t kfo[4], vfo[4];
#pragma unroll
    for (int p = 0; p < 4; p++) {
        kfo[p] = (uint32_t)(((p << 4) + ((g >> 1) << 3) + l8) * AST + ((g & 1) << 3)) * 2;
        vfo[p] = (uint32_t)((((g & 1) << 3) + l8) * AST + (((p << 1) + (g >> 1)) << 3)) * 2;
    }

    float o[8][4];
#pragma unroll
    for (int i = 0; i < 8; i++)
#pragma unroll
        for (int j = 0; j < 4; j++) o[i][j] = 0.f;
    float mrow0 = -1e30f, mrow1 = -1e30f, lrow0 = 0.f, lrow1 = 0.f;

    APREF_SELF(0);
    CP_COMMIT();

    for (int t = 0; t < ntile; t++) {
        if (t + 1 < ntile) { APREF_SELF(t + 1); CP_COMMIT(); CP_WAIT1(); }
        else               { CP_WAIT0(); }
        __syncthreads();
        const uint32_t kb = (uint32_t)(t & 1) * KVB;
        const int mb = (t & 1) * 64;

        float sc[8][4];
#pragma unroll
        for (int i = 0; i < 8; i++)
#pragma unroll
            for (int j = 0; j < 4; j++) sc[i][j] = 0.f;

#pragma unroll
        for (int kt = 0; kt < 4; kt++) {
            const uint32_t ko = (uint32_t)(kt << 5);
            uint32_t ah0, ah1, ah2, ah3, al0, al1, al2, al3;
            LDSM4(ah0, ah1, ah2, ah3, uQh + qfo + ko);
            LDSM4(al0, al1, al2, al3, uQl + qfo + ko);
#pragma unroll
            for (int p = 0; p < 4; p++) {
                uint32_t k0r, k1r, k2r, k3r;
                LDSM4(k0r, k1r, k2r, k3r, uK + kb + kfo[p] + ko);
                MMA_F16(sc[2*p],   ah0, ah1, ah2, ah3, k0r, k1r);
                MMA_F16(sc[2*p],   al0, al1, al2, al3, k0r, k1r);
                MMA_F16(sc[2*p+1], ah0, ah1, ah2, ah3, k2r, k3r);
                MMA_F16(sc[2*p+1], al0, al1, al2, al3, k2r, k3r);
            }
        }

        const int grow = qt * 64 + q0 + r;
#pragma unroll
        for (int nt = 0; nt < 8; nt++) {
            int c0 = t * 64 + nt * 8 + cq;
            float m0 = sMsf[mb + nt * 8 + cq], m1 = sMsf[mb + nt * 8 + cq + 1];
            float v;
            v = sc[nt][0] * 0.125f; sc[nt][0] = ((c0     <= grow    ) ? v : -10000.f) + m0;
            v = sc[nt][1] * 0.125f; sc[nt][1] = ((c0 + 1 <= grow    ) ? v : -10000.f) + m1;
            v = sc[nt][2] * 0.125f; sc[nt][2] = ((c0     <= grow + 8) ? v : -10000.f) + m0;
            v = sc[nt][3] * 0.125f; sc[nt][3] = ((c0 + 1 <= grow + 8) ? v : -10000.f) + m1;
        }

        float mx0 = -1e30f, mx1 = -1e30f;
#pragma unroll
        for (int nt = 0; nt < 8; nt++) {
            mx0 = fmaxf(mx0, fmaxf(sc[nt][0], sc[nt][1]));
            mx1 = fmaxf(mx1, fmaxf(sc[nt][2], sc[nt][3]));
        }
        mx0 = fmaxf(mx0, __shfl_xor_sync(0xffffffffu, mx0, 1));
        mx0 = fmaxf(mx0, __shfl_xor_sync(0xffffffffu, mx0, 2));
        mx1 = fmaxf(mx1, __shfl_xor_sync(0xffffffffu, mx1, 1));
        mx1 = fmaxf(mx1, __shfl_xor_sync(0xffffffffu, mx1, 2));
        float mn0 = fmaxf(mrow0, mx0), mn1 = fmaxf(mrow1, mx1);
        float al0f = __expf(mrow0 - mn0), al1f = __expf(mrow1 - mn1);
        float s0 = 0.f, s1 = 0.f;
#pragma unroll
        for (int nt = 0; nt < 8; nt++) {
            sc[nt][0] = __expf(sc[nt][0] - mn0); s0 += sc[nt][0];
            sc[nt][1] = __expf(sc[nt][1] - mn0); s0 += sc[nt][1];
            sc[nt][2] = __expf(sc[nt][2] - mn1); s1 += sc[nt][2];
            sc[nt][3] = __expf(sc[nt][3] - mn1); s1 += sc[nt][3];
        }
        s0 += __shfl_xor_sync(0xffffffffu, s0, 1);
        s0 += __shfl_xor_sync(0xffffffffu, s0, 2);
        s1 += __shfl_xor_sync(0xffffffffu, s1, 1);
        s1 += __shfl_xor_sync(0xffffffffu, s1, 2);
        lrow0 = lrow0 * al0f + s0; mrow0 = mn0;
        lrow1 = lrow1 * al1f + s1; mrow1 = mn1;
#pragma unroll
        for (int nt = 0; nt < 8; nt++) {
            o[nt][0] *= al0f; o[nt][1] *= al0f;
            o[nt][2] *= al1f; o[nt][3] *= al1f;
        }

#pragma unroll
        for (int kc = 0; kc < 4; kc++) {
            uint32_t ph[4], pl[4];
            split_pack_h(sc[2*kc][0],   sc[2*kc][1],   ph[0], pl[0]);
            split_pack_h(sc[2*kc][2],   sc[2*kc][3],   ph[1], pl[1]);
            split_pack_h(sc[2*kc+1][0], sc[2*kc+1][1], ph[2], pl[2]);
            split_pack_h(sc[2*kc+1][2], sc[2*kc+1][3], ph[3], pl[3]);
            const uint32_t vrow = kb + (uint32_t)(kc * 16 * AST) * 2;
#pragma unroll
            for (int p = 0; p < 4; p++) {
                uint32_t v0r, v1r, v2r, v3r;
                LDSM4T(v0r, v1r, v2r, v3r, uV + vrow + vfo[p]);
                MMA_F16(o[2*p],   ph[0], ph[1], ph[2], ph[3], v0r, v1r);
                MMA_F16(o[2*p],   pl[0], pl[1], pl[2], pl[3], v0r, v1r);
                MMA_F16(o[2*p+1], ph[0], ph[1], ph[2], ph[3], v2r, v3r);
                MMA_F16(o[2*p+1], pl[0], pl[1], pl[2], pl[3], v2r, v3r);
            }
        }
        __syncthreads();
    }

    float i0 = 1.f / lrow0, i1 = 1.f / lrow1;
    size_t ob = (size_t)b * SXX * 2048 + (size_t)(qt * 64 + q0 + r) * 2048 + h * 64;
#pragma unroll
    for (int dn = 0; dn < 8; dn++) {
        *(uint32_t*)&cath[ob + dn * 8 + cq] = pack_h2(o[dn][0] * i0, o[dn][1] * i0);
        *(uint32_t*)&cath[ob + (size_t)8 * 2048 + dn * 8 + cq] = pack_h2(o[dn][2] * i1, o[dn][3] * i1);
    }
}

// ---------------- cross attention ----------------
__global__ __launch_bounds__(128)
void attn_cross_mma(const unsigned short* __restrict__ qkvh,
                    const unsigned short* __restrict__ qkvl,
                    const unsigned short* __restrict__ kvh,
                    unsigned short* __restrict__ cath)
{
    extern __shared__ char smraw[];
    unsigned short* sQh = (unsigned short*)smraw;
    unsigned short* sQl = sQh + QB;
    unsigned short* sK  = sQl + QB;
    unsigned short* sV  = sK  + 2 * QB;
    const uint32_t uQh = smem_u32(sQh), uQl = smem_u32(sQl);
    const uint32_t uK = smem_u32(sK), uV = smem_u32(sV);

    const int qt = blockIdx.x, h = blockIdx.y, b = blockIdx.z;
    const int tid = threadIdx.x, lane = tid & 31, wid = tid >> 5;
    const int q0 = wid << 4;
    const int r = lane >> 2, cq = (lane & 3) << 1;
    const int l8 = lane & 7, g = lane >> 3;

    const int lenx = g_lens[b], leny = g_lens[2 + b];
    const int off  = FULLN - lenx;

    size_t obase = (size_t)b * SXX * 2048 + (size_t)(qt * 64) * 2048 + 1024 + h * 64;
    if (qt * 64 >= lenx) {
        const uint4 z = {0, 0, 0, 0};
        for (int i = tid; i < 512; i += 128) {
            int rr = i >> 3, seg = i & 7;
            *(uint4*)&cath[obase + (size_t)rr * 2048 + seg * 8] = z;
        }
        return;
    }

    const size_t qgb = (size_t)b * SXX * QSTRIDE;
    for (int i = tid; i < 512; i += 128) {
        int rr = i >> 3, seg = i & 7;
        size_t src = qgb + (size_t)(qt * 64 + rr) * QSTRIDE + 3072 + h * 64 + seg * 8;
        *(uint4*)&sQh[rr * AST + seg * 8] = *(const uint4*)&qkvh[src];
        *(uint4*)&sQl[rr * AST + seg * 8] = *(const uint4*)&qkvl[src];
    }

    int qlast = qt * 64 + 63;
    if (qlast >= lenx) qlast = lenx - 1;
    int jmax = off + qlast + 1;
    if (jmax > leny) jmax = leny;
    const int ntile = (jmax + 63) >> 6;
    const size_t kgb = (size_t)b * SYY * 2048;

#define APREF_CROSS(t) do { \
        uint32_t kd_ = uK + (uint32_t)((t) & 1) * KVB; \
        uint32_t vd_ = uV + (uint32_t)((t) & 1) * KVB; \
        _Pragma("unroll") \
        for (int it_ = 0; it_ < 4; it_++) { \
            int i_ = tid + it_ * 128; \
            int rr_ = i_ >> 3, sg_ = i_ & 7; \
            size_t kr_ = kgb + (size_t)((t) * 64 + rr_) * 2048 + h * 64 + sg_ * 8; \
            uint32_t so_ = (uint32_t)(rr_ * AST + sg_ * 8) * 2; \
            CP_ASYNC16(kd_ + so_, kvh + kr_); \
            CP_ASYNC16(vd_ + so_, kvh + kr_ + 1024); \
        } \
    } while (0)

    uint32_t qfo = (uint32_t)((q0 + ((g & 1) << 3) + l8) * AST + ((g >> 1) << 3)) * 2;
    uint32_t kfo[4], vfo[4];
#pragma unroll
    for (int p = 0; p < 4; p++) {
        kfo[p] = (uint32_t)(((p << 4) + ((g >> 1) << 3) + l8) * AST + ((g & 1) << 3)) * 2;
        vfo[p] = (uint32_t)((((g & 1) << 3) + l8) * AST + (((p << 1) + (g >> 1)) << 3)) * 2;
    }

    float o[8][4];
#pragma unroll
    for (int i = 0; i < 8; i++)
#pragma unroll
        for (int j = 0; j < 4; j++) o[i][j] = 0.f;
    float mrow0 = -1e30f, mrow1 = -1e30f, lrow0 = 0.f, lrow1 = 0.f;

    APREF_CROSS(0);
    CP_COMMIT();

    for (int t = 0; t < ntile; t++) {
        if (t + 1 < ntile) { APREF_CROSS(t + 1); CP_COMMIT(); CP_WAIT1(); }
        else               { CP_WAIT0(); }
        __syncthreads();
        const uint32_t kb = (uint32_t)(t & 1) * KVB;

        float sc[8][4];
#pragma unroll
        for (int i = 0; i < 8; i++)
#pragma unroll
            for (int j = 0; j < 4; j++) sc[i][j] = 0.f;

#pragma unroll
        for (int kt = 0; kt < 4; kt++) {
            const uint32_t ko = (uint32_t)(kt << 5);
            uint32_t ah0, ah1, ah2, ah3, al0, al1, al2, al3;
            LDSM4(ah0, ah1, ah2, ah3, uQh + qfo + ko);
            LDSM4(al0, al1, al2, al3, uQl + qfo + ko);
#pragma unroll
            for (int p = 0; p < 4; p++) {
                uint32_t k0r, k1r, k2r, k3r;
                LDSM4(k0r, k1r, k2r, k3r, uK + kb + kfo[p] + ko);
                MMA_F16(sc[2*p],   ah0, ah1, ah2, ah3, k0r, k1r);
                MMA_F16(sc[2*p],   al0, al1, al2, al3, k0r, k1r);
                MMA_F16(sc[2*p+1], ah0, ah1, ah2, ah3, k2r, k3r);
                MMA_F16(sc[2*p+1], al0, al1, al2, al3, k2r, k3r);
            }
        }

        const int grow = off + qt * 64 + q0 + r;
#pragma unroll
        for (int nt = 0; nt < 8; nt++) {
            int c0 = t * 64 + nt * 8 + cq;
            sc[nt][0] = (c0     <= grow     && c0     < leny) ? sc[nt][0] * 0.125f : -1e30f;
            sc[nt][1] = (c0 + 1 <= grow     && c0 + 1 < leny) ? sc[nt][1] * 0.125f : -1e30f;
            sc[nt][2] = (c0     <= grow + 8 && c0     < leny) ? sc[nt][2] * 0.125f : -1e30f;
            sc[nt][3] = (c0 + 1 <= grow + 8 && c0 + 1 < leny) ? sc[nt][3] * 0.125f : -1e30f;
        }

        float mx0 = -1e30f, mx1 = -1e30f;
#pragma unroll
        for (int nt = 0; nt < 8; nt++) {
            mx0 = fmaxf(mx0, fmaxf(sc[nt][0], sc[nt][1]));
            mx1 = fmaxf(mx1, fmaxf(sc[nt][2], sc[nt][3]));
        }
        mx0 = fmaxf(mx0, __shfl_xor_sync(0xffffffffu, mx0, 1));
        mx0 = fmaxf(mx0, __shfl_xor_sync(0xffffffffu, mx0, 2));
        mx1 = fmaxf(mx1, __shfl_xor_sync(0xffffffffu, mx1, 1));
        mx1 = fmaxf(mx1, __shfl_xor_sync(0xffffffffu, mx1, 2));
        float mn0 = fmaxf(mrow0, mx0), mn1 = fmaxf(mrow1, mx1);
        float al0f = __expf(mrow0 - mn0), al1f = __expf(mrow1 - mn1);
        float s0 = 0.f, s1 = 0.f;
#pragma unroll
        for (int nt = 0; nt < 8; nt++) {
            sc[nt][0] = __expf(sc[nt][0] - mn0); s0 += sc[nt][0];
            sc[nt][1] = __expf(sc[nt][1] - mn0); s0 += sc[nt][1];
            sc[nt][2] = __expf(sc[nt][2] - mn1); s1 += sc[nt][2];
            sc[nt][3] = __expf(sc[nt][3] - mn1); s1 += sc[nt][3];
        }
        s0 += __shfl_xor_sync(0xffffffffu, s0, 1);
        s0 += __shfl_xor_sync(0xffffffffu, s0, 2);
        s1 += __shfl_xor_sync(0xffffffffu, s1, 1);
        s1 += __shfl_xor_sync(0xffffffffu, s1, 2);
        lrow0 = lrow0 * al0f + s0; mrow0 = mn0;
        lrow1 = lrow1 * al1f + s1; mrow1 = mn1;
#pragma unroll
        for (int nt = 0; nt < 8; nt++) {
            o[nt][0] *= al0f; o[nt][1] *= al0f;
            o[nt][2] *= al1f; o[nt][3] *= al1f;
        }

#pragma unroll
        for (int kc = 0; kc < 4; kc++) {
            uint32_t ph[4], pl[4];
            split_pack_h(sc[2*kc][0],   sc[2*kc][1],   ph[0], pl[0]);
            split_pack_h(sc[2*kc][2],   sc[2*kc][3],   ph[1], pl[1]);
            split_pack_h(sc[2*kc+1][0], sc[2*kc+1][1], ph[2], pl[2]);
            split_pack_h(sc[2*kc+1][2], sc[2*kc+1][3], ph[3], pl[3]);
            const uint32_t vrow = kb + (uint32_t)(kc * 16 * AST) * 2;
#pragma unroll
            for (int p = 0; p < 4; p++) {
                uint32_t v0r, v1r, v2r, v3r;
                LDSM4T(v0r, v1r, v2r, v3r, uV + vrow + vfo[p]);
                MMA_F16(o[2*p],   ph[0], ph[1], ph[2], ph[3], v0r, v1r);
                MMA_F16(o[2*p],   pl[0], pl[1], pl[2], pl[3], v0r, v1r);
                MMA_F16(o[2*p+1], ph[0], ph[1], ph[2], ph[3], v2r, v3r);
                MMA_F16(o[2*p+1], pl[0], pl[1], pl[2], pl[3], v2r, v3r);
            }
        }
        __syncthreads();
    }

    float i0 = 1.f / lrow0, i1 = 1.f / lrow1;
    int row0 = qt * 64 + q0 + r, row1 = row0 + 8;
    bool v0 = row0 < lenx, v1 = row1 < lenx;
    size_t ob = (size_t)b * SXX * 2048 + (size_t)row0 * 2048 + 1024 + h * 64;
#pragma unroll
    for (int dn = 0; dn < 8; dn++) {
        *(uint32_t*)&cath[ob + dn * 8 + cq] =
            v0 ? pack_h2(o[dn][0] * i0, o[dn][1] * i0) : 0u;
        *(uint32_t*)&cath[ob + (size_t)8 * 2048 + dn * 8 + cq] =
            v1 ? pack_h2(o[dn][2] * i1, o[dn][3] * i1) : 0u;
    }
}

// ---------------- launch ----------------
extern "C" void kernel_launch(void* const* d_in, const int* in_sizes, int n_in,
                              void* d_out, int out_size)
{
    const float* x      = (const float*)d_in[0];
    const float* y      = (const float*)d_in[1];
    const float* maskx  = (const float*)d_in[2];
    const float* W_attn = (const float*)d_in[3];
    const float* b_attn = (const float*)d_in[4];
    const float* W_2a   = (const float*)d_in[5];
    const float* b_2a   = (const float*)d_in[6];
    const float* W_2b   = (const float*)d_in[7];
    const float* b_2b   = (const float*)d_in[8];
    const float* W_proj = (const float*)d_in[9];
    const float* b_proj = (const float*)d_in[10];
    const int*   xtb    = (const int*)d_in[11];
    const int*   ytb    = (const int*)d_in[15];

    unsigned short *xh, *xl, *yh, *yl;
    unsigned short *qkvh, *qkvl, *kv2h, *cath;
    unsigned short *wc, *wb, *wph, *wpl;
    float* bias4k;
    cudaGetSymbolAddress((void**)&xh, g_xh);     cudaGetSymbolAddress((void**)&xl, g_xl);
    cudaGetSymbolAddress((void**)&yh, g_yh);     cudaGetSymbolAddress((void**)&yl, g_yl);
    cudaGetSymbolAddress((void**)&qkvh, g_qkvh); cudaGetSymbolAddress((void**)&qkvl, g_qkvl);
    cudaGetSymbolAddress((void**)&kv2h, g_kv2h);
    cudaGetSymbolAddress((void**)&cath, g_cath);
    cudaGetSymbolAddress((void**)&wc, g_wc_h);
    cudaGetSymbolAddress((void**)&wb, g_w2b_h);
    cudaGetSymbolAddress((void**)&wph, g_wpj_h); cudaGetSymbolAddress((void**)&wpl, g_wpj_l);
    cudaGetSymbolAddress((void**)&bias4k, g_bias4k);

    const int SMEM_G = 6 * TS * 2;                    // 61440 B
    const int SMEM_ATTN = 6 * QB * 2 + 2 * 64 * 4;    // 55808 B
    cudaFuncSetAttribute((const void*)gemm_mma<0>,    cudaFuncAttributeMaxDynamicSharedMemorySize, SMEM_G);
    cudaFuncSetAttribute((const void*)gemm_mma<1>,    cudaFuncAttributeMaxDynamicSharedMemorySize, SMEM_G);
    cudaFuncSetAttribute((const void*)gemm_mma<2>,    cudaFuncAttributeMaxDynamicSharedMemorySize, SMEM_G);
    cudaFuncSetAttribute((const void*)attn_self_mma,  cudaFuncAttributeMaxDynamicSharedMemorySize, SMEM_ATTN);
    cudaFuncSetAttribute((const void*)attn_cross_mma, cudaFuncAttributeMaxDynamicSharedMemorySize, SMEM_ATTN);

    lens_kernel<<<1, 256>>>(xtb, in_sizes[11], ytb, in_sizes[15]);
    concat_bias<<<16, 256>>>(b_attn, b_2a, bias4k);

    split_fp32<<<2048, 256>>>(x, xh, xl, 2048 * 1024 / 4);
    split_fp32<<<2048, 256>>>(y, yh, yl, 2048 * 1024 / 4);
    transpose_cvt<<<dim3(96, 32), 256>>>(W_attn, wc, nullptr, 1024, 3072);
    transpose_cvt<<<dim3(32, 32), 256>>>(W_2a, wc + (size_t)3072 * 1024, nullptr, 1024, 1024);
    transpose_cvt<<<dim3(64, 32), 256>>>(W_2b, wb, nullptr, 1024, 2048);
    transpose_cvt<<<dim3(32, 64), 256>>>(W_proj, wph, wpl, 2048, 1024);

    // fused [QKV|Q2] GEMM: [2048, 4096]
    gemm_mma<0><<<dim3(32, 16), 256, SMEM_G>>>(xh, xl, wc, nullptr, bias4k, nullptr, qkvh, qkvl, 2048, 4096, 1024);
    // kv2: hi-only output
    gemm_mma<1><<<dim3(16, 16), 256, SMEM_G>>>(yh, yl, wb, nullptr, b_2b, nullptr, kv2h, nullptr, 2048, 2048, 1024);

    attn_self_mma <<<dim3(16, 16, 2), 128, SMEM_ATTN>>>(qkvh, qkvl, maskx, cath);
    attn_cross_mma<<<dim3(16, 16, 2), 128, SMEM_ATTN>>>(qkvh, qkvl, kv2h, cath);

    // proj: cat (single fp16) x Wproj (hi/lo), fp32 out
    gemm_mma<2><<<dim3(8, 16), 256, SMEM_G>>>(cath, nullptr, wph, wpl, b_proj, (float*)d_out, nullptr, nullptr, 2048, 1024, 2048);
}

// round 9
// speedup vs baseline: 4.4733x; 1.1074x over previous
#include <cuda_runtime.h>
#include <cuda_fp16.h>
#include <cstdint>

#define NB    2
#define SXX   1024
#define SYY   1024
#define DIM   1024
#define NH    16
#define HDIM  64
#define FULLN 1536

// ---------------- scratch (device globals) ----------------
__device__ int   g_lens[4];
__device__ float g_bias4k[4096];

__device__ unsigned short g_xh [2048 * 1024], g_xl [2048 * 1024];
__device__ unsigned short g_yh [2048 * 1024], g_yl [2048 * 1024];
// fused QKV|Q2: cols 0-1023 Q, 1024-2047 K, 2048-3071 V, 3072-4095 Q2
__device__ unsigned short g_qkvh[2048 * 4096], g_qkvl[2048 * 4096];
__device__ unsigned short g_kv2h[2048 * 2048];
__device__ unsigned short g_cath[2048 * 2048];
__device__ unsigned short g_wc_h [4096 * 1024];     // W_attn|W_2a [N,K]
__device__ unsigned short g_w2b_h[2048 * 1024];
__device__ unsigned short g_wpj_h[1024 * 2048], g_wpj_l[1024 * 2048];

// ---------------- helpers ----------------
__device__ __forceinline__ uint32_t smem_u32(const void* p) {
    uint32_t a;
    asm("{ .reg .u64 t; cvta.to.shared.u64 t, %1; cvt.u32.u64 %0, t; }" : "=r"(a) : "l"(p));
    return a;
}
#define CP_ASYNC16(dst, src) \
    asm volatile("cp.async.ca.shared.global [%0], [%1], 16;" :: "r"(dst), "l"(src) : "memory")
#define CP_COMMIT() asm volatile("cp.async.commit_group;" ::: "memory")
#define CP_WAIT1()  asm volatile("cp.async.wait_group 1;" ::: "memory")
#define CP_WAIT0()  asm volatile("cp.async.wait_group 0;" ::: "memory")

#define MMA_F16(c, a0, a1, a2, a3, b0, b1) \
    asm volatile("mma.sync.aligned.m16n8k16.row.col.f32.f16.f16.f32 " \
        "{%0,%1,%2,%3}, {%4,%5,%6,%7}, {%8,%9}, {%0,%1,%2,%3};" \
        : "+f"((c)[0]), "+f"((c)[1]), "+f"((c)[2]), "+f"((c)[3]) \
        : "r"(a0), "r"(a1), "r"(a2), "r"(a3), "r"(b0), "r"(b1))

#define LDSM4(r0, r1, r2, r3, a) \
    asm volatile("ldmatrix.sync.aligned.m8n8.x4.shared.b16 {%0,%1,%2,%3}, [%4];" \
        : "=r"(r0), "=r"(r1), "=r"(r2), "=r"(r3) : "r"(a))
#define LDSM4T(r0, r1, r2, r3, a) \
    asm volatile("ldmatrix.sync.aligned.m8n8.x4.trans.shared.b16 {%0,%1,%2,%3}, [%4];" \
        : "=r"(r0), "=r"(r1), "=r"(r2), "=r"(r3) : "r"(a))

__device__ __forceinline__ void split_pack_h(float a, float b, uint32_t& h, uint32_t& l) {
    __half ha = __float2half_rn(a), hb = __float2half_rn(b);
    __half la = __float2half_rn(a - __half2float(ha));
    __half lb = __float2half_rn(b - __half2float(hb));
    h = (uint32_t)*(unsigned short*)&ha | ((uint32_t)*(unsigned short*)&hb << 16);
    l = (uint32_t)*(unsigned short*)&la | ((uint32_t)*(unsigned short*)&lb << 16);
}
__device__ __forceinline__ uint32_t pack_h2(float a, float b) {
    __half2 v = __floats2half2_rn(a, b);
    return *(uint32_t*)&v;
}

// ---------------- lens + bias concat (one launch) ----------------
__global__ void prep_small(const int* __restrict__ xb, int nx,
                           const int* __restrict__ yb, int ny,
                           const float* __restrict__ ba, const float* __restrict__ b2a,
                           float* __restrict__ bias4k)
{
    if (blockIdx.x == 16) {
        __shared__ int cnt[4];
        int t = threadIdx.x;
        if (t < 4) cnt[t] = 0;
        __syncthreads();
        for (int i = t; i < nx; i += blockDim.x) atomicAdd(&cnt[xb[i]], 1);
        for (int i = t; i < ny; i += blockDim.x) atomicAdd(&cnt[2 + yb[i]], 1);
        __syncthreads();
        if (t < 4) g_lens[t] = cnt[t];
    } else {
        int i = blockIdx.x * 256 + threadIdx.x;
        bias4k[i] = (i < 3072) ? ba[i] : b2a[i - 3072];
    }
}

// ---------------- fp32 -> fp16 hi/lo split, x and y in one launch ----------------
__global__ __launch_bounds__(256)
void split_xy(const float* __restrict__ x, const float* __restrict__ y,
              unsigned short* __restrict__ xh, unsigned short* __restrict__ xl,
              unsigned short* __restrict__ yh, unsigned short* __restrict__ yl)
{
    const int N4 = 2048 * 1024 / 4;
    int i = blockIdx.x * 256 + threadIdx.x;
    const float* in; unsigned short *oh, *ol;
    int j;
    if (i < N4) { in = x; oh = xh; ol = xl; j = i; }
    else        { in = y; oh = yh; ol = yl; j = i - N4; }
    float4 v = ((const float4*)in)[j];
    uint32_t h0, l0, h1, l1;
    split_pack_h(v.x, v.y, h0, l0);
    split_pack_h(v.z, v.w, h1, l1);
    ((uint2*)oh)[j] = make_uint2(h0, h1);
    ((uint2*)ol)[j] = make_uint2(l0, l1);
}

// ---------------- all weight transposes in one launch ----------------
// segments (flat blocks): [0,3072) W_attn 1024x3072 -> wc
//                         [3072,4096) W_2a 1024x1024 -> wc+3072*1024
//                         [4096,6144) W_2b 1024x2048 -> wb
//                         [6144,8192) W_proj 2048x1024 -> wph/wpl (hi/lo)
__global__ __launch_bounds__(256)
void transpose_all(const float* __restrict__ Wa, const float* __restrict__ W2a,
                   const float* __restrict__ W2b, const float* __restrict__ Wp,
                   unsigned short* __restrict__ wc, unsigned short* __restrict__ wb,
                   unsigned short* __restrict__ wph, unsigned short* __restrict__ wpl)
{
    int f = blockIdx.x;
    const float* in; unsigned short *oh, *ol = nullptr;
    int K, N, bx, by;
    if (f < 3072)      { in = Wa;  oh = wc;  K = 1024; N = 3072; f -= 0;    bx = f % 96; by = f / 96; }
    else if (f < 4096) { in = W2a; oh = wc + (size_t)3072 * 1024; K = 1024; N = 1024; f -= 3072; bx = f % 32; by = f / 32; }
    else if (f < 6144) { in = W2b; oh = wb;  K = 1024; N = 2048; f -= 4096; bx = f % 64; by = f / 64; }
    else               { in = Wp;  oh = wph; ol = wpl; K = 2048; N = 1024; f -= 6144; bx = f % 32; by = f / 32; }

    __shared__ float tile[32][33];
    int n0 = bx << 5, k0 = by << 5;
    int tx = threadIdx.x & 31, ty = threadIdx.x >> 5;
    for (int i = ty; i < 32; i += 8)
        tile[i][tx] = in[(size_t)(k0 + i) * N + n0 + tx];
    __syncthreads();
    for (int i = ty; i < 32; i += 8) {
        float v = tile[tx][i];
        __half h = __float2half_rn(v);
        size_t o = (size_t)(n0 + i) * K + k0 + tx;
        oh[o] = *(unsigned short*)&h;
        if (ol) {
            __half l = __float2half_rn(v - __half2float(h));
            ol[o] = *(unsigned short*)&l;
        }
    }
}

// ---------------- front GEMMs fused: (qkv|q2) + kv2, one flat grid ----------------
// C = (Ah+Al)·Bh, K=1024.  blocks [0,512): problem 0 (N=4096, hi/lo out);
//                          [512,768): problem 1 (N=2048, hi out).
#define TS   (128 * 40)
__global__ __launch_bounds__(256)
void gemm_front(const unsigned short* __restrict__ xh, const unsigned short* __restrict__ xl,
                const unsigned short* __restrict__ yh, const unsigned short* __restrict__ yl,
                const unsigned short* __restrict__ wc, const unsigned short* __restrict__ wb,
                const float* __restrict__ bias4k, const float* __restrict__ b2b,
                unsigned short* __restrict__ qkvh, unsigned short* __restrict__ qkvl,
                unsigned short* __restrict__ kv2h)
{
    extern __shared__ unsigned short sm16[];
    unsigned short* sAh = sm16;
    unsigned short* sAl = sm16 + 2 * TS;
    unsigned short* sBh = sm16 + 4 * TS;
    const uint32_t uAh = smem_u32(sAh), uAl = smem_u32(sAl), uBh = smem_u32(sBh);

    const int bid = blockIdx.x;
    const unsigned short *Ah, *Al, *Bh;
    const float* bias;
    unsigned short *Ch, *Cl;
    int bm, bn, N;
    if (bid < 512) {
        bm = (bid >> 5) << 7; bn = (bid & 31) << 7; N = 4096;
        Ah = xh; Al = xl; Bh = wc; bias = bias4k; Ch = qkvh; Cl = qkvl;
    } else {
        int i = bid - 512;
        bm = (i >> 4) << 7; bn = (i & 15) << 7; N = 2048;
        Ah = yh; Al = yl; Bh = wb; bias = b2b; Ch = kv2h; Cl = nullptr;
    }
    const int K = 1024;

    const int tid  = threadIdx.x;
    const int lane = tid & 31, wid = tid >> 5;
    const int wm = (wid >> 2) << 6;
    const int wn = (wid & 3) << 5;

    float acc[4][4][4];
#pragma unroll
    for (int i = 0; i < 4; i++)
#pragma unroll
        for (int j = 0; j < 4; j++)
#pragma unroll
            for (int k = 0; k < 4; k++) acc[i][j][k] = 0.f;

    const int lr = tid >> 2;
    const int ls = tid & 3;
    const int nchunk = K >> 5;

#define PREFETCH_F(t) do { \
        int buf_ = (t) & 1; \
        int k0_  = (t) << 5; \
        _Pragma("unroll") \
        for (int p_ = 0; p_ < 2; p_++) { \
            int row_ = lr + (p_ << 6); \
            uint32_t so_ = (uint32_t)(buf_ * TS + row_ * 40 + ls * 8) * 2; \
            size_t ao_ = (size_t)(bm + row_) * K + k0_ + ls * 8; \
            size_t bo_ = (size_t)(bn + row_) * K + k0_ + ls * 8; \
            CP_ASYNC16(uAh + so_, Ah + ao_); \
            CP_ASYNC16(uAl + so_, Al + ao_); \
            CP_ASYNC16(uBh + so_, Bh + bo_); \
        } \
    } while (0)

    PREFETCH_F(0);
    CP_COMMIT();

    const int l8 = lane & 7, g = lane >> 3;
    uint32_t aoff[4], boff[2];
#pragma unroll
    for (int mi = 0; mi < 4; mi++)
        aoff[mi] = (uint32_t)((wm + (mi << 4) + ((g & 1) << 3) + l8) * 40 + ((g >> 1) << 3)) * 2;
#pragma unroll
    for (int p = 0; p < 2; p++)
        boff[p] = (uint32_t)((wn + (p << 4) + ((g >> 1) << 3) + l8) * 40 + ((g & 1) << 3)) * 2;

    const int fr = lane >> 2;
    const int fc = (lane & 3) << 1;

    for (int t = 0; t < nchunk; t++) {
        if (t + 1 < nchunk) { PREFETCH_F(t + 1); CP_COMMIT(); CP_WAIT1(); }
        else                { CP_WAIT0(); }
        __syncthreads();
        const uint32_t bufB = (uint32_t)(t & 1) * (TS * 2);
#pragma unroll
        for (int kk = 0; kk < 2; kk++) {
            const uint32_t kof = bufB + (kk << 5);
            uint32_t bh[2][4];
#pragma unroll
            for (int p = 0; p < 2; p++)
                LDSM4(bh[p][0], bh[p][1], bh[p][2], bh[p][3], uBh + kof + boff[p]);
#pragma unroll
            for (int mi = 0; mi < 4; mi++) {
                uint32_t ah0, ah1, ah2, ah3, al0, al1, al2, al3;
                LDSM4(ah0, ah1, ah2, ah3, uAh + kof + aoff[mi]);
                LDSM4(al0, al1, al2, al3, uAl + kof + aoff[mi]);
#pragma unroll
                for (int p = 0; p < 2; p++) {
                    MMA_F16(acc[mi][2*p],   ah0, ah1, ah2, ah3, bh[p][0], bh[p][1]);
                    MMA_F16(acc[mi][2*p],   al0, al1, al2, al3, bh[p][0], bh[p][1]);
                    MMA_F16(acc[mi][2*p+1], ah0, ah1, ah2, ah3, bh[p][2], bh[p][3]);
                    MMA_F16(acc[mi][2*p+1], al0, al1, al2, al3, bh[p][2], bh[p][3]);
                }
            }
        }
        __syncthreads();
    }

    if (Cl) {
#pragma unroll
        for (int mi = 0; mi < 4; mi++) {
            int row = bm + wm + (mi << 4) + fr;
#pragma unroll
            for (int ni = 0; ni < 4; ni++) {
                int col = bn + wn + (ni << 3) + fc;
                float bx = bias[col], by = bias[col + 1];
                uint32_t hh, ll;
                split_pack_h(acc[mi][ni][0] + bx, acc[mi][ni][1] + by, hh, ll);
                *(uint32_t*)&Ch[(size_t)row * N + col] = hh;
                *(uint32_t*)&Cl[(size_t)row * N + col] = ll;
                split_pack_h(acc[mi][ni][2] + bx, acc[mi][ni][3] + by, hh, ll);
                *(uint32_t*)&Ch[(size_t)(row + 8) * N + col] = hh;
                *(uint32_t*)&Cl[(size_t)(row + 8) * N + col] = ll;
            }
        }
    } else {
#pragma unroll
        for (int mi = 0; mi < 4; mi++) {
            int row = bm + wm + (mi << 4) + fr;
#pragma unroll
            for (int ni = 0; ni < 4; ni++) {
                int col = bn + wn + (ni << 3) + fc;
                float bx = bias[col], by = bias[col + 1];
                *(uint32_t*)&Ch[(size_t)row * N + col] =
                    pack_h2(acc[mi][ni][0] + bx, acc[mi][ni][1] + by);
                *(uint32_t*)&Ch[(size_t)(row + 8) * N + col] =
                    pack_h2(acc[mi][ni][2] + bx, acc[mi][ni][3] + by);
            }
        }
    }
}

// ---------------- proj GEMM: C = Ah·(Bh+Bl), fp32 out ----------------
__global__ __launch_bounds__(256)
void gemm_proj(const unsigned short* __restrict__ Ah,
               const unsigned short* __restrict__ Bh, const unsigned short* __restrict__ Bl,
               const float* __restrict__ bias, float* __restrict__ Cf,
               int M, int N, int K)
{
    extern __shared__ unsigned short sm16[];
    unsigned short* sAh = sm16;
    unsigned short* sBl = sm16 + 2 * TS;
    unsigned short* sBh = sm16 + 4 * TS;
    const uint32_t uAh = smem_u32(sAh), uBl = smem_u32(sBl), uBh = smem_u32(sBh);

    const int tid  = threadIdx.x;
    const int lane = tid & 31, wid = tid >> 5;
    const int wm = (wid >> 2) << 6;
    const int wn = (wid & 3) << 5;
    const int bm = blockIdx.y << 7, bn = blockIdx.x << 7;

    float acc[4][4][4];
#pragma unroll
    for (int i = 0; i < 4; i++)
#pragma unroll
        for (int j = 0; j < 4; j++)
#pragma unroll
            for (int k = 0; k < 4; k++) acc[i][j][k] = 0.f;

    const int lr = tid >> 2;
    const int ls = tid & 3;
    const int nchunk = K >> 5;

#define PREFETCH_P(t) do { \
        int buf_ = (t) & 1; \
        int k0_  = (t) << 5; \
        _Pragma("unroll") \
        for (int p_ = 0; p_ < 2; p_++) { \
            int row_ = lr + (p_ << 6); \
            uint32_t so_ = (uint32_t)(buf_ * TS + row_ * 40 + ls * 8) * 2; \
            size_t ao_ = (size_t)(bm + row_) * K + k0_ + ls * 8; \
            size_t bo_ = (size_t)(bn + row_) * K + k0_ + ls * 8; \
            CP_ASYNC16(uAh + so_, Ah + ao_); \
            CP_ASYNC16(uBh + so_, Bh + bo_); \
            CP_ASYNC16(uBl + so_, Bl + bo_); \
        } \
    } while (0)

    PREFETCH_P(0);
    CP_COMMIT();

    const int l8 = lane & 7, g = lane >> 3;
    uint32_t aoff[4], boff[2];
#pragma unroll
    for (int mi = 0; mi < 4; mi++)
        aoff[mi] = (uint32_t)((wm + (mi << 4) + ((g & 1) << 3) + l8) * 40 + ((g >> 1) << 3)) * 2;
#pragma unroll
    for (int p = 0; p < 2; p++)
        boff[p] = (uint32_t)((wn + (p << 4) + ((g >> 1) << 3) + l8) * 40 + ((g & 1) << 3)) * 2;

    const int fr = lane >> 2;
    const int fc = (lane & 3) << 1;

    for (int t = 0; t < nchunk; t++) {
        if (t + 1 < nchunk) { PREFETCH_P(t + 1); CP_COMMIT(); CP_WAIT1(); }
        else                { CP_WAIT0(); }
        __syncthreads();
        const uint32_t bufB = (uint32_t)(t & 1) * (TS * 2);
#pragma unroll
        for (int kk = 0; kk < 2; kk++) {
            const uint32_t kof = bufB + (kk << 5);
            uint32_t bh[2][4], bl[2][4];
#pragma unroll
            for (int p = 0; p < 2; p++) {
                LDSM4(bh[p][0], bh[p][1], bh[p][2], bh[p][3], uBh + kof + boff[p]);
                LDSM4(bl[p][0], bl[p][1], bl[p][2], bl[p][3], uBl + kof + boff[p]);
            }
#pragma unroll
            for (int mi = 0; mi < 4; mi++) {
                uint32_t ah0, ah1, ah2, ah3;
                LDSM4(ah0, ah1, ah2, ah3, uAh + kof + aoff[mi]);
#pragma unroll
                for (int p = 0; p < 2; p++) {
                    MMA_F16(acc[mi][2*p],   ah0, ah1, ah2, ah3, bh[p][0], bh[p][1]);
                    MMA_F16(acc[mi][2*p],   ah0, ah1, ah2, ah3, bl[p][0], bl[p][1]);
                    MMA_F16(acc[mi][2*p+1], ah0, ah1, ah2, ah3, bh[p][2], bh[p][3]);
                    MMA_F16(acc[mi][2*p+1], ah0, ah1, ah2, ah3, bl[p][2], bl[p][3]);
                }
            }
        }
        __syncthreads();
    }

#pragma unroll
    for (int mi = 0; mi < 4; mi++) {
        int row = bm + wm + (mi << 4) + fr;
#pragma unroll
        for (int ni = 0; ni < 4; ni++) {
            int col = bn + wn + (ni << 3) + fc;
            float bx = bias[col], by = bias[col + 1];
            float2 v0 = { acc[mi][ni][0] + bx, acc[mi][ni][1] + by };
            float2 v1 = { acc[mi][ni][2] + bx, acc[mi][ni][3] + by };
            *(float2*)(Cf + (size_t)row * N + col)       = v0;
            *(float2*)(Cf + (size_t)(row + 8) * N + col) = v1;
        }
    }
}

// ================= fused MMA flash attention (self + cross in one launch) =================
#define AST 72
#define QB  (64 * AST)
#define KVB (QB * 2)
#define QSTRIDE 4096

__global__ __launch_bounds__(128)
void attn_fused(const unsigned short* __restrict__ qkvh,
                const unsigned short* __restrict__ qkvl,
                const unsigned short* __restrict__ kvh,
                const float* __restrict__ mask,
                unsigned short* __restrict__ cath)
{
    extern __shared__ char smraw[];
    unsigned short* sQh = (unsigned short*)smraw;
    unsigned short* sQl = sQh + QB;
    unsigned short* sK  = sQl + QB;
    unsigned short* sV  = sK  + 2 * QB;
    float* sMsf = (float*)(sV + 2 * QB);
    const uint32_t uQh = smem_u32(sQh), uQl = smem_u32(sQl);
    const uint32_t uK = smem_u32(sK), uV = smem_u32(sV);
    const uint32_t uMs = smem_u32(sMsf);

    const int bx = blockIdx.x;               // 0..31
    const bool is_self = bx < 16;
    const int qt = is_self ? (15 - bx) : (31 - bx);   // long CTAs first
    const int h = blockIdx.y, b = blockIdx.z;
    const int tid = threadIdx.x, lane = tid & 31, wid = tid >> 5;
    const int q0 = wid << 4;
    const int r = lane >> 2, cq = (lane & 3) << 1;
    const int l8 = lane & 7, g = lane >> 3;

    const int lenx = g_lens[b], leny = g_lens[2 + b];

    // fragment base offsets (shared by both paths)
    uint32_t qfo = (uint32_t)((q0 + ((g & 1) << 3) + l8) * AST + ((g >> 1) << 3)) * 2;
    uint32_t kfo[4], vfo[4];
#pragma unroll
    for (int p = 0; p < 4; p++) {
        kfo[p] = (uint32_t)(((p << 4) + ((g >> 1) << 3) + l8) * AST + ((g & 1) << 3)) * 2;
        vfo[p] = (uint32_t)((((g & 1) << 3) + l8) * AST + (((p << 1) + (g >> 1)) << 3)) * 2;
    }

    float o[8][4];
#pragma unroll
    for (int i = 0; i < 8; i++)
#pragma unroll
        for (int j = 0; j < 4; j++) o[i][j] = 0.f;
    float mrow0 = -1e30f, mrow1 = -1e30f, lrow0 = 0.f, lrow1 = 0.f;

    if (is_self) {
        // ---------------- self attention ----------------
        const size_t gb = (size_t)b * SXX * QSTRIDE;
        for (int i = tid; i < 512; i += 128) {
            int rr = i >> 3, seg = i & 7;
            size_t src = gb + (size_t)(qt * 64 + rr) * QSTRIDE + h * 64 + seg * 8;
            *(uint4*)&sQh[rr * AST + seg * 8] = *(const uint4*)&qkvh[src];
            *(uint4*)&sQl[rr * AST + seg * 8] = *(const uint4*)&qkvl[src];
        }

        const float* maskb = mask + b * SXX;
        int nt1 = qt + 1, nt2 = (lenx + 63) >> 6;
        const int ntile = nt1 < nt2 ? nt1 : nt2;

#define APREF_SELF(t) do { \
        uint32_t kd_ = uK + (uint32_t)((t) & 1) * KVB; \
        uint32_t vd_ = uV + (uint32_t)((t) & 1) * KVB; \
        _Pragma("unroll") \
        for (int it_ = 0; it_ < 4; it_++) { \
            int i_ = tid + it_ * 128; \
            int rr_ = i_ >> 3, sg_ = i_ & 7; \
            size_t kr_ = gb + (size_t)((t) * 64 + rr_) * QSTRIDE + 1024 + h * 64 + sg_ * 8; \
            uint32_t so_ = (uint32_t)(rr_ * AST + sg_ * 8) * 2; \
            CP_ASYNC16(kd_ + so_, qkvh + kr_); \
            CP_ASYNC16(vd_ + so_, qkvh + kr_ + 1024); \
        } \
        if (tid < 16) CP_ASYNC16(uMs + ((t) & 1) * 256 + tid * 16, maskb + (t) * 64 + tid * 4); \
    } while (0)

        APREF_SELF(0);
        CP_COMMIT();

        for (int t = 0; t < ntile; t++) {
            if (t + 1 < ntile) { APREF_SELF(t + 1); CP_COMMIT(); CP_WAIT1(); }
            else               { CP_WAIT0(); }
            __syncthreads();
            const uint32_t kb = (uint32_t)(t & 1) * KVB;
            const int mb = (t & 1) * 64;

            float sc[8][4];
#pragma unroll
            for (int i = 0; i < 8; i++)
#pragma unroll
                for (int j = 0; j < 4; j++) sc[i][j] = 0.f;

#pragma unroll
            for (int kt = 0; kt < 4; kt++) {
                const uint32_t ko = (uint32_t)(kt << 5);
                uint32_t ah0, ah1, ah2, ah3, al0, al1, al2, al3;
                LDSM4(ah0, ah1, ah2, ah3, uQh + qfo + ko);
                LDSM4(al0, al1, al2, al3, uQl + qfo + ko);
#pragma unroll
                for (int p = 0; p < 4; p++) {
                    uint32_t k0r, k1r, k2r, k3r;
                    LDSM4(k0r, k1r, k2r, k3r, uK + kb + kfo[p] + ko);
                    MMA_F16(sc[2*p],   ah0, ah1, ah2, ah3, k0r, k1r);
                    MMA_F16(sc[2*p],   al0, al1, al2, al3, k0r, k1r);
                    MMA_F16(sc[2*p+1], ah0, ah1, ah2, ah3, k2r, k3r);
                    MMA_F16(sc[2*p+1], al0, al1, al2, al3, k2r, k3r);
                }
            }

            const int grow = qt * 64 + q0 + r;
#pragma unroll
            for (int nt = 0; nt < 8; nt++) {
                int c0 = t * 64 + nt * 8 + cq;
                float m0 = sMsf[mb + nt * 8 + cq], m1 = sMsf[mb + nt * 8 + cq + 1];
                float v;
                v = sc[nt][0] * 0.125f; sc[nt][0] = ((c0     <= grow    ) ? v : -10000.f) + m0;
                v = sc[nt][1] * 0.125f; sc[nt][1] = ((c0 + 1 <= grow    ) ? v : -10000.f) + m1;
                v = sc[nt][2] * 0.125f; sc[nt][2] = ((c0     <= grow + 8) ? v : -10000.f) + m0;
                v = sc[nt][3] * 0.125f; sc[nt][3] = ((c0 + 1 <= grow + 8) ? v : -10000.f) + m1;
            }

            float mx0 = -1e30f, mx1 = -1e30f;
#pragma unroll
            for (int nt = 0; nt < 8; nt++) {
                mx0 = fmaxf(mx0, fmaxf(sc[nt][0], sc[nt][1]));
                mx1 = fmaxf(mx1, fmaxf(sc[nt][2], sc[nt][3]));
            }
            mx0 = fmaxf(mx0, __shfl_xor_sync(0xffffffffu, mx0, 1));
            mx0 = fmaxf(mx0, __shfl_xor_sync(0xffffffffu, mx0, 2));
            mx1 = fmaxf(mx1, __shfl_xor_sync(0xffffffffu, mx1, 1));
            mx1 = fmaxf(mx1, __shfl_xor_sync(0xffffffffu, mx1, 2));
            float mn0 = fmaxf(mrow0, mx0), mn1 = fmaxf(mrow1, mx1);
            float al0f = __expf(mrow0 - mn0), al1f = __expf(mrow1 - mn1);
            float s0 = 0.f, s1 = 0.f;
#pragma unroll
            for (int nt = 0; nt < 8; nt++) {
                sc[nt][0] = __expf(sc[nt][0] - mn0); s0 += sc[nt][0];
                sc[nt][1] = __expf(sc[nt][1] - mn0); s0 += sc[nt][1];
                sc[nt][2] = __expf(sc[nt][2] - mn1); s1 += sc[nt][2];
                sc[nt][3] = __expf(sc[nt][3] - mn1); s1 += sc[nt][3];
            }
            s0 += __shfl_xor_sync(0xffffffffu, s0, 1);
            s0 += __shfl_xor_sync(0xffffffffu, s0, 2);
            s1 += __shfl_xor_sync(0xffffffffu, s1, 1);
            s1 += __shfl_xor_sync(0xffffffffu, s1, 2);
            lrow0 = lrow0 * al0f + s0; mrow0 = mn0;
            lrow1 = lrow1 * al1f + s1; mrow1 = mn1;
#pragma unroll
            for (int nt = 0; nt < 8; nt++) {
                o[nt][0] *= al0f; o[nt][1] *= al0f;
                o[nt][2] *= al1f; o[nt][3] *= al1f;
            }

#pragma unroll
            for (int kc = 0; kc < 4; kc++) {
                uint32_t ph[4], pl[4];
                split_pack_h(sc[2*kc][0],   sc[2*kc][1],   ph[0], pl[0]);
                split_pack_h(sc[2*kc][2],   sc[2*kc][3],   ph[1], pl[1]);
                split_pack_h(sc[2*kc+1][0], sc[2*kc+1][1], ph[2], pl[2]);
                split_pack_h(sc[2*kc+1][2], sc[2*kc+1][3], ph[3], pl[3]);
                const uint32_t vrow = kb + (uint32_t)(kc * 16 * AST) * 2;
#pragma unroll
                for (int p = 0; p < 4; p++) {
                    uint32_t v0r, v1r, v2r, v3r;
                    LDSM4T(v0r, v1r, v2r, v3r, uV + vrow + vfo[p]);
                    MMA_F16(o[2*p],   ph[0], ph[1], ph[2], ph[3], v0r, v1r);
                    MMA_F16(o[2*p],   pl[0], pl[1], pl[2], pl[3], v0r, v1r);
                    MMA_F16(o[2*p+1], ph[0], ph[1], ph[2], ph[3], v2r, v3r);
                    MMA_F16(o[2*p+1], pl[0], pl[1], pl[2], pl[3], v2r, v3r);
                }
            }
            __syncthreads();
        }

        float i0 = 1.f / lrow0, i1 = 1.f / lrow1;
        size_t ob = (size_t)b * SXX * 2048 + (size_t)(qt * 64 + q0 + r) * 2048 + h * 64;
#pragma unroll
        for (int dn = 0; dn < 8; dn++) {
            *(uint32_t*)&cath[ob + dn * 8 + cq] = pack_h2(o[dn][0] * i0, o[dn][1] * i0);
            *(uint32_t*)&cath[ob + (size_t)8 * 2048 + dn * 8 + cq] = pack_h2(o[dn][2] * i1, o[dn][3] * i1);
        }
    } else {
        // ---------------- cross attention ----------------
        const int off = FULLN - lenx;
        size_t obase = (size_t)b * SXX * 2048 + (size_t)(qt * 64) * 2048 + 1024 + h * 64;
        if (qt * 64 >= lenx) {
            const uint4 z = {0, 0, 0, 0};
            for (int i = tid; i < 512; i += 128) {
                int rr = i >> 3, seg = i & 7;
                *(uint4*)&cath[obase + (size_t)rr * 2048 + seg * 8] = z;
            }
            return;
        }

        const size_t qgb = (size_t)b * SXX * QSTRIDE;
        for (int i = tid; i < 512; i += 128) {
            int rr = i >> 3, seg = i & 7;
            size_t src = qgb + (size_t)(qt * 64 + rr) * QSTRIDE + 3072 + h * 64 + seg * 8;
            *(uint4*)&sQh[rr * AST + seg * 8] = *(const uint4*)&qkvh[src];
            *(uint4*)&sQl[rr * AST + seg * 8] = *(const uint4*)&qkvl[src];
        }

        int qlast = qt * 64 + 63;
        if (qlast >= lenx) qlast = lenx - 1;
        int jmax = off + qlast + 1;
        if (jmax > leny) jmax = leny;
        const int ntile = (jmax + 63) >> 6;
        const size_t kgb = (size_t)b * SYY * 2048;

#define APREF_CROSS(t) do { \
        uint32_t kd_ = uK + (uint32_t)((t) & 1) * KVB; \
        uint32_t vd_ = uV + (uint32_t)((t) & 1) * KVB; \
        _Pragma("unroll") \
        for (int it_ = 0; it_ < 4; it_++) { \
            int i_ = tid + it_ * 128; \
            int rr_ = i_ >> 3, sg_ = i_ & 7; \
            size_t kr_ = kgb + (size_t)((t) * 64 + rr_) * 2048 + h * 64 + sg_ * 8; \
            uint32_t so_ = (uint32_t)(rr_ * AST + sg_ * 8) * 2; \
            CP_ASYNC16(kd_ + so_, kvh + kr_); \
            CP_ASYNC16(vd_ + so_, kvh + kr_ + 1024); \
        } \
    } while (0)

        APREF_CROSS(0);
        CP_COMMIT();

        for (int t = 0; t < ntile; t++) {
            if (t + 1 < ntile) { APREF_CROSS(t + 1); CP_COMMIT(); CP_WAIT1(); }
            else               { CP_WAIT0(); }
            __syncthreads();
            const uint32_t kb = (uint32_t)(t & 1) * KVB;

            float sc[8][4];
#pragma unroll
            for (int i = 0; i < 8; i++)
#pragma unroll
                for (int j = 0; j < 4; j++) sc[i][j] = 0.f;

#pragma unroll
            for (int kt = 0; kt < 4; kt++) {
                const uint32_t ko = (uint32_t)(kt << 5);
                uint32_t ah0, ah1, ah2, ah3, al0, al1, al2, al3;
                LDSM4(ah0, ah1, ah2, ah3, uQh + qfo + ko);
                LDSM4(al0, al1, al2, al3, uQl + qfo + ko);
#pragma unroll
                for (int p = 0; p < 4; p++) {
                    uint32_t k0r, k1r, k2r, k3r;
                    LDSM4(k0r, k1r, k2r, k3r, uK + kb + kfo[p] + ko);
                    MMA_F16(sc[2*p],   ah0, ah1, ah2, ah3, k0r, k1r);
                    MMA_F16(sc[2*p],   al0, al1, al2, al3, k0r, k1r);
                    MMA_F16(sc[2*p+1], ah0, ah1, ah2, ah3, k2r, k3r);
                    MMA_F16(sc[2*p+1], al0, al1, al2, al3, k2r, k3r);
                }
            }

            const int grow = off + qt * 64 + q0 + r;
#pragma unroll
            for (int nt = 0; nt < 8; nt++) {
                int c0 = t * 64 + nt * 8 + cq;
                sc[nt][0] = (c0     <= grow     && c0     < leny) ? sc[nt][0] * 0.125f : -1e30f;
                sc[nt][1] = (c0 + 1 <= grow     && c0 + 1 < leny) ? sc[nt][1] * 0.125f : -1e30f;
                sc[nt][2] = (c0     <= grow + 8 && c0     < leny) ? sc[nt][2] * 0.125f : -1e30f;
                sc[nt][3] = (c0 + 1 <= grow + 8 && c0 + 1 < leny) ? sc[nt][3] * 0.125f : -1e30f;
            }

            float mx0 = -1e30f, mx1 = -1e30f;
#pragma unroll
            for (int nt = 0; nt < 8; nt++) {
                mx0 = fmaxf(mx0, fmaxf(sc[nt][0], sc[nt][1]));
                mx1 = fmaxf(mx1, fmaxf(sc[nt][2], sc[nt][3]));
            }
            mx0 = fmaxf(mx0, __shfl_xor_sync(0xffffffffu, mx0, 1));
            mx0 = fmaxf(mx0, __shfl_xor_sync(0xffffffffu, mx0, 2));
            mx1 = fmaxf(mx1, __shfl_xor_sync(0xffffffffu, mx1, 1));
            mx1 = fmaxf(mx1, __shfl_xor_sync(0xffffffffu, mx1, 2));
            float mn0 = fmaxf(mrow0, mx0), mn1 = fmaxf(mrow1, mx1);
            float al0f = __expf(mrow0 - mn0), al1f = __expf(mrow1 - mn1);
            float s0 = 0.f, s1 = 0.f;
#pragma unroll
            for (int nt = 0; nt < 8; nt++) {
                sc[nt][0] = __expf(sc[nt][0] - mn0); s0 += sc[nt][0];
                sc[nt][1] = __expf(sc[nt][1] - mn0); s0 += sc[nt][1];
                sc[nt][2] = __expf(sc[nt][2] - mn1); s1 += sc[nt][2];
                sc[nt][3] = __expf(sc[nt][3] - mn1); s1 += sc[nt][3];
            }
            s0 += __shfl_xor_sync(0xffffffffu, s0, 1);
            s0 += __shfl_xor_sync(0xffffffffu, s0, 2);
            s1 += __shfl_xor_sync(0xffffffffu, s1, 1);
            s1 += __shfl_xor_sync(0xffffffffu, s1, 2);
            lrow0 = lrow0 * al0f + s0; mrow0 = mn0;
            lrow1 = lrow1 * al1f + s1; mrow1 = mn1;
#pragma unroll
            for (int nt = 0; nt < 8; nt++) {
                o[nt][0] *= al0f; o[nt][1] *= al0f;
                o[nt][2] *= al1f; o[nt][3] *= al1f;
            }

#pragma unroll
            for (int kc = 0; kc < 4; kc++) {
                uint32_t ph[4], pl[4];
                split_pack_h(sc[2*kc][0],   sc[2*kc][1],   ph[0], pl[0]);
                split_pack_h(sc[2*kc][2],   sc[2*kc][3],   ph[1], pl[1]);
                split_pack_h(sc[2*kc+1][0], sc[2*kc+1][1], ph[2], pl[2]);
                split_pack_h(sc[2*kc+1][2], sc[2*kc+1][3], ph[3], pl[3]);
                const uint32_t vrow = kb + (uint32_t)(kc * 16 * AST) * 2;
#pragma unroll
                for (int p = 0; p < 4; p++) {
                    uint32_t v0r, v1r, v2r, v3r;
                    LDSM4T(v0r, v1r, v2r, v3r, uV + vrow + vfo[p]);
                    MMA_F16(o[2*p],   ph[0], ph[1], ph[2], ph[3], v0r, v1r);
                    MMA_F16(o[2*p],   pl[0], pl[1], pl[2], pl[3], v0r, v1r);
                    MMA_F16(o[2*p+1], ph[0], ph[1], ph[2], ph[3], v2r, v3r);
                    MMA_F16(o[2*p+1], pl[0], pl[1], pl[2], pl[3], v2r, v3r);
                }
            }
            __syncthreads();
        }

        float i0 = 1.f / lrow0, i1 = 1.f / lrow1;
        int row0 = qt * 64 + q0 + r, row1 = row0 + 8;
        bool v0 = row0 < lenx, v1 = row1 < lenx;
        size_t ob = (size_t)b * SXX * 2048 + (size_t)row0 * 2048 + 1024 + h * 64;
#pragma unroll
        for (int dn = 0; dn < 8; dn++) {
            *(uint32_t*)&cath[ob + dn * 8 + cq] =
                v0 ? pack_h2(o[dn][0] * i0, o[dn][1] * i0) : 0u;
            *(uint32_t*)&cath[ob + (size_t)8 * 2048 + dn * 8 + cq] =
                v1 ? pack_h2(o[dn][2] * i1, o[dn][3] * i1) : 0u;
        }
    }
}

// ---------------- launch ----------------
extern "C" void kernel_launch(void* const* d_in, const int* in_sizes, int n_in,
                              void* d_out, int out_size)
{
    const float* x      = (const float*)d_in[0];
    const float* y      = (const float*)d_in[1];
    const float* maskx  = (const float*)d_in[2];
    const float* W_attn = (const float*)d_in[3];
    const float* b_attn = (const float*)d_in[4];
    const float* W_2a   = (const float*)d_in[5];
    const float* b_2a   = (const float*)d_in[6];
    const float* W_2b   = (const float*)d_in[7];
    const float* b_2b   = (const float*)d_in[8];
    const float* W_proj = (const float*)d_in[9];
    const float* b_proj = (const float*)d_in[10];
    const int*   xtb    = (const int*)d_in[11];
    const int*   ytb    = (const int*)d_in[15];

    unsigned short *xh, *xl, *yh, *yl;
    unsigned short *qkvh, *qkvl, *kv2h, *cath;
    unsigned short *wc, *wb, *wph, *wpl;
    float* bias4k;
    cudaGetSymbolAddress((void**)&xh, g_xh);     cudaGetSymbolAddress((void**)&xl, g_xl);
    cudaGetSymbolAddress((void**)&yh, g_yh);     cudaGetSymbolAddress((void**)&yl, g_yl);
    cudaGetSymbolAddress((void**)&qkvh, g_qkvh); cudaGetSymbolAddress((void**)&qkvl, g_qkvl);
    cudaGetSymbolAddress((void**)&kv2h, g_kv2h);
    cudaGetSymbolAddress((void**)&cath, g_cath);
    cudaGetSymbolAddress((void**)&wc, g_wc_h);
    cudaGetSymbolAddress((void**)&wb, g_w2b_h);
    cudaGetSymbolAddress((void**)&wph, g_wpj_h); cudaGetSymbolAddress((void**)&wpl, g_wpj_l);
    cudaGetSymbolAddress((void**)&bias4k, g_bias4k);

    const int SMEM_G = 6 * TS * 2;                    // 61440 B
    const int SMEM_ATTN = 6 * QB * 2 + 2 * 64 * 4;    // 55808 B
    cudaFuncSetAttribute((const void*)gemm_front, cudaFuncAttributeMaxDynamicSharedMemorySize, SMEM_G);
    cudaFuncSetAttribute((const void*)gemm_proj,  cudaFuncAttributeMaxDynamicSharedMemorySize, SMEM_G);
    cudaFuncSetAttribute((const void*)attn_fused, cudaFuncAttributeMaxDynamicSharedMemorySize, SMEM_ATTN);

    prep_small<<<17, 256>>>(xtb, in_sizes[11], ytb, in_sizes[15], b_attn, b_2a, bias4k);
    split_xy<<<4096, 256>>>(x, y, xh, xl, yh, yl);
    transpose_all<<<8192, 256>>>(W_attn, W_2a, W_2b, W_proj, wc, wb, wph, wpl);

    gemm_front<<<768, 256, SMEM_G>>>(xh, xl, yh, yl, wc, wb, bias4k, b_2b, qkvh, qkvl, kv2h);

    attn_fused<<<dim3(32, 16, 2), 128, SMEM_ATTN>>>(qkvh, qkvl, kv2h, maskx, cath);

    gemm_proj<<<dim3(8, 16), 256, SMEM_G>>>(cath, wph, wpl, b_proj, (float*)d_out, 2048, 1024, 2048);
}

// round 10
// speedup vs baseline: 4.5798x; 1.0238x over previous
#include <cuda_runtime.h>
#include <cuda_fp16.h>
#include <cstdint>

#define NB    2
#define SXX   1024
#define SYY   1024
#define DIM   1024
#define NH    16
#define HDIM  64
#define FULLN 1536

// ---------------- scratch (device globals) ----------------
__device__ int   g_lens[4];
__device__ float g_bias4k[4096];

__device__ unsigned short g_xh [2048 * 1024], g_xl [2048 * 1024];
__device__ unsigned short g_yh [2048 * 1024], g_yl [2048 * 1024];
// fused QKV|Q2: cols 0-1023 Q, 1024-2047 K, 2048-3071 V, 3072-4095 Q2
__device__ unsigned short g_qkvh[2048 * 4096], g_qkvl[2048 * 4096];
__device__ unsigned short g_kv2h[2048 * 2048];
__device__ unsigned short g_cath[2048 * 2048];
__device__ unsigned short g_wc_h [4096 * 1024];     // W_attn|W_2a [N,K]
__device__ unsigned short g_w2b_h[2048 * 1024];
__device__ unsigned short g_wpj_h[1024 * 2048], g_wpj_l[1024 * 2048];

// ---------------- helpers ----------------
__device__ __forceinline__ uint32_t smem_u32(const void* p) {
    uint32_t a;
    asm("{ .reg .u64 t; cvta.to.shared.u64 t, %1; cvt.u32.u64 %0, t; }" : "=r"(a) : "l"(p));
    return a;
}
#define CP_ASYNC16(dst, src) \
    asm volatile("cp.async.ca.shared.global [%0], [%1], 16;" :: "r"(dst), "l"(src) : "memory")
#define CP_COMMIT() asm volatile("cp.async.commit_group;" ::: "memory")
#define CP_WAIT1()  asm volatile("cp.async.wait_group 1;" ::: "memory")
#define CP_WAIT0()  asm volatile("cp.async.wait_group 0;" ::: "memory")

#define MMA_F16(c, a0, a1, a2, a3, b0, b1) \
    asm volatile("mma.sync.aligned.m16n8k16.row.col.f32.f16.f16.f32 " \
        "{%0,%1,%2,%3}, {%4,%5,%6,%7}, {%8,%9}, {%0,%1,%2,%3};" \
        : "+f"((c)[0]), "+f"((c)[1]), "+f"((c)[2]), "+f"((c)[3]) \
        : "r"(a0), "r"(a1), "r"(a2), "r"(a3), "r"(b0), "r"(b1))

#define LDSM4(r0, r1, r2, r3, a) \
    asm volatile("ldmatrix.sync.aligned.m8n8.x4.shared.b16 {%0,%1,%2,%3}, [%4];" \
        : "=r"(r0), "=r"(r1), "=r"(r2), "=r"(r3) : "r"(a))
#define LDSM4T(r0, r1, r2, r3, a) \
    asm volatile("ldmatrix.sync.aligned.m8n8.x4.trans.shared.b16 {%0,%1,%2,%3}, [%4];" \
        : "=r"(r0), "=r"(r1), "=r"(r2), "=r"(r3) : "r"(a))

__device__ __forceinline__ void split_pack_h(float a, float b, uint32_t& h, uint32_t& l) {
    __half ha = __float2half_rn(a), hb = __float2half_rn(b);
    __half la = __float2half_rn(a - __half2float(ha));
    __half lb = __float2half_rn(b - __half2float(hb));
    h = (uint32_t)*(unsigned short*)&ha | ((uint32_t)*(unsigned short*)&hb << 16);
    l = (uint32_t)*(unsigned short*)&la | ((uint32_t)*(unsigned short*)&lb << 16);
}
__device__ __forceinline__ uint32_t pack_h2(float a, float b) {
    __half2 v = __floats2half2_rn(a, b);
    return *(uint32_t*)&v;
}

// ---------------- lens + bias concat ----------------
__global__ void prep_small(const int* __restrict__ xb, int nx,
                           const int* __restrict__ yb, int ny,
                           const float* __restrict__ ba, const float* __restrict__ b2a,
                           float* __restrict__ bias4k)
{
    if (blockIdx.x == 16) {
        __shared__ int cnt[4];
        int t = threadIdx.x;
        if (t < 4) cnt[t] = 0;
        __syncthreads();
        for (int i = t; i < nx; i += blockDim.x) atomicAdd(&cnt[xb[i]], 1);
        for (int i = t; i < ny; i += blockDim.x) atomicAdd(&cnt[2 + yb[i]], 1);
        __syncthreads();
        if (t < 4) g_lens[t] = cnt[t];
    } else {
        int i = blockIdx.x * 256 + threadIdx.x;
        bias4k[i] = (i < 3072) ? ba[i] : b2a[i - 3072];
    }
}

// ---------------- fp32 -> fp16 hi/lo split (x and y) ----------------
__global__ __launch_bounds__(256)
void split_xy(const float* __restrict__ x, const float* __restrict__ y,
              unsigned short* __restrict__ xh, unsigned short* __restrict__ xl,
              unsigned short* __restrict__ yh, unsigned short* __restrict__ yl)
{
    const int N4 = 2048 * 1024 / 4;
    int i = blockIdx.x * 256 + threadIdx.x;
    const float* in; unsigned short *oh, *ol;
    int j;
    if (i < N4) { in = x; oh = xh; ol = xl; j = i; }
    else        { in = y; oh = yh; ol = yl; j = i - N4; }
    float4 v = ((const float4*)in)[j];
    uint32_t h0, l0, h1, l1;
    split_pack_h(v.x, v.y, h0, l0);
    split_pack_h(v.z, v.w, h1, l1);
    ((uint2*)oh)[j] = make_uint2(h0, h1);
    ((uint2*)ol)[j] = make_uint2(l0, l1);
}

// ---------------- all weight transposes ----------------
__global__ __launch_bounds__(256)
void transpose_all(const float* __restrict__ Wa, const float* __restrict__ W2a,
                   const float* __restrict__ W2b, const float* __restrict__ Wp,
                   unsigned short* __restrict__ wc, unsigned short* __restrict__ wb,
                   unsigned short* __restrict__ wph, unsigned short* __restrict__ wpl)
{
    int f = blockIdx.x;
    const float* in; unsigned short *oh, *ol = nullptr;
    int K, N, bx, by;
    if (f < 3072)      { in = Wa;  oh = wc;  K = 1024; N = 3072; f -= 0;    bx = f % 96; by = f / 96; }
    else if (f < 4096) { in = W2a; oh = wc + (size_t)3072 * 1024; K = 1024; N = 1024; f -= 3072; bx = f % 32; by = f / 32; }
    else if (f < 6144) { in = W2b; oh = wb;  K = 1024; N = 2048; f -= 4096; bx = f % 64; by = f / 64; }
    else               { in = Wp;  oh = wph; ol = wpl; K = 2048; N = 1024; f -= 6144; bx = f % 32; by = f / 32; }

    __shared__ float tile[32][33];
    int n0 = bx << 5, k0 = by << 5;
    int tx = threadIdx.x & 31, ty = threadIdx.x >> 5;
    for (int i = ty; i < 32; i += 8)
        tile[i][tx] = in[(size_t)(k0 + i) * N + n0 + tx];
    __syncthreads();
    for (int i = ty; i < 32; i += 8) {
        float v = tile[tx][i];
        __half h = __float2half_rn(v);
        size_t o = (size_t)(n0 + i) * K + k0 + tx;
        oh[o] = *(unsigned short*)&h;
        if (ol) {
            __half l = __float2half_rn(v - __half2float(h));
            ol[o] = *(unsigned short*)&l;
        }
    }
}

// ---------------- front GEMMs fused, K-chunk 64, stride 72 ----------------
#define TSF (128 * 72)
#define TSB (64 * 72)
__global__ __launch_bounds__(256)
void gemm_front(const unsigned short* __restrict__ xh, const unsigned short* __restrict__ xl,
                const unsigned short* __restrict__ yh, const unsigned short* __restrict__ yl,
                const unsigned short* __restrict__ wc, const unsigned short* __restrict__ wb,
                const float* __restrict__ bias4k, const float* __restrict__ b2b,
                unsigned short* __restrict__ qkvh, unsigned short* __restrict__ qkvl,
                unsigned short* __restrict__ kv2h)
{
    extern __shared__ unsigned short sm16[];
    unsigned short* sAh = sm16;             // [2][TSF]
    unsigned short* sAl = sm16 + 2 * TSF;
    unsigned short* sBh = sm16 + 4 * TSF;
    const uint32_t uAh = smem_u32(sAh), uAl = smem_u32(sAl), uBh = smem_u32(sBh);

    const int bid = blockIdx.x;
    const unsigned short *Ah, *Al, *Bh;
    const float* bias;
    unsigned short *Ch, *Cl;
    int bm, bn, N;
    bool need_lo;
    if (bid < 512) {
        bm = (bid >> 5) << 7; bn = (bid & 31) << 7; N = 4096;
        Ah = xh; Al = xl; Bh = wc; bias = bias4k; Ch = qkvh; Cl = qkvl;
        need_lo = (bn < 1024) || (bn >= 3072);    // K/V lo never read
    } else {
        int i = bid - 512;
        bm = (i >> 4) << 7; bn = (i & 15) << 7; N = 2048;
        Ah = yh; Al = yl; Bh = wb; bias = b2b; Ch = kv2h; Cl = nullptr;
        need_lo = false;
    }
    const int K = 1024;

    const int tid  = threadIdx.x;
    const int lane = tid & 31, wid = tid >> 5;
    const int wm = (wid >> 2) << 6;
    const int wn = (wid & 3) << 5;

    float acc[4][4][4];
#pragma unroll
    for (int i = 0; i < 4; i++)
#pragma unroll
        for (int j = 0; j < 4; j++)
#pragma unroll
            for (int k = 0; k < 4; k++) acc[i][j][k] = 0.f;

    const int nchunk = K >> 6;   // 16

#define PREFETCH_F(t) do { \
        uint32_t st_ = (uint32_t)((t) & 1) * (TSF * 2); \
        int k0_  = (t) << 6; \
        _Pragma("unroll") \
        for (int it_ = 0; it_ < 4; it_++) { \
            int i_ = tid + it_ * 256; \
            int row_ = i_ >> 3, sg_ = i_ & 7; \
            uint32_t so_ = st_ + (uint32_t)(row_ * 72 + sg_ * 8) * 2; \
            size_t ao_ = (size_t)(bm + row_) * K + k0_ + sg_ * 8; \
            size_t bo_ = (size_t)(bn + row_) * K + k0_ + sg_ * 8; \
            CP_ASYNC16(uAh + so_, Ah + ao_); \
            CP_ASYNC16(uAl + so_, Al + ao_); \
            CP_ASYNC16(uBh + so_, Bh + bo_); \
        } \
    } while (0)

    PREFETCH_F(0);
    CP_COMMIT();

    const int l8 = lane & 7, g = lane >> 3;
    uint32_t aoff[4], boff[2];
#pragma unroll
    for (int mi = 0; mi < 4; mi++)
        aoff[mi] = (uint32_t)((wm + (mi << 4) + ((g & 1) << 3) + l8) * 72 + ((g >> 1) << 3)) * 2;
#pragma unroll
    for (int p = 0; p < 2; p++)
        boff[p] = (uint32_t)((wn + (p << 4) + ((g >> 1) << 3) + l8) * 72 + ((g & 1) << 3)) * 2;

    const int fr = lane >> 2;
    const int fc = (lane & 3) << 1;

    for (int t = 0; t < nchunk; t++) {
        if (t + 1 < nchunk) { PREFETCH_F(t + 1); CP_COMMIT(); CP_WAIT1(); }
        else                { CP_WAIT0(); }
        __syncthreads();
        const uint32_t stg = (uint32_t)(t & 1) * (TSF * 2);
#pragma unroll
        for (int kt = 0; kt < 4; kt++) {
            const uint32_t kof = stg + (uint32_t)(kt << 5);
            uint32_t bh[2][4];
#pragma unroll
            for (int p = 0; p < 2; p++)
                LDSM4(bh[p][0], bh[p][1], bh[p][2], bh[p][3], uBh + kof + boff[p]);
#pragma unroll
            for (int mi = 0; mi < 4; mi++) {
                uint32_t ah0, ah1, ah2, ah3, al0, al1, al2, al3;
                LDSM4(ah0, ah1, ah2, ah3, uAh + kof + aoff[mi]);
                LDSM4(al0, al1, al2, al3, uAl + kof + aoff[mi]);
#pragma unroll
                for (int p = 0; p < 2; p++) {
                    MMA_F16(acc[mi][2*p],   ah0, ah1, ah2, ah3, bh[p][0], bh[p][1]);
                    MMA_F16(acc[mi][2*p],   al0, al1, al2, al3, bh[p][0], bh[p][1]);
                    MMA_F16(acc[mi][2*p+1], ah0, ah1, ah2, ah3, bh[p][2], bh[p][3]);
                    MMA_F16(acc[mi][2*p+1], al0, al1, al2, al3, bh[p][2], bh[p][3]);
                }
            }
        }
        __syncthreads();
    }

    if (need_lo) {
#pragma unroll
        for (int mi = 0; mi < 4; mi++) {
            int row = bm + wm + (mi << 4) + fr;
#pragma unroll
            for (int ni = 0; ni < 4; ni++) {
                int col = bn + wn + (ni << 3) + fc;
                float bx = bias[col], by = bias[col + 1];
                uint32_t hh, ll;
                split_pack_h(acc[mi][ni][0] + bx, acc[mi][ni][1] + by, hh, ll);
                *(uint32_t*)&Ch[(size_t)row * N + col] = hh;
                *(uint32_t*)&Cl[(size_t)row * N + col] = ll;
                split_pack_h(acc[mi][ni][2] + bx, acc[mi][ni][3] + by, hh, ll);
                *(uint32_t*)&Ch[(size_t)(row + 8) * N + col] = hh;
                *(uint32_t*)&Cl[(size_t)(row + 8) * N + col] = ll;
            }
        }
    } else {
#pragma unroll
        for (int mi = 0; mi < 4; mi++) {
            int row = bm + wm + (mi << 4) + fr;
#pragma unroll
            for (int ni = 0; ni < 4; ni++) {
                int col = bn + wn + (ni << 3) + fc;
                float bx = bias[col], by = bias[col + 1];
                *(uint32_t*)&Ch[(size_t)row * N + col] =
                    pack_h2(acc[mi][ni][0] + bx, acc[mi][ni][1] + by);
                *(uint32_t*)&Ch[(size_t)(row + 8) * N + col] =
                    pack_h2(acc[mi][ni][2] + bx, acc[mi][ni][3] + by);
            }
        }
    }
}

// ---------------- proj GEMM: 128x64 tile, K-chunk 64, 3 CTAs/SM ----------------
__global__ __launch_bounds__(256, 3)
void gemm_proj(const unsigned short* __restrict__ Ah,
               const unsigned short* __restrict__ Bh, const unsigned short* __restrict__ Bl,
               const float* __restrict__ bias, float* __restrict__ Cf,
               int M, int N, int K)
{
    extern __shared__ unsigned short sm16[];
    unsigned short* sAh = sm16;                 // [2][TSF]
    unsigned short* sBh = sm16 + 2 * TSF;       // [2][TSB]
    unsigned short* sBl = sm16 + 2 * TSF + 2 * TSB;
    const uint32_t uAh = smem_u32(sAh), uBh = smem_u32(sBh), uBl = smem_u32(sBl);

    const int tid  = threadIdx.x;
    const int lane = tid & 31, wid = tid >> 5;
    const int wm = (wid >> 2) << 6;         // 0 / 64
    const int wn = (wid & 3) << 4;          // 0/16/32/48
    const int bm = blockIdx.y << 7, bn = blockIdx.x << 6;

    float acc[4][2][4];
#pragma unroll
    for (int i = 0; i < 4; i++)
#pragma unroll
        for (int j = 0; j < 2; j++)
#pragma unroll
            for (int k = 0; k < 4; k++) acc[i][j][k] = 0.f;

    const int nchunk = K >> 6;   // 32

#define PREFETCH_P(t) do { \
        int k0_ = (t) << 6; \
        uint32_t sa_ = (uint32_t)((t) & 1) * (TSF * 2); \
        uint32_t sb_ = (uint32_t)((t) & 1) * (TSB * 2); \
        _Pragma("unroll") \
        for (int it_ = 0; it_ < 4; it_++) { \
            int i_ = tid + it_ * 256; \
            int row_ = i_ >> 3, sg_ = i_ & 7; \
            uint32_t so_ = sa_ + (uint32_t)(row_ * 72 + sg_ * 8) * 2; \
            CP_ASYNC16(uAh + so_, Ah + (size_t)(bm + row_) * K + k0_ + sg_ * 8); \
        } \
        _Pragma("unroll") \
        for (int it_ = 0; it_ < 2; it_++) { \
            int i_ = tid + it_ * 256; \
            int row_ = i_ >> 3, sg_ = i_ & 7; \
            uint32_t so_ = sb_ + (uint32_t)(row_ * 72 + sg_ * 8) * 2; \
            size_t bo_ = (size_t)(bn + row_) * K + k0_ + sg_ * 8; \
            CP_ASYNC16(uBh + so_, Bh + bo_); \
            CP_ASYNC16(uBl + so_, Bl + bo_); \
        } \
    } while (0)

    PREFETCH_P(0);
    CP_COMMIT();

    const int l8 = lane & 7, g = lane >> 3;
    uint32_t aoff[4], boff;
#pragma unroll
    for (int mi = 0; mi < 4; mi++)
        aoff[mi] = (uint32_t)((wm + (mi << 4) + ((g & 1) << 3) + l8) * 72 + ((g >> 1) << 3)) * 2;
    boff = (uint32_t)((wn + ((g >> 1) << 3) + l8) * 72 + ((g & 1) << 3)) * 2;

    const int fr = lane >> 2;
    const int fc = (lane & 3) << 1;

    for (int t = 0; t < nchunk; t++) {
        if (t + 1 < nchunk) { PREFETCH_P(t + 1); CP_COMMIT(); CP_WAIT1(); }
        else                { CP_WAIT0(); }
        __syncthreads();
        const uint32_t sa = (uint32_t)(t & 1) * (TSF * 2);
        const uint32_t sb = (uint32_t)(t & 1) * (TSB * 2);
#pragma unroll
        for (int kt = 0; kt < 4; kt++) {
            const uint32_t ko = (uint32_t)(kt << 5);
            uint32_t bh0, bh1, bh2, bh3, bl0, bl1, bl2, bl3;
            LDSM4(bh0, bh1, bh2, bh3, uBh + sb + ko + boff);
            LDSM4(bl0, bl1, bl2, bl3, uBl + sb + ko + boff);
#pragma unroll
            for (int mi = 0; mi < 4; mi++) {
                uint32_t a0, a1, a2, a3;
                LDSM4(a0, a1, a2, a3, uAh + sa + ko + aoff[mi]);
                MMA_F16(acc[mi][0], a0, a1, a2, a3, bh0, bh1);
                MMA_F16(acc[mi][0], a0, a1, a2, a3, bl0, bl1);
                MMA_F16(acc[mi][1], a0, a1, a2, a3, bh2, bh3);
                MMA_F16(acc[mi][1], a0, a1, a2, a3, bl2, bl3);
            }
        }
        __syncthreads();
    }

#pragma unroll
    for (int mi = 0; mi < 4; mi++) {
        int row = bm + wm + (mi << 4) + fr;
#pragma unroll
        for (int ni = 0; ni < 2; ni++) {
            int col = bn + wn + (ni << 3) + fc;
            float bx = bias[col], by = bias[col + 1];
            float2 v0 = { acc[mi][ni][0] + bx, acc[mi][ni][1] + by };
            float2 v1 = { acc[mi][ni][2] + bx, acc[mi][ni][3] + by };
            *(float2*)(Cf + (size_t)row * N + col)       = v0;
            *(float2*)(Cf + (size_t)(row + 8) * N + col) = v1;
        }
    }
}

// ================= fused MMA flash attention (self + cross) =================
#define AST 72
#define QB  (64 * AST)
#define KVB (QB * 2)
#define QSTRIDE 4096

__global__ __launch_bounds__(128)
void attn_fused(const unsigned short* __restrict__ qkvh,
                const unsigned short* __restrict__ qkvl,
                const unsigned short* __restrict__ kvh,
                const float* __restrict__ mask,
                unsigned short* __restrict__ cath)
{
    extern __shared__ char smraw[];
    unsigned short* sQh = (unsigned short*)smraw;
    unsigned short* sQl = sQh + QB;
    unsigned short* sK  = sQl + QB;
    unsigned short* sV  = sK  + 2 * QB;
    float* sMsf = (float*)(sV + 2 * QB);
    const uint32_t uQh = smem_u32(sQh), uQl = smem_u32(sQl);
    const uint32_t uK = smem_u32(sK), uV = smem_u32(sV);
    const uint32_t uMs = smem_u32(sMsf);

    const int bx = blockIdx.x;
    const bool is_self = bx < 16;
    const int qt = is_self ? (15 - bx) : (31 - bx);
    const int h = blockIdx.y, b = blockIdx.z;
    const int tid = threadIdx.x, lane = tid & 31, wid = tid >> 5;
    const int q0 = wid << 4;
    const int r = lane >> 2, cq = (lane & 3) << 1;
    const int l8 = lane & 7, g = lane >> 3;

    const int lenx = g_lens[b], leny = g_lens[2 + b];

    uint32_t qfo = (uint32_t)((q0 + ((g & 1) << 3) + l8) * AST + ((g >> 1) << 3)) * 2;
    uint32_t kfo[4], vfo[4];
#pragma unroll
    for (int p = 0; p < 4; p++) {
        kfo[p] = (uint32_t)(((p << 4) + ((g >> 1) << 3) + l8) * AST + ((g & 1) << 3)) * 2;
        vfo[p] = (uint32_t)((((g & 1) << 3) + l8) * AST + (((p << 1) + (g >> 1)) << 3)) * 2;
    }

    float o[8][4];
#pragma unroll
    for (int i = 0; i < 8; i++)
#pragma unroll
        for (int j = 0; j < 4; j++) o[i][j] = 0.f;
    float mrow0 = -1e30f, mrow1 = -1e30f, lrow0 = 0.f, lrow1 = 0.f;

    if (is_self) {
        const size_t gb = (size_t)b * SXX * QSTRIDE;
        for (int i = tid; i < 512; i += 128) {
            int rr = i >> 3, seg = i & 7;
            size_t src = gb + (size_t)(qt * 64 + rr) * QSTRIDE + h * 64 + seg * 8;
            *(uint4*)&sQh[rr * AST + seg * 8] = *(const uint4*)&qkvh[src];
            *(uint4*)&sQl[rr * AST + seg * 8] = *(const uint4*)&qkvl[src];
        }

        const float* maskb = mask + b * SXX;
        int nt1 = qt + 1, nt2 = (lenx + 63) >> 6;
        const int ntile = nt1 < nt2 ? nt1 : nt2;

#define APREF_SELF(t) do { \
        uint32_t kd_ = uK + (uint32_t)((t) & 1) * KVB; \
        uint32_t vd_ = uV + (uint32_t)((t) & 1) * KVB; \
        _Pragma("unroll") \
        for (int it_ = 0; it_ < 4; it_++) { \
            int i_ = tid + it_ * 128; \
            int rr_ = i_ >> 3, sg_ = i_ & 7; \
            size_t kr_ = gb + (size_t)((t) * 64 + rr_) * QSTRIDE + 1024 + h * 64 + sg_ * 8; \
            uint32_t so_ = (uint32_t)(rr_ * AST + sg_ * 8) * 2; \
            CP_ASYNC16(kd_ + so_, qkvh + kr_); \
            CP_ASYNC16(vd_ + so_, qkvh + kr_ + 1024); \
        } \
        if (tid < 16) CP_ASYNC16(uMs + ((t) & 1) * 256 + tid * 16, maskb + (t) * 64 + tid * 4); \
    } while (0)

        APREF_SELF(0);
        CP_COMMIT();

        for (int t = 0; t < ntile; t++) {
            if (t + 1 < ntile) { APREF_SELF(t + 1); CP_COMMIT(); CP_WAIT1(); }
            else               { CP_WAIT0(); }
            __syncthreads();
            const uint32_t kb = (uint32_t)(t & 1) * KVB;
            const int mb = (t & 1) * 64;

            float sc[8][4];
#pragma unroll
            for (int i = 0; i < 8; i++)
#pragma unroll
                for (int j = 0; j < 4; j++) sc[i][j] = 0.f;

#pragma unroll
            for (int kt = 0; kt < 4; kt++) {
                const uint32_t ko = (uint32_t)(kt << 5);
                uint32_t ah0, ah1, ah2, ah3, al0, al1, al2, al3;
                LDSM4(ah0, ah1, ah2, ah3, uQh + qfo + ko);
                LDSM4(al0, al1, al2, al3, uQl + qfo + ko);
#pragma unroll
                for (int p = 0; p < 4; p++) {
                    uint32_t k0r, k1r, k2r, k3r;
                    LDSM4(k0r, k1r, k2r, k3r, uK + kb + kfo[p] + ko);
                    MMA_F16(sc[2*p],   ah0, ah1, ah2, ah3, k0r, k1r);
                    MMA_F16(sc[2*p],   al0, al1, al2, al3, k0r, k1r);
                    MMA_F16(sc[2*p+1], ah0, ah1, ah2, ah3, k2r, k3r);
                    MMA_F16(sc[2*p+1], al0, al1, al2, al3, k2r, k3r);
                }
            }

            const int grow = qt * 64 + q0 + r;
#pragma unroll
            for (int nt = 0; nt < 8; nt++) {
                int c0 = t * 64 + nt * 8 + cq;
                float m0 = sMsf[mb + nt * 8 + cq], m1 = sMsf[mb + nt * 8 + cq + 1];
                float v;
                v = sc[nt][0] * 0.125f; sc[nt][0] = ((c0     <= grow    ) ? v : -10000.f) + m0;
                v = sc[nt][1] * 0.125f; sc[nt][1] = ((c0 + 1 <= grow    ) ? v : -10000.f) + m1;
                v = sc[nt][2] * 0.125f; sc[nt][2] = ((c0     <= grow + 8) ? v : -10000.f) + m0;
                v = sc[nt][3] * 0.125f; sc[nt][3] = ((c0 + 1 <= grow + 8) ? v : -10000.f) + m1;
            }

            float mx0 = -1e30f, mx1 = -1e30f;
#pragma unroll
            for (int nt = 0; nt < 8; nt++) {
                mx0 = fmaxf(mx0, fmaxf(sc[nt][0], sc[nt][1]));
                mx1 = fmaxf(mx1, fmaxf(sc[nt][2], sc[nt][3]));
            }
            mx0 = fmaxf(mx0, __shfl_xor_sync(0xffffffffu, mx0, 1));
            mx0 = fmaxf(mx0, __shfl_xor_sync(0xffffffffu, mx0, 2));
            mx1 = fmaxf(mx1, __shfl_xor_sync(0xffffffffu, mx1, 1));
            mx1 = fmaxf(mx1, __shfl_xor_sync(0xffffffffu, mx1, 2));
            float mn0 = fmaxf(mrow0, mx0), mn1 = fmaxf(mrow1, mx1);
            float al0f = __expf(mrow0 - mn0), al1f = __expf(mrow1 - mn1);
            float s0 = 0.f, s1 = 0.f;
#pragma unroll
            for (int nt = 0; nt < 8; nt++) {
                sc[nt][0] = __expf(sc[nt][0] - mn0); s0 += sc[nt][0];
                sc[nt][1] = __expf(sc[nt][1] - mn0); s0 += sc[nt][1];
                sc[nt][2] = __expf(sc[nt][2] - mn1); s1 += sc[nt][2];
                sc[nt][3] = __expf(sc[nt][3] - mn1); s1 += sc[nt][3];
            }
            s0 += __shfl_xor_sync(0xffffffffu, s0, 1);
            s0 += __shfl_xor_sync(0xffffffffu, s0, 2);
            s1 += __shfl_xor_sync(0xffffffffu, s1, 1);
            s1 += __shfl_xor_sync(0xffffffffu, s1, 2);
            lrow0 = lrow0 * al0f + s0; mrow0 = mn0;
            lrow1 = lrow1 * al1f + s1; mrow1 = mn1;
#pragma unroll
            for (int nt = 0; nt < 8; nt++) {
                o[nt][0] *= al0f; o[nt][1] *= al0f;
                o[nt][2] *= al1f; o[nt][3] *= al1f;
            }

#pragma unroll
            for (int kc = 0; kc < 4; kc++) {
                uint32_t ph[4], pl[4];
                split_pack_h(sc[2*kc][0],   sc[2*kc][1],   ph[0], pl[0]);
                split_pack_h(sc[2*kc][2],   sc[2*kc][3],   ph[1], pl[1]);
                split_pack_h(sc[2*kc+1][0], sc[2*kc+1][1], ph[2], pl[2]);
                split_pack_h(sc[2*kc+1][2], sc[2*kc+1][3], ph[3], pl[3]);
                const uint32_t vrow = kb + (uint32_t)(kc * 16 * AST) * 2;
#pragma unroll
                for (int p = 0; p < 4; p++) {
                    uint32_t v0r, v1r, v2r, v3r;
                    LDSM4T(v0r, v1r, v2r, v3r, uV + vrow + vfo[p]);
                    MMA_F16(o[2*p],   ph[0], ph[1], ph[2], ph[3], v0r, v1r);
                    MMA_F16(o[2*p],   pl[0], pl[1], pl[2], pl[3], v0r, v1r);
                    MMA_F16(o[2*p+1], ph[0], ph[1], ph[2], ph[3], v2r, v3r);
                    MMA_F16(o[2*p+1], pl[0], pl[1], pl[2], pl[3], v2r, v3r);
                }
            }
            __syncthreads();
        }

        float i0 = 1.f / lrow0, i1 = 1.f / lrow1;
        size_t ob = (size_t)b * SXX * 2048 + (size_t)(qt * 64 + q0 + r) * 2048 + h * 64;
#pragma unroll
        for (int dn = 0; dn < 8; dn++) {
            *(uint32_t*)&cath[ob + dn * 8 + cq] = pack_h2(o[dn][0] * i0, o[dn][1] * i0);
            *(uint32_t*)&cath[ob + (size_t)8 * 2048 + dn * 8 + cq] = pack_h2(o[dn][2] * i1, o[dn][3] * i1);
        }
    } else {
        const int off = FULLN - lenx;
        size_t obase = (size_t)b * SXX * 2048 + (size_t)(qt * 64) * 2048 + 1024 + h * 64;
        if (qt * 64 >= lenx) {
            const uint4 z = {0, 0, 0, 0};
            for (int i = tid; i < 512; i += 128) {
                int rr = i >> 3, seg = i & 7;
                *(uint4*)&cath[obase + (size_t)rr * 2048 + seg * 8] = z;
            }
            return;
        }

        const size_t qgb = (size_t)b * SXX * QSTRIDE;
        for (int i = tid; i < 512; i += 128) {
            int rr = i >> 3, seg = i & 7;
            size_t src = qgb + (size_t)(qt * 64 + rr) * QSTRIDE + 3072 + h * 64 + seg * 8;
            *(uint4*)&sQh[rr * AST + seg * 8] = *(const uint4*)&qkvh[src];
            *(uint4*)&sQl[rr * AST + seg * 8] = *(const uint4*)&qkvl[src];
        }

        int qlast = qt * 64 + 63;
        if (qlast >= lenx) qlast = lenx - 1;
        int jmax = off + qlast + 1;
        if (jmax > leny) jmax = leny;
        const int ntile = (jmax + 63) >> 6;
        const size_t kgb = (size_t)b * SYY * 2048;

#define APREF_CROSS(t) do { \
        uint32_t kd_ = uK + (uint32_t)((t) & 1) * KVB; \
        uint32_t vd_ = uV + (uint32_t)((t) & 1) * KVB; \
        _Pragma("unroll") \
        for (int it_ = 0; it_ < 4; it_++) { \
            int i_ = tid + it_ * 128; \
            int rr_ = i_ >> 3, sg_ = i_ & 7; \
            size_t kr_ = kgb + (size_t)((t) * 64 + rr_) * 2048 + h * 64 + sg_ * 8; \
            uint32_t so_ = (uint32_t)(rr_ * AST + sg_ * 8) * 2; \
            CP_ASYNC16(kd_ + so_, kvh + kr_); \
            CP_ASYNC16(vd_ + so_, kvh + kr_ + 1024); \
        } \
    } while (0)

        APREF_CROSS(0);
        CP_COMMIT();

        for (int t = 0; t < ntile; t++) {
            if (t + 1 < ntile) { APREF_CROSS(t + 1); CP_COMMIT(); CP_WAIT1(); }
            else               { CP_WAIT0(); }
            __syncthreads();
            const uint32_t kb = (uint32_t)(t & 1) * KVB;

            float sc[8][4];
#pragma unroll
            for (int i = 0; i < 8; i++)
#pragma unroll
                for (int j = 0; j < 4; j++) sc[i][j] = 0.f;

#pragma unroll
            for (int kt = 0; kt < 4; kt++) {
                const uint32_t ko = (uint32_t)(kt << 5);
                uint32_t ah0, ah1, ah2, ah3, al0, al1, al2, al3;
                LDSM4(ah0, ah1, ah2, ah3, uQh + qfo + ko);
                LDSM4(al0, al1, al2, al3, uQl + qfo + ko);
#pragma unroll
                for (int p = 0; p < 4; p++) {
                    uint32_t k0r, k1r, k2r, k3r;
                    LDSM4(k0r, k1r, k2r, k3r, uK + kb + kfo[p] + ko);
                    MMA_F16(sc[2*p],   ah0, ah1, ah2, ah3, k0r, k1r);
                    MMA_F16(sc[2*p],   al0, al1, al2, al3, k0r, k1r);
                    MMA_F16(sc[2*p+1], ah0, ah1, ah2, ah3, k2r, k3r);
                    MMA_F16(sc[2*p+1], al0, al1, al2, al3, k2r, k3r);
                }
            }

            const int grow = off + qt * 64 + q0 + r;
#pragma unroll
            for (int nt = 0; nt < 8; nt++) {
                int c0 = t * 64 + nt * 8 + cq;
                sc[nt][0] = (c0     <= grow     && c0     < leny) ? sc[nt][0] * 0.125f : -1e30f;
                sc[nt][1] = (c0 + 1 <= grow     && c0 + 1 < leny) ? sc[nt][1] * 0.125f : -1e30f;
                sc[nt][2] = (c0     <= grow + 8 && c0     < leny) ? sc[nt][2] * 0.125f : -1e30f;
                sc[nt][3] = (c0 + 1 <= grow + 8 && c0 + 1 < leny) ? sc[nt][3] * 0.125f : -1e30f;
            }

            float mx0 = -1e30f, mx1 = -1e30f;
#pragma unroll
            for (int nt = 0; nt < 8; nt++) {
                mx0 = fmaxf(mx0, fmaxf(sc[nt][0], sc[nt][1]));
                mx1 = fmaxf(mx1, fmaxf(sc[nt][2], sc[nt][3]));
            }
            mx0 = fmaxf(mx0, __shfl_xor_sync(0xffffffffu, mx0, 1));
            mx0 = fmaxf(mx0, __shfl_xor_sync(0xffffffffu, mx0, 2));
            mx1 = fmaxf(mx1, __shfl_xor_sync(0xffffffffu, mx1, 1));
            mx1 = fmaxf(mx1, __shfl_xor_sync(0xffffffffu, mx1, 2));
            float mn0 = fmaxf(mrow0, mx0), mn1 = fmaxf(mrow1, mx1);
            float al0f = __expf(mrow0 - mn0), al1f = __expf(mrow1 - mn1);
            float s0 = 0.f, s1 = 0.f;
#pragma unroll
            for (int nt = 0; nt < 8; nt++) {
                sc[nt][0] = __expf(sc[nt][0] - mn0); s0 += sc[nt][0];
                sc[nt][1] = __expf(sc[nt][1] - mn0); s0 += sc[nt][1];
                sc[nt][2] = __expf(sc[nt][2] - mn1); s1 += sc[nt][2];
                sc[nt][3] = __expf(sc[nt][3] - mn1); s1 += sc[nt][3];
            }
            s0 += __shfl_xor_sync(0xffffffffu, s0, 1);
            s0 += __shfl_xor_sync(0xffffffffu, s0, 2);
            s1 += __shfl_xor_sync(0xffffffffu, s1, 1);
            s1 += __shfl_xor_sync(0xffffffffu, s1, 2);
            lrow0 = lrow0 * al0f + s0; mrow0 = mn0;
            lrow1 = lrow1 * al1f + s1; mrow1 = mn1;
#pragma unroll
            for (int nt = 0; nt < 8; nt++) {
                o[nt][0] *= al0f; o[nt][1] *= al0f;
                o[nt][2] *= al1f; o[nt][3] *= al1f;
            }

#pragma unroll
            for (int kc = 0; kc < 4; kc++) {
                uint32_t ph[4], pl[4];
                split_pack_h(sc[2*kc][0],   sc[2*kc][1],   ph[0], pl[0]);
                split_pack_h(sc[2*kc][2],   sc[2*kc][3],   ph[1], pl[1]);
                split_pack_h(sc[2*kc+1][0], sc[2*kc+1][1], ph[2], pl[2]);
                split_pack_h(sc[2*kc+1][2], sc[2*kc+1][3], ph[3], pl[3]);
                const uint32_t vrow = kb + (uint32_t)(kc * 16 * AST) * 2;
#pragma unroll
                for (int p = 0; p < 4; p++) {
                    uint32_t v0r, v1r, v2r, v3r;
                    LDSM4T(v0r, v1r, v2r, v3r, uV + vrow + vfo[p]);
                    MMA_F16(o[2*p],   ph[0], ph[1], ph[2], ph[3], v0r, v1r);
                    MMA_F16(o[2*p],   pl[0], pl[1], pl[2], pl[3], v0r, v1r);
                    MMA_F16(o[2*p+1], ph[0], ph[1], ph[2], ph[3], v2r, v3r);
                    MMA_F16(o[2*p+1], pl[0], pl[1], pl[2], pl[3], v2r, v3r);
                }
            }
            __syncthreads();
        }

        float i0 = 1.f / lrow0, i1 = 1.f / lrow1;
        int row0 = qt * 64 + q0 + r, row1 = row0 + 8;
        bool v0 = row0 < lenx, v1 = row1 < lenx;
        size_t ob = (size_t)b * SXX * 2048 + (size_t)row0 * 2048 + 1024 + h * 64;
#pragma unroll
        for (int dn = 0; dn < 8; dn++) {
            *(uint32_t*)&cath[ob + dn * 8 + cq] =
                v0 ? pack_h2(o[dn][0] * i0, o[dn][1] * i0) : 0u;
            *(uint32_t*)&cath[ob + (size_t)8 * 2048 + dn * 8 + cq] =
                v1 ? pack_h2(o[dn][2] * i1, o[dn][3] * i1) : 0u;
        }
    }
}

// ---------------- launch ----------------
extern "C" void kernel_launch(void* const* d_in, const int* in_sizes, int n_in,
                              void* d_out, int out_size)
{
    const float* x      = (const float*)d_in[0];
    const float* y      = (const float*)d_in[1];
    const float* maskx  = (const float*)d_in[2];
    const float* W_attn = (const float*)d_in[3];
    const float* b_attn = (const float*)d_in[4];
    const float* W_2a   = (const float*)d_in[5];
    const float* b_2a   = (const float*)d_in[6];
    const float* W_2b   = (const float*)d_in[7];
    const float* b_2b   = (const float*)d_in[8];
    const float* W_proj = (const float*)d_in[9];
    const float* b_proj = (const float*)d_in[10];
    const int*   xtb    = (const int*)d_in[11];
    const int*   ytb    = (const int*)d_in[15];

    unsigned short *xh, *xl, *yh, *yl;
    unsigned short *qkvh, *qkvl, *kv2h, *cath;
    unsigned short *wc, *wb, *wph, *wpl;
    float* bias4k;
    cudaGetSymbolAddress((void**)&xh, g_xh);     cudaGetSymbolAddress((void**)&xl, g_xl);
    cudaGetSymbolAddress((void**)&yh, g_yh);     cudaGetSymbolAddress((void**)&yl, g_yl);
    cudaGetSymbolAddress((void**)&qkvh, g_qkvh); cudaGetSymbolAddress((void**)&qkvl, g_qkvl);
    cudaGetSymbolAddress((void**)&kv2h, g_kv2h);
    cudaGetSymbolAddress((void**)&cath, g_cath);
    cudaGetSymbolAddress((void**)&wc, g_wc_h);
    cudaGetSymbolAddress((void**)&wb, g_w2b_h);
    cudaGetSymbolAddress((void**)&wph, g_wpj_h); cudaGetSymbolAddress((void**)&wpl, g_wpj_l);
    cudaGetSymbolAddress((void**)&bias4k, g_bias4k);

    const int SMEM_GF = 6 * TSF * 2;                    // 110592 B
    const int SMEM_GP = (2 * TSF + 4 * TSB) * 2;        // 73728 B
    const int SMEM_ATTN = 6 * QB * 2 + 2 * 64 * 4;      // 55808 B
    cudaFuncSetAttribute((const void*)gemm_front, cudaFuncAttributeMaxDynamicSharedMemorySize, SMEM_GF);
    cudaFuncSetAttribute((const void*)gemm_proj,  cudaFuncAttributeMaxDynamicSharedMemorySize, SMEM_GP);
    cudaFuncSetAttribute((const void*)attn_fused, cudaFuncAttributeMaxDynamicSharedMemorySize, SMEM_ATTN);

    prep_small<<<17, 256>>>(xtb, in_sizes[11], ytb, in_sizes[15], b_attn, b_2a, bias4k);
    split_xy<<<4096, 256>>>(x, y, xh, xl, yh, yl);
    transpose_all<<<8192, 256>>>(W_attn, W_2a, W_2b, W_proj, wc, wb, wph, wpl);

    gemm_front<<<768, 256, SMEM_GF>>>(xh, xl, yh, yl, wc, wb, bias4k, b_2b, qkvh, qkvl, kv2h);

    attn_fused<<<dim3(32, 16, 2), 128, SMEM_ATTN>>>(qkvh, qkvl, kv2h, maskx, cath);

    gemm_proj<<<dim3(16, 16), 256, SMEM_GP>>>(cath, wph, wpl, b_proj, (float*)d_out, 2048, 1024, 2048);
}